// round 4
// baseline (speedup 1.0000x reference)
#include <cuda_runtime.h>
#include <cuda_bf16.h>
#include <math.h>
#include <stdint.h>

// ---------------------------------------------------------------------------
// Problem constants
// ---------------------------------------------------------------------------
#define BATCH   2
#define SEQ     2048
#define HID     1024
#define HEADS   16
#define HDIM    64
#define ROWS    (BATCH * SEQ)          // 4096

// ---------------------------------------------------------------------------
// Scratch (static device globals -- no runtime allocation)
// ---------------------------------------------------------------------------
__device__ float g_Q[ROWS * HID];
__device__ float g_K[ROWS * HID];
__device__ float g_V[ROWS * HID];
__device__ float g_CTX[ROWS * HID];
__device__ float g_X[ROWS * HID];

// bf16 split buffers (hi/lo) for tensor-core GEMMs
__device__ __nv_bfloat16 g_Hhi[ROWS * HID];
__device__ __nv_bfloat16 g_Hlo[ROWS * HID];
__device__ __nv_bfloat16 g_Chi[ROWS * HID];
__device__ __nv_bfloat16 g_Clo[ROWS * HID];
__device__ __nv_bfloat16 g_WqTh[HID * HID];
__device__ __nv_bfloat16 g_WqTl[HID * HID];
__device__ __nv_bfloat16 g_WkTh[HID * HID];
__device__ __nv_bfloat16 g_WkTl[HID * HID];
__device__ __nv_bfloat16 g_WvTh[HID * HID];
__device__ __nv_bfloat16 g_WvTl[HID * HID];
__device__ __nv_bfloat16 g_WoTh[HID * HID];
__device__ __nv_bfloat16 g_WoTl[HID * HID];

// ---------------------------------------------------------------------------
// Warp MMA helpers (arch-agnostic PTX: ldmatrix + mma.sync bf16)
// ---------------------------------------------------------------------------
__device__ __forceinline__ uint32_t smem_u32(const void* p) {
    uint32_t a;
    asm("{ .reg .u64 t; cvta.to.shared.u64 t, %1; cvt.u32.u64 %0, t; }"
        : "=r"(a) : "l"(p));
    return a;
}

__device__ __forceinline__ void ldmx4(uint32_t& r0, uint32_t& r1, uint32_t& r2,
                                      uint32_t& r3, uint32_t addr) {
    asm volatile("ldmatrix.sync.aligned.m8n8.x4.shared.b16 {%0,%1,%2,%3}, [%4];"
                 : "=r"(r0), "=r"(r1), "=r"(r2), "=r"(r3) : "r"(addr));
}
__device__ __forceinline__ void ldmx2(uint32_t& r0, uint32_t& r1, uint32_t addr) {
    asm volatile("ldmatrix.sync.aligned.m8n8.x2.shared.b16 {%0,%1}, [%2];"
                 : "=r"(r0), "=r"(r1) : "r"(addr));
}
__device__ __forceinline__ void mma_bf16(float& d0, float& d1, float& d2, float& d3,
                                         uint32_t a0, uint32_t a1, uint32_t a2,
                                         uint32_t a3, uint32_t b0, uint32_t b1) {
    asm volatile(
        "mma.sync.aligned.m16n8k16.row.col.f32.bf16.bf16.f32 "
        "{%0,%1,%2,%3}, {%4,%5,%6,%7}, {%8,%9}, {%0,%1,%2,%3};"
        : "+f"(d0), "+f"(d1), "+f"(d2), "+f"(d3)
        : "r"(a0), "r"(a1), "r"(a2), "r"(a3), "r"(b0), "r"(b1));
}

// ---------------------------------------------------------------------------
// fp32 -> bf16 hi/lo split (elementwise, float4-vectorized)
// ---------------------------------------------------------------------------
__device__ __forceinline__ void split1(float x, __nv_bfloat16& h, __nv_bfloat16& l) {
    h = __float2bfloat16(x);
    l = __float2bfloat16(x - __bfloat162float(h));
}

__global__ __launch_bounds__(256)
void convert_split(const float* __restrict__ in, __nv_bfloat16* __restrict__ hi,
                   __nv_bfloat16* __restrict__ lo, int n4)
{
    int i = blockIdx.x * blockDim.x + threadIdx.x;
    if (i >= n4) return;
    float4 v = ((const float4*)in)[i];
    __nv_bfloat16 h0, l0, h1, l1, h2, l2, h3, l3;
    split1(v.x, h0, l0); split1(v.y, h1, l1);
    split1(v.z, h2, l2); split1(v.w, h3, l3);
    ((__nv_bfloat162*)hi)[2 * i + 0] = __nv_bfloat162(h0, h1);
    ((__nv_bfloat162*)hi)[2 * i + 1] = __nv_bfloat162(h2, h3);
    ((__nv_bfloat162*)lo)[2 * i + 0] = __nv_bfloat162(l0, l1);
    ((__nv_bfloat162*)lo)[2 * i + 1] = __nv_bfloat162(l2, l3);
}

// ---------------------------------------------------------------------------
// W [K,N] fp32 -> transposed hi/lo bf16 [N,K]
// ---------------------------------------------------------------------------
__global__ __launch_bounds__(256)
void transpose_split(const float* __restrict__ W, __nv_bfloat16* __restrict__ Th,
                     __nv_bfloat16* __restrict__ Tl)
{
    __shared__ float t[32][33];
    const int n0 = blockIdx.x * 32, k0 = blockIdx.y * 32;
    const int tx = threadIdx.x, ty = threadIdx.y;
#pragma unroll
    for (int i = 0; i < 32; i += 8)
        t[ty + i][tx] = W[(size_t)(k0 + ty + i) * HID + n0 + tx];
    __syncthreads();
#pragma unroll
    for (int i = 0; i < 32; i += 8) {
        float x = t[tx][ty + i];     // W[k0+tx][n0+ty+i]
        __nv_bfloat16 h, l; split1(x, h, l);
        Th[(size_t)(n0 + ty + i) * HID + k0 + tx] = h;
        Tl[(size_t)(n0 + ty + i) * HID + k0 + tx] = l;
    }
}

// ---------------------------------------------------------------------------
// Tensor-core GEMM via mma.sync (bf16 hi/lo split, fp32 accum):
//   C[4096,1024] = A @ W (+bias)(+res)
//   A: bf16 hi/lo [4096,1024] K-major.  BT: bf16 hi/lo [1024(n),1024(k)].
//   CTA: 128x128 tile, 8 warps (2x4), warp tile 64x32 = 4x4 m16n8 tiles.
//   BK=32 (two k16 steps), 3 MMAs per tile per step (hh + hl + lh).
// ---------------------------------------------------------------------------
#define GSTR 40   // padded smem row stride in bf16 (80 B, 16B-aligned)

__global__ __launch_bounds__(256, 2)
void gemm_mma(const __nv_bfloat16* __restrict__ Ahi, const __nv_bfloat16* __restrict__ Alo,
              const __nv_bfloat16* __restrict__ Bhi, const __nv_bfloat16* __restrict__ Blo,
              const float* __restrict__ bias, const float* __restrict__ res,
              float* __restrict__ C)
{
    __shared__ __nv_bfloat16 sm[4][128][GSTR];   // Ahi, Alo, Bhi, Blo tiles

    const int tid  = threadIdx.x;
    const int lane = tid & 31;
    const int warp = tid >> 5;
    const int wm   = (warp >> 2) * 64;   // warp m offset (0 or 64)
    const int wn   = (warp & 3) * 32;    // warp n offset (0,32,64,96)
    const int m0 = blockIdx.y * 128, n0 = blockIdx.x * 128;

    float acc[4][4][4];
#pragma unroll
    for (int mi = 0; mi < 4; mi++)
#pragma unroll
        for (int nj = 0; nj < 4; nj++)
#pragma unroll
            for (int e = 0; e < 4; e++) acc[mi][nj][e] = 0.f;

    const __nv_bfloat16* srcs[4] = {Ahi, Alo, Bhi, Blo};

    for (int kc = 0; kc < HID / 32; kc++) {
        const int kbase = kc * 32;
        __syncthreads();                 // previous compute done reading smem
#pragma unroll
        for (int a = 0; a < 4; a++) {
            const int rbase = (a < 2) ? m0 : n0;
            const __nv_bfloat16* src = srcs[a];
#pragma unroll
            for (int i = 0; i < 2; i++) {
                int fi  = tid + i * 256;         // 0..511
                int row = fi >> 2;               // 0..127
                int c   = fi & 3;                // chunk of 8 bf16
                uint4 v = *(const uint4*)&src[(size_t)(rbase + row) * HID + kbase + c * 8];
                *(uint4*)&sm[a][row][c * 8] = v;
            }
        }
        __syncthreads();

#pragma unroll
        for (int ks = 0; ks < 2; ks++) {
            // B fragments for all 4 n-tiles (hi + lo)
            uint32_t bh[4][2], bl[4][2];
#pragma unroll
            for (int nj = 0; nj < 4; nj++) {
                uint32_t ra = smem_u32(&sm[2][wn + nj * 8 + (lane & 7)]
                                          [((lane >> 3) & 1) * 8 + ks * 16]);
                ldmx2(bh[nj][0], bh[nj][1], ra);
                uint32_t rb = smem_u32(&sm[3][wn + nj * 8 + (lane & 7)]
                                          [((lane >> 3) & 1) * 8 + ks * 16]);
                ldmx2(bl[nj][0], bl[nj][1], rb);
            }
#pragma unroll
            for (int mi = 0; mi < 4; mi++) {
                uint32_t ah0, ah1, ah2, ah3, al0, al1, al2, al3;
                uint32_t aa = smem_u32(&sm[0][wm + mi * 16 + (lane & 15)]
                                          [(lane >> 4) * 8 + ks * 16]);
                ldmx4(ah0, ah1, ah2, ah3, aa);
                uint32_t ab = smem_u32(&sm[1][wm + mi * 16 + (lane & 15)]
                                          [(lane >> 4) * 8 + ks * 16]);
                ldmx4(al0, al1, al2, al3, ab);
#pragma unroll
                for (int nj = 0; nj < 4; nj++) {
                    mma_bf16(acc[mi][nj][0], acc[mi][nj][1], acc[mi][nj][2], acc[mi][nj][3],
                             ah0, ah1, ah2, ah3, bh[nj][0], bh[nj][1]);
                    mma_bf16(acc[mi][nj][0], acc[mi][nj][1], acc[mi][nj][2], acc[mi][nj][3],
                             ah0, ah1, ah2, ah3, bl[nj][0], bl[nj][1]);
                    mma_bf16(acc[mi][nj][0], acc[mi][nj][1], acc[mi][nj][2], acc[mi][nj][3],
                             al0, al1, al2, al3, bh[nj][0], bh[nj][1]);
                }
            }
        }
    }

    // Epilogue: fragment layout -> direct float2 stores
#pragma unroll
    for (int mi = 0; mi < 4; mi++) {
#pragma unroll
        for (int nj = 0; nj < 4; nj++) {
            int row = m0 + wm + mi * 16 + (lane >> 2);
            int col = n0 + wn + nj * 8 + 2 * (lane & 3);
            float2 v0, v1;
            v0.x = acc[mi][nj][0] + bias[col];
            v0.y = acc[mi][nj][1] + bias[col + 1];
            v1.x = acc[mi][nj][2] + bias[col];
            v1.y = acc[mi][nj][3] + bias[col + 1];
            if (res) {
                float2 r0 = *(const float2*)&res[(size_t)row * HID + col];
                float2 r1 = *(const float2*)&res[(size_t)(row + 8) * HID + col];
                v0.x += r0.x; v0.y += r0.y;
                v1.x += r1.x; v1.y += r1.y;
            }
            *(float2*)&C[(size_t)row * HID + col] = v0;
            *(float2*)&C[(size_t)(row + 8) * HID + col] = v1;
        }
    }
}

// ---------------------------------------------------------------------------
// Flash attention v2 (fp32) -- unchanged from R2
// ---------------------------------------------------------------------------
#define BQ   128
#define BKT  128
#define QSTR 128
#define VSTR 64
#define PSTR 128

#define ATT_SMEM_FLOATS (64*QSTR + 64*QSTR + 128*VSTR + 128*PSTR)
#define ATT_SMEM_BYTES  (ATT_SMEM_FLOATS * 4)

__global__ __launch_bounds__(256)
void flash_attn(const float* __restrict__ Q, const float* __restrict__ K,
                const float* __restrict__ V, float* __restrict__ Ctx)
{
    extern __shared__ float smf[];
    float* Qs = smf;                 // [64][QSTR]   (d-major)
    float* Ks = Qs + 64 * QSTR;      // [64][QSTR]   (d-major)
    float* Vs = Ks + 64 * QSTR;      // [128][VSTR]  (k-major)
    float* Ps = Vs + 128 * VSTR;     // [128][PSTR]  (q-major)

    const int tid = threadIdx.x;
    const int tx = tid & 15;
    const int ty = tid >> 4;
    const int q0 = blockIdx.x * BQ;
    const int h  = blockIdx.y;
    const int b  = blockIdx.z;
    const size_t base = (size_t)b * SEQ * HID + (size_t)h * HDIM;

#pragma unroll
    for (int t = 0; t < 8; t++) {
        int fi  = tid + t * 256;
        int row = fi & 127;
        int d4  = (fi >> 7) * 4;
        float4 v = *(const float4*)&Q[base + (size_t)(q0 + row) * HID + d4];
        Qs[(d4 + 0) * QSTR + row] = v.x;
        Qs[(d4 + 1) * QSTR + row] = v.y;
        Qs[(d4 + 2) * QSTR + row] = v.z;
        Qs[(d4 + 3) * QSTR + row] = v.w;
    }

    float m[8], l[8], acc[8][4];
#pragma unroll
    for (int i = 0; i < 8; i++) {
        m[i] = -1e30f; l[i] = 0.f;
#pragma unroll
        for (int j = 0; j < 4; j++) acc[i][j] = 0.f;
    }

    const float scale = 0.125f;

    for (int kt = 0; kt < SEQ / BKT; kt++) {
        const int k0 = kt * BKT;
        __syncthreads();

#pragma unroll
        for (int t = 0; t < 8; t++) {
            int fi  = tid + t * 256;
            int row = fi & 127;
            int d4  = (fi >> 7) * 4;
            float4 kv = *(const float4*)&K[base + (size_t)(k0 + row) * HID + d4];
            Ks[(d4 + 0) * QSTR + row] = kv.x;
            Ks[(d4 + 1) * QSTR + row] = kv.y;
            Ks[(d4 + 2) * QSTR + row] = kv.z;
            Ks[(d4 + 3) * QSTR + row] = kv.w;
            int vrow = fi >> 4;
            int vd4  = (fi & 15) * 4;
            float4 vv = *(const float4*)&V[base + (size_t)(k0 + vrow) * HID + vd4];
            *(float4*)&Vs[vrow * VSTR + vd4] = vv;
        }
        __syncthreads();

        float s[8][8];
#pragma unroll
        for (int i = 0; i < 8; i++)
#pragma unroll
            for (int j = 0; j < 8; j++) s[i][j] = 0.f;

#pragma unroll 4
        for (int d = 0; d < 64; d++) {
            float4 qa = *(float4*)&Qs[d * QSTR + ty * 4];
            float4 qb = *(float4*)&Qs[d * QSTR + 64 + ty * 4];
            float4 ka = *(float4*)&Ks[d * QSTR + tx * 4];
            float4 kb = *(float4*)&Ks[d * QSTR + 64 + tx * 4];
            float a[8] = {qa.x, qa.y, qa.z, qa.w, qb.x, qb.y, qb.z, qb.w};
            float bb[8] = {ka.x, ka.y, ka.z, ka.w, kb.x, kb.y, kb.z, kb.w};
#pragma unroll
            for (int i = 0; i < 8; i++)
#pragma unroll
                for (int j = 0; j < 8; j++) s[i][j] += a[i] * bb[j];
        }

#pragma unroll
        for (int i = 0; i < 8; i++) {
#pragma unroll
            for (int j = 0; j < 8; j++) s[i][j] *= scale;
            float mx = s[i][0];
#pragma unroll
            for (int j = 1; j < 8; j++) mx = fmaxf(mx, s[i][j]);
            mx = fmaxf(mx, __shfl_xor_sync(0xffffffffu, mx, 1));
            mx = fmaxf(mx, __shfl_xor_sync(0xffffffffu, mx, 2));
            mx = fmaxf(mx, __shfl_xor_sync(0xffffffffu, mx, 4));
            mx = fmaxf(mx, __shfl_xor_sync(0xffffffffu, mx, 8));
            float m_new = fmaxf(m[i], mx);
            float alpha = __expf(m[i] - m_new);
            float sum = 0.f;
#pragma unroll
            for (int j = 0; j < 8; j++) {
                s[i][j] = __expf(s[i][j] - m_new);
                sum += s[i][j];
            }
            sum += __shfl_xor_sync(0xffffffffu, sum, 1);
            sum += __shfl_xor_sync(0xffffffffu, sum, 2);
            sum += __shfl_xor_sync(0xffffffffu, sum, 4);
            sum += __shfl_xor_sync(0xffffffffu, sum, 8);
            l[i] = l[i] * alpha + sum;
            m[i] = m_new;
#pragma unroll
            for (int j = 0; j < 4; j++) acc[i][j] *= alpha;
        }

#pragma unroll
        for (int i = 0; i < 8; i++) {
            int r = (i < 4) ? (ty * 4 + i) : (60 + ty * 4 + i);
            *(float4*)&Ps[r * PSTR + tx * 4] =
                make_float4(s[i][0], s[i][1], s[i][2], s[i][3]);
            *(float4*)&Ps[r * PSTR + 64 + tx * 4] =
                make_float4(s[i][4], s[i][5], s[i][6], s[i][7]);
        }
        __syncthreads();

#pragma unroll 4
        for (int k4 = 0; k4 < 32; k4++) {
            float4 v0 = *(float4*)&Vs[(k4 * 4 + 0) * VSTR + tx * 4];
            float4 v1 = *(float4*)&Vs[(k4 * 4 + 1) * VSTR + tx * 4];
            float4 v2 = *(float4*)&Vs[(k4 * 4 + 2) * VSTR + tx * 4];
            float4 v3 = *(float4*)&Vs[(k4 * 4 + 3) * VSTR + tx * 4];
#pragma unroll
            for (int i = 0; i < 8; i++) {
                int r = (i < 4) ? (ty * 4 + i) : (60 + ty * 4 + i);
                float4 p = *(float4*)&Ps[r * PSTR + k4 * 4];
                acc[i][0] += p.x * v0.x + p.y * v1.x + p.z * v2.x + p.w * v3.x;
                acc[i][1] += p.x * v0.y + p.y * v1.y + p.z * v2.y + p.w * v3.y;
                acc[i][2] += p.x * v0.z + p.y * v1.z + p.z * v2.z + p.w * v3.z;
                acc[i][3] += p.x * v0.w + p.y * v1.w + p.z * v2.w + p.w * v3.w;
            }
        }
    }

#pragma unroll
    for (int i = 0; i < 8; i++) {
        int r = (i < 4) ? (ty * 4 + i) : (60 + ty * 4 + i);
        float inv_l = 1.f / l[i];
        float4 o;
        o.x = acc[i][0] * inv_l;
        o.y = acc[i][1] * inv_l;
        o.z = acc[i][2] * inv_l;
        o.w = acc[i][3] * inv_l;
        *(float4*)&Ctx[base + (size_t)(q0 + r) * HID + tx * 4] = o;
    }
}

// ---------------------------------------------------------------------------
// LayerNorm: one block per row of 1024
// ---------------------------------------------------------------------------
__global__ __launch_bounds__(256)
void layernorm_kernel(const float* __restrict__ X, const float* __restrict__ gamma,
                      const float* __restrict__ beta, float* __restrict__ out)
{
    __shared__ float red[2][8];
    const int row = blockIdx.x;
    const int tid = threadIdx.x;
    const float* x = X + (size_t)row * HID;

    float4 v = *(const float4*)&x[tid * 4];
    float s  = v.x + v.y + v.z + v.w;
    float ss = v.x * v.x + v.y * v.y + v.z * v.z + v.w * v.w;
#pragma unroll
    for (int o = 16; o > 0; o >>= 1) {
        s  += __shfl_xor_sync(0xffffffffu, s, o);
        ss += __shfl_xor_sync(0xffffffffu, ss, o);
    }
    const int w = tid >> 5, l = tid & 31;
    if (l == 0) { red[0][w] = s; red[1][w] = ss; }
    __syncthreads();
    if (w == 0) {
        float s2  = (l < 8) ? red[0][l] : 0.f;
        float ss2 = (l < 8) ? red[1][l] : 0.f;
#pragma unroll
        for (int o = 4; o > 0; o >>= 1) {
            s2  += __shfl_xor_sync(0xffffffffu, s2, o);
            ss2 += __shfl_xor_sync(0xffffffffu, ss2, o);
        }
        if (l == 0) { red[0][0] = s2; red[1][0] = ss2; }
    }
    __syncthreads();

    const float mean = red[0][0] * (1.f / HID);
    const float var  = red[1][0] * (1.f / HID) - mean * mean;
    const float rstd = rsqrtf(var + 1e-5f);

    const int c = tid * 4;
    float4 gv = *(const float4*)&gamma[c];
    float4 bv = *(const float4*)&beta[c];
    float4 o;
    o.x = (v.x - mean) * rstd * gv.x + bv.x;
    o.y = (v.y - mean) * rstd * gv.y + bv.y;
    o.z = (v.z - mean) * rstd * gv.z + bv.z;
    o.w = (v.w - mean) * rstd * gv.w + bv.w;
    *(float4*)&out[(size_t)row * HID + c] = o;
}

// ---------------------------------------------------------------------------
// Launch
// ---------------------------------------------------------------------------
extern "C" void kernel_launch(void* const* d_in, const int* in_sizes, int n_in,
                              void* d_out, int out_size)
{
    const float* hidden = (const float*)d_in[0];
    const float* Wq = (const float*)d_in[1];
    const float* bq = (const float*)d_in[2];
    const float* Wk = (const float*)d_in[3];
    const float* bk = (const float*)d_in[4];
    const float* Wv = (const float*)d_in[5];
    const float* bv = (const float*)d_in[6];
    const float* Wo = (const float*)d_in[7];
    const float* bo = (const float*)d_in[8];
    const float* gamma = (const float*)d_in[9];
    const float* beta  = (const float*)d_in[10];
    float* out = (float*)d_out;

    float *q, *k, *v, *ctx, *x;
    cudaGetSymbolAddress((void**)&q,   g_Q);
    cudaGetSymbolAddress((void**)&k,   g_K);
    cudaGetSymbolAddress((void**)&v,   g_V);
    cudaGetSymbolAddress((void**)&ctx, g_CTX);
    cudaGetSymbolAddress((void**)&x,   g_X);

    __nv_bfloat16 *hhi, *hlo, *chi, *clo;
    __nv_bfloat16 *wqh, *wql, *wkh, *wkl, *wvh, *wvl, *woh, *wol;
    cudaGetSymbolAddress((void**)&hhi, g_Hhi);
    cudaGetSymbolAddress((void**)&hlo, g_Hlo);
    cudaGetSymbolAddress((void**)&chi, g_Chi);
    cudaGetSymbolAddress((void**)&clo, g_Clo);
    cudaGetSymbolAddress((void**)&wqh, g_WqTh);
    cudaGetSymbolAddress((void**)&wql, g_WqTl);
    cudaGetSymbolAddress((void**)&wkh, g_WkTh);
    cudaGetSymbolAddress((void**)&wkl, g_WkTl);
    cudaGetSymbolAddress((void**)&wvh, g_WvTh);
    cudaGetSymbolAddress((void**)&wvl, g_WvTl);
    cudaGetSymbolAddress((void**)&woh, g_WoTh);
    cudaGetSymbolAddress((void**)&wol, g_WoTl);

    // ---- converts ----
    convert_split<<<(ROWS * HID / 4 + 255) / 256, 256>>>(hidden, hhi, hlo, ROWS * HID / 4);
    dim3 tg(HID / 32, HID / 32), tb(32, 8);
    transpose_split<<<tg, tb>>>(Wq, wqh, wql);
    transpose_split<<<tg, tb>>>(Wk, wkh, wkl);
    transpose_split<<<tg, tb>>>(Wv, wvh, wvl);
    transpose_split<<<tg, tb>>>(Wo, woh, wol);

    // ---- QKV projections (tensor core via mma.sync) ----
    dim3 gg(HID / 128, ROWS / 128);   // (8, 32)
    gemm_mma<<<gg, 256>>>(hhi, hlo, wqh, wql, bq, nullptr, q);
    gemm_mma<<<gg, 256>>>(hhi, hlo, wkh, wkl, bk, nullptr, k);
    gemm_mma<<<gg, 256>>>(hhi, hlo, wvh, wvl, bv, nullptr, v);

    // ---- attention (fp32 SIMT) ----
    cudaFuncSetAttribute(flash_attn, cudaFuncAttributeMaxDynamicSharedMemorySize,
                         ATT_SMEM_BYTES);
    flash_attn<<<dim3(SEQ / BQ, HEADS, BATCH), 256, ATT_SMEM_BYTES>>>(q, k, v, ctx);

    // ---- output projection + residual (tensor core via mma.sync) ----
    convert_split<<<(ROWS * HID / 4 + 255) / 256, 256>>>(ctx, chi, clo, ROWS * HID / 4);
    gemm_mma<<<gg, 256>>>(chi, clo, woh, wol, bo, hidden, x);

    // ---- layernorm ----
    layernorm_kernel<<<ROWS, 256>>>(x, gamma, beta, out);
}

// round 5
// speedup vs baseline: 1.7320x; 1.7320x over previous
#include <cuda_runtime.h>
#include <cuda_bf16.h>
#include <math.h>
#include <stdint.h>

// ---------------------------------------------------------------------------
// Problem constants
// ---------------------------------------------------------------------------
#define BATCH   2
#define SEQ     2048
#define HID     1024
#define HEADS   16
#define HDIM    64
#define ROWS    (BATCH * SEQ)          // 4096

// ---------------------------------------------------------------------------
// Scratch (static device globals -- no runtime allocation)
// ---------------------------------------------------------------------------
__device__ float g_Q[ROWS * HID];
__device__ float g_K[ROWS * HID];
__device__ float g_V[ROWS * HID];
__device__ float g_CTX[ROWS * HID];
__device__ float g_X[ROWS * HID];

// bf16 split buffers (hi/lo) for tensor-core GEMMs
__device__ __nv_bfloat16 g_Hhi[ROWS * HID];
__device__ __nv_bfloat16 g_Hlo[ROWS * HID];
__device__ __nv_bfloat16 g_Chi[ROWS * HID];
__device__ __nv_bfloat16 g_Clo[ROWS * HID];
__device__ __nv_bfloat16 g_WqTh[HID * HID];
__device__ __nv_bfloat16 g_WqTl[HID * HID];
__device__ __nv_bfloat16 g_WkTh[HID * HID];
__device__ __nv_bfloat16 g_WkTl[HID * HID];
__device__ __nv_bfloat16 g_WvTh[HID * HID];
__device__ __nv_bfloat16 g_WvTl[HID * HID];
__device__ __nv_bfloat16 g_WoTh[HID * HID];
__device__ __nv_bfloat16 g_WoTl[HID * HID];

// ---------------------------------------------------------------------------
// Warp MMA helpers (arch-agnostic PTX: ldmatrix + mma.sync bf16 + cp.async)
// ---------------------------------------------------------------------------
__device__ __forceinline__ uint32_t smem_u32(const void* p) {
    uint32_t a;
    asm("{ .reg .u64 t; cvta.to.shared.u64 t, %1; cvt.u32.u64 %0, t; }"
        : "=r"(a) : "l"(p));
    return a;
}

__device__ __forceinline__ void ldmx4(uint32_t& r0, uint32_t& r1, uint32_t& r2,
                                      uint32_t& r3, uint32_t addr) {
    asm volatile("ldmatrix.sync.aligned.m8n8.x4.shared.b16 {%0,%1,%2,%3}, [%4];"
                 : "=r"(r0), "=r"(r1), "=r"(r2), "=r"(r3) : "r"(addr));
}
__device__ __forceinline__ void ldmx2(uint32_t& r0, uint32_t& r1, uint32_t addr) {
    asm volatile("ldmatrix.sync.aligned.m8n8.x2.shared.b16 {%0,%1}, [%2];"
                 : "=r"(r0), "=r"(r1) : "r"(addr));
}
__device__ __forceinline__ void mma_bf16(float& d0, float& d1, float& d2, float& d3,
                                         uint32_t a0, uint32_t a1, uint32_t a2,
                                         uint32_t a3, uint32_t b0, uint32_t b1) {
    asm volatile(
        "mma.sync.aligned.m16n8k16.row.col.f32.bf16.bf16.f32 "
        "{%0,%1,%2,%3}, {%4,%5,%6,%7}, {%8,%9}, {%0,%1,%2,%3};"
        : "+f"(d0), "+f"(d1), "+f"(d2), "+f"(d3)
        : "r"(a0), "r"(a1), "r"(a2), "r"(a3), "r"(b0), "r"(b1));
}

__device__ __forceinline__ void cp16(uint32_t dst, const void* src) {
    asm volatile("cp.async.cg.shared.global [%0], [%1], 16;"
                 :: "r"(dst), "l"(src));
}
__device__ __forceinline__ void cp_commit() {
    asm volatile("cp.async.commit_group;" ::: "memory");
}
template <int N>
__device__ __forceinline__ void cp_wait() {
    asm volatile("cp.async.wait_group %0;" :: "n"(N) : "memory");
}

// ---------------------------------------------------------------------------
// fp32 -> bf16 hi/lo split (elementwise, float4-vectorized)
// ---------------------------------------------------------------------------
__device__ __forceinline__ void split1(float x, __nv_bfloat16& h, __nv_bfloat16& l) {
    h = __float2bfloat16(x);
    l = __float2bfloat16(x - __bfloat162float(h));
}

__global__ __launch_bounds__(256)
void convert_split(const float* __restrict__ in, __nv_bfloat16* __restrict__ hi,
                   __nv_bfloat16* __restrict__ lo, int n4)
{
    int i = blockIdx.x * blockDim.x + threadIdx.x;
    if (i >= n4) return;
    float4 v = ((const float4*)in)[i];
    __nv_bfloat16 h0, l0, h1, l1, h2, l2, h3, l3;
    split1(v.x, h0, l0); split1(v.y, h1, l1);
    split1(v.z, h2, l2); split1(v.w, h3, l3);
    ((__nv_bfloat162*)hi)[2 * i + 0] = __nv_bfloat162(h0, h1);
    ((__nv_bfloat162*)hi)[2 * i + 1] = __nv_bfloat162(h2, h3);
    ((__nv_bfloat162*)lo)[2 * i + 0] = __nv_bfloat162(l0, l1);
    ((__nv_bfloat162*)lo)[2 * i + 1] = __nv_bfloat162(l2, l3);
}

// ---------------------------------------------------------------------------
// W [K,N] fp32 -> transposed hi/lo bf16 [N,K]
// ---------------------------------------------------------------------------
__global__ __launch_bounds__(256)
void transpose_split(const float* __restrict__ W, __nv_bfloat16* __restrict__ Th,
                     __nv_bfloat16* __restrict__ Tl)
{
    __shared__ float t[32][33];
    const int n0 = blockIdx.x * 32, k0 = blockIdx.y * 32;
    const int tx = threadIdx.x, ty = threadIdx.y;
#pragma unroll
    for (int i = 0; i < 32; i += 8)
        t[ty + i][tx] = W[(size_t)(k0 + ty + i) * HID + n0 + tx];
    __syncthreads();
#pragma unroll
    for (int i = 0; i < 32; i += 8) {
        float x = t[tx][ty + i];     // W[k0+tx][n0+ty+i]
        __nv_bfloat16 h, l; split1(x, h, l);
        Th[(size_t)(n0 + ty + i) * HID + k0 + tx] = h;
        Tl[(size_t)(n0 + ty + i) * HID + k0 + tx] = l;
    }
}

// ---------------------------------------------------------------------------
// Pipelined tensor-core GEMM (bf16 hi/lo split, fp32 accum):
//   C[4096,1024] = A @ W (+bias)(+res)
//   CTA 128x128, 8 warps (2x4), warp tile 64x32 (4x4 m16n8 tiles).
//   BK=32 per stage; per stage smem: A[128][64] (hi|lo), B[128][64] (hi|lo),
//   rows 128B, chunk-XOR swizzle (c ^ (r&7)) -> conflict-free ldmatrix.
//   3-stage cp.async pipeline.
// ---------------------------------------------------------------------------
#define PIPE 3
#define STAGE_BYTES 32768            // 2 tiles * 128 rows * 128 B
#define GEMM_SMEM   (PIPE * STAGE_BYTES)
#define NKC  (HID / 32)              // 32 k-chunks

__global__ __launch_bounds__(256, 2)
void gemm_mma(const __nv_bfloat16* __restrict__ Ahi, const __nv_bfloat16* __restrict__ Alo,
              const __nv_bfloat16* __restrict__ Bhi, const __nv_bfloat16* __restrict__ Blo,
              const float* __restrict__ bias, const float* __restrict__ res,
              float* __restrict__ C)
{
    extern __shared__ char smc[];
    const uint32_t sbase = smem_u32(smc);

    const int tid  = threadIdx.x;
    const int lane = tid & 31;
    const int warp = tid >> 5;
    const int wm   = (warp >> 2) * 64;
    const int wn   = (warp & 3) * 32;
    const int m0 = blockIdx.y * 128, n0 = blockIdx.x * 128;

    // per-thread load slots: 8 x 16B per stage (2048 chunks / 256 threads)
    // idx = tid + t*256 ; tile = idx>>10 (0=A,1=B); r=(idx>>3)&127; c=idx&7
    auto load_stage = [&](int stage, int kc) {
        const uint32_t sb = sbase + stage * STAGE_BYTES;
#pragma unroll
        for (int t = 0; t < 8; t++) {
            int idx  = tid + t * 256;
            int tile = idx >> 10;
            int r    = (idx >> 3) & 127;
            int c    = idx & 7;
            const __nv_bfloat16* src;
            if (tile == 0)
                src = (c < 4 ? Ahi : Alo) + (size_t)(m0 + r) * HID + kc * 32 + (c & 3) * 8;
            else
                src = (c < 4 ? Bhi : Blo) + (size_t)(n0 + r) * HID + kc * 32 + (c & 3) * 8;
            uint32_t dst = sb + (uint32_t)(tile * 16384 + r * 128 + ((c ^ (r & 7)) * 16));
            cp16(dst, src);
        }
        cp_commit();
    };

    float acc[4][4][4];
#pragma unroll
    for (int mi = 0; mi < 4; mi++)
#pragma unroll
        for (int nj = 0; nj < 4; nj++)
#pragma unroll
            for (int e = 0; e < 4; e++) acc[mi][nj][e] = 0.f;

    load_stage(0, 0);
    load_stage(1, 1);

    for (int kc = 0; kc < NKC; kc++) {
        cp_wait<PIPE - 2>();
        __syncthreads();

        if (kc + 2 < NKC) load_stage((kc + 2) % PIPE, kc + 2);

        const uint32_t sA = sbase + (kc % PIPE) * STAGE_BYTES;
        const uint32_t sB = sA + 16384;

#pragma unroll
        for (int ks = 0; ks < 2; ks++) {
            // B fragments (hi + lo) for the 4 n-tiles
            uint32_t bh[4][2], bl[4][2];
#pragma unroll
            for (int nj = 0; nj < 4; nj++) {
                int r  = wn + nj * 8 + (lane & 7);
                int cc = ks * 2 + ((lane >> 3) & 1);
                ldmx2(bh[nj][0], bh[nj][1],
                      sB + (uint32_t)(r * 128 + ((cc ^ (r & 7)) * 16)));
                ldmx2(bl[nj][0], bl[nj][1],
                      sB + (uint32_t)(r * 128 + (((cc + 4) ^ (r & 7)) * 16)));
            }
#pragma unroll
            for (int mi = 0; mi < 4; mi++) {
                int r  = wm + mi * 16 + (lane & 15);
                int cc = ks * 2 + (lane >> 4);
                uint32_t ah0, ah1, ah2, ah3, al0, al1, al2, al3;
                ldmx4(ah0, ah1, ah2, ah3,
                      sA + (uint32_t)(r * 128 + ((cc ^ (r & 7)) * 16)));
                ldmx4(al0, al1, al2, al3,
                      sA + (uint32_t)(r * 128 + (((cc + 4) ^ (r & 7)) * 16)));
#pragma unroll
                for (int nj = 0; nj < 4; nj++) {
                    mma_bf16(acc[mi][nj][0], acc[mi][nj][1], acc[mi][nj][2], acc[mi][nj][3],
                             ah0, ah1, ah2, ah3, bh[nj][0], bh[nj][1]);
                    mma_bf16(acc[mi][nj][0], acc[mi][nj][1], acc[mi][nj][2], acc[mi][nj][3],
                             ah0, ah1, ah2, ah3, bl[nj][0], bl[nj][1]);
                    mma_bf16(acc[mi][nj][0], acc[mi][nj][1], acc[mi][nj][2], acc[mi][nj][3],
                             al0, al1, al2, al3, bh[nj][0], bh[nj][1]);
                }
            }
        }
    }

    // Epilogue: fragment layout -> direct float2 stores
#pragma unroll
    for (int mi = 0; mi < 4; mi++) {
#pragma unroll
        for (int nj = 0; nj < 4; nj++) {
            int row = m0 + wm + mi * 16 + (lane >> 2);
            int col = n0 + wn + nj * 8 + 2 * (lane & 3);
            float2 v0, v1;
            v0.x = acc[mi][nj][0] + bias[col];
            v0.y = acc[mi][nj][1] + bias[col + 1];
            v1.x = acc[mi][nj][2] + bias[col];
            v1.y = acc[mi][nj][3] + bias[col + 1];
            if (res) {
                float2 r0 = *(const float2*)&res[(size_t)row * HID + col];
                float2 r1 = *(const float2*)&res[(size_t)(row + 8) * HID + col];
                v0.x += r0.x; v0.y += r0.y;
                v1.x += r1.x; v1.y += r1.y;
            }
            *(float2*)&C[(size_t)row * HID + col] = v0;
            *(float2*)&C[(size_t)(row + 8) * HID + col] = v1;
        }
    }
}

// ---------------------------------------------------------------------------
// Flash attention v2 (fp32) -- unchanged from R2
// ---------------------------------------------------------------------------
#define BQ   128
#define BKT  128
#define QSTR 128
#define VSTR 64
#define PSTR 128

#define ATT_SMEM_FLOATS (64*QSTR + 64*QSTR + 128*VSTR + 128*PSTR)
#define ATT_SMEM_BYTES  (ATT_SMEM_FLOATS * 4)

__global__ __launch_bounds__(256)
void flash_attn(const float* __restrict__ Q, const float* __restrict__ K,
                const float* __restrict__ V, float* __restrict__ Ctx)
{
    extern __shared__ float smf[];
    float* Qs = smf;                 // [64][QSTR]   (d-major)
    float* Ks = Qs + 64 * QSTR;      // [64][QSTR]   (d-major)
    float* Vs = Ks + 64 * QSTR;      // [128][VSTR]  (k-major)
    float* Ps = Vs + 128 * VSTR;     // [128][PSTR]  (q-major)

    const int tid = threadIdx.x;
    const int tx = tid & 15;
    const int ty = tid >> 4;
    const int q0 = blockIdx.x * BQ;
    const int h  = blockIdx.y;
    const int b  = blockIdx.z;
    const size_t base = (size_t)b * SEQ * HID + (size_t)h * HDIM;

#pragma unroll
    for (int t = 0; t < 8; t++) {
        int fi  = tid + t * 256;
        int row = fi & 127;
        int d4  = (fi >> 7) * 4;
        float4 v = *(const float4*)&Q[base + (size_t)(q0 + row) * HID + d4];
        Qs[(d4 + 0) * QSTR + row] = v.x;
        Qs[(d4 + 1) * QSTR + row] = v.y;
        Qs[(d4 + 2) * QSTR + row] = v.z;
        Qs[(d4 + 3) * QSTR + row] = v.w;
    }

    float m[8], l[8], acc[8][4];
#pragma unroll
    for (int i = 0; i < 8; i++) {
        m[i] = -1e30f; l[i] = 0.f;
#pragma unroll
        for (int j = 0; j < 4; j++) acc[i][j] = 0.f;
    }

    const float scale = 0.125f;

    for (int kt = 0; kt < SEQ / BKT; kt++) {
        const int k0 = kt * BKT;
        __syncthreads();

#pragma unroll
        for (int t = 0; t < 8; t++) {
            int fi  = tid + t * 256;
            int row = fi & 127;
            int d4  = (fi >> 7) * 4;
            float4 kv = *(const float4*)&K[base + (size_t)(k0 + row) * HID + d4];
            Ks[(d4 + 0) * QSTR + row] = kv.x;
            Ks[(d4 + 1) * QSTR + row] = kv.y;
            Ks[(d4 + 2) * QSTR + row] = kv.z;
            Ks[(d4 + 3) * QSTR + row] = kv.w;
            int vrow = fi >> 4;
            int vd4  = (fi & 15) * 4;
            float4 vv = *(const float4*)&V[base + (size_t)(k0 + vrow) * HID + vd4];
            *(float4*)&Vs[vrow * VSTR + vd4] = vv;
        }
        __syncthreads();

        float s[8][8];
#pragma unroll
        for (int i = 0; i < 8; i++)
#pragma unroll
            for (int j = 0; j < 8; j++) s[i][j] = 0.f;

#pragma unroll 4
        for (int d = 0; d < 64; d++) {
            float4 qa = *(float4*)&Qs[d * QSTR + ty * 4];
            float4 qb = *(float4*)&Qs[d * QSTR + 64 + ty * 4];
            float4 ka = *(float4*)&Ks[d * QSTR + tx * 4];
            float4 kb = *(float4*)&Ks[d * QSTR + 64 + tx * 4];
            float a[8] = {qa.x, qa.y, qa.z, qa.w, qb.x, qb.y, qb.z, qb.w};
            float bb[8] = {ka.x, ka.y, ka.z, ka.w, kb.x, kb.y, kb.z, kb.w};
#pragma unroll
            for (int i = 0; i < 8; i++)
#pragma unroll
                for (int j = 0; j < 8; j++) s[i][j] += a[i] * bb[j];
        }

#pragma unroll
        for (int i = 0; i < 8; i++) {
#pragma unroll
            for (int j = 0; j < 8; j++) s[i][j] *= scale;
            float mx = s[i][0];
#pragma unroll
            for (int j = 1; j < 8; j++) mx = fmaxf(mx, s[i][j]);
            mx = fmaxf(mx, __shfl_xor_sync(0xffffffffu, mx, 1));
            mx = fmaxf(mx, __shfl_xor_sync(0xffffffffu, mx, 2));
            mx = fmaxf(mx, __shfl_xor_sync(0xffffffffu, mx, 4));
            mx = fmaxf(mx, __shfl_xor_sync(0xffffffffu, mx, 8));
            float m_new = fmaxf(m[i], mx);
            float alpha = __expf(m[i] - m_new);
            float sum = 0.f;
#pragma unroll
            for (int j = 0; j < 8; j++) {
                s[i][j] = __expf(s[i][j] - m_new);
                sum += s[i][j];
            }
            sum += __shfl_xor_sync(0xffffffffu, sum, 1);
            sum += __shfl_xor_sync(0xffffffffu, sum, 2);
            sum += __shfl_xor_sync(0xffffffffu, sum, 4);
            sum += __shfl_xor_sync(0xffffffffu, sum, 8);
            l[i] = l[i] * alpha + sum;
            m[i] = m_new;
#pragma unroll
            for (int j = 0; j < 4; j++) acc[i][j] *= alpha;
        }

#pragma unroll
        for (int i = 0; i < 8; i++) {
            int r = (i < 4) ? (ty * 4 + i) : (60 + ty * 4 + i);
            *(float4*)&Ps[r * PSTR + tx * 4] =
                make_float4(s[i][0], s[i][1], s[i][2], s[i][3]);
            *(float4*)&Ps[r * PSTR + 64 + tx * 4] =
                make_float4(s[i][4], s[i][5], s[i][6], s[i][7]);
        }
        __syncthreads();

#pragma unroll 4
        for (int k4 = 0; k4 < 32; k4++) {
            float4 v0 = *(float4*)&Vs[(k4 * 4 + 0) * VSTR + tx * 4];
            float4 v1 = *(float4*)&Vs[(k4 * 4 + 1) * VSTR + tx * 4];
            float4 v2 = *(float4*)&Vs[(k4 * 4 + 2) * VSTR + tx * 4];
            float4 v3 = *(float4*)&Vs[(k4 * 4 + 3) * VSTR + tx * 4];
#pragma unroll
            for (int i = 0; i < 8; i++) {
                int r = (i < 4) ? (ty * 4 + i) : (60 + ty * 4 + i);
                float4 p = *(float4*)&Ps[r * PSTR + k4 * 4];
                acc[i][0] += p.x * v0.x + p.y * v1.x + p.z * v2.x + p.w * v3.x;
                acc[i][1] += p.x * v0.y + p.y * v1.y + p.z * v2.y + p.w * v3.y;
                acc[i][2] += p.x * v0.z + p.y * v1.z + p.z * v2.z + p.w * v3.z;
                acc[i][3] += p.x * v0.w + p.y * v1.w + p.z * v2.w + p.w * v3.w;
            }
        }
    }

#pragma unroll
    for (int i = 0; i < 8; i++) {
        int r = (i < 4) ? (ty * 4 + i) : (60 + ty * 4 + i);
        float inv_l = 1.f / l[i];
        float4 o;
        o.x = acc[i][0] * inv_l;
        o.y = acc[i][1] * inv_l;
        o.z = acc[i][2] * inv_l;
        o.w = acc[i][3] * inv_l;
        *(float4*)&Ctx[base + (size_t)(q0 + r) * HID + tx * 4] = o;
    }
}

// ---------------------------------------------------------------------------
// LayerNorm: one block per row of 1024
// ---------------------------------------------------------------------------
__global__ __launch_bounds__(256)
void layernorm_kernel(const float* __restrict__ X, const float* __restrict__ gamma,
                      const float* __restrict__ beta, float* __restrict__ out)
{
    __shared__ float red[2][8];
    const int row = blockIdx.x;
    const int tid = threadIdx.x;
    const float* x = X + (size_t)row * HID;

    float4 v = *(const float4*)&x[tid * 4];
    float s  = v.x + v.y + v.z + v.w;
    float ss = v.x * v.x + v.y * v.y + v.z * v.z + v.w * v.w;
#pragma unroll
    for (int o = 16; o > 0; o >>= 1) {
        s  += __shfl_xor_sync(0xffffffffu, s, o);
        ss += __shfl_xor_sync(0xffffffffu, ss, o);
    }
    const int w = tid >> 5, l = tid & 31;
    if (l == 0) { red[0][w] = s; red[1][w] = ss; }
    __syncthreads();
    if (w == 0) {
        float s2  = (l < 8) ? red[0][l] : 0.f;
        float ss2 = (l < 8) ? red[1][l] : 0.f;
#pragma unroll
        for (int o = 4; o > 0; o >>= 1) {
            s2  += __shfl_xor_sync(0xffffffffu, s2, o);
            ss2 += __shfl_xor_sync(0xffffffffu, ss2, o);
        }
        if (l == 0) { red[0][0] = s2; red[1][0] = ss2; }
    }
    __syncthreads();

    const float mean = red[0][0] * (1.f / HID);
    const float var  = red[1][0] * (1.f / HID) - mean * mean;
    const float rstd = rsqrtf(var + 1e-5f);

    const int c = tid * 4;
    float4 gv = *(const float4*)&gamma[c];
    float4 bv = *(const float4*)&beta[c];
    float4 o;
    o.x = (v.x - mean) * rstd * gv.x + bv.x;
    o.y = (v.y - mean) * rstd * gv.y + bv.y;
    o.z = (v.z - mean) * rstd * gv.z + bv.z;
    o.w = (v.w - mean) * rstd * gv.w + bv.w;
    *(float4*)&out[(size_t)row * HID + c] = o;
}

// ---------------------------------------------------------------------------
// Launch
// ---------------------------------------------------------------------------
extern "C" void kernel_launch(void* const* d_in, const int* in_sizes, int n_in,
                              void* d_out, int out_size)
{
    const float* hidden = (const float*)d_in[0];
    const float* Wq = (const float*)d_in[1];
    const float* bq = (const float*)d_in[2];
    const float* Wk = (const float*)d_in[3];
    const float* bk = (const float*)d_in[4];
    const float* Wv = (const float*)d_in[5];
    const float* bv = (const float*)d_in[6];
    const float* Wo = (const float*)d_in[7];
    const float* bo = (const float*)d_in[8];
    const float* gamma = (const float*)d_in[9];
    const float* beta  = (const float*)d_in[10];
    float* out = (float*)d_out;

    float *q, *k, *v, *ctx, *x;
    cudaGetSymbolAddress((void**)&q,   g_Q);
    cudaGetSymbolAddress((void**)&k,   g_K);
    cudaGetSymbolAddress((void**)&v,   g_V);
    cudaGetSymbolAddress((void**)&ctx, g_CTX);
    cudaGetSymbolAddress((void**)&x,   g_X);

    __nv_bfloat16 *hhi, *hlo, *chi, *clo;
    __nv_bfloat16 *wqh, *wql, *wkh, *wkl, *wvh, *wvl, *woh, *wol;
    cudaGetSymbolAddress((void**)&hhi, g_Hhi);
    cudaGetSymbolAddress((void**)&hlo, g_Hlo);
    cudaGetSymbolAddress((void**)&chi, g_Chi);
    cudaGetSymbolAddress((void**)&clo, g_Clo);
    cudaGetSymbolAddress((void**)&wqh, g_WqTh);
    cudaGetSymbolAddress((void**)&wql, g_WqTl);
    cudaGetSymbolAddress((void**)&wkh, g_WkTh);
    cudaGetSymbolAddress((void**)&wkl, g_WkTl);
    cudaGetSymbolAddress((void**)&wvh, g_WvTh);
    cudaGetSymbolAddress((void**)&wvl, g_WvTl);
    cudaGetSymbolAddress((void**)&woh, g_WoTh);
    cudaGetSymbolAddress((void**)&wol, g_WoTl);

    // ---- converts ----
    convert_split<<<(ROWS * HID / 4 + 255) / 256, 256>>>(hidden, hhi, hlo, ROWS * HID / 4);
    dim3 tg(HID / 32, HID / 32), tb(32, 8);
    transpose_split<<<tg, tb>>>(Wq, wqh, wql);
    transpose_split<<<tg, tb>>>(Wk, wkh, wkl);
    transpose_split<<<tg, tb>>>(Wv, wvh, wvl);
    transpose_split<<<tg, tb>>>(Wo, woh, wol);

    // ---- QKV projections (pipelined mma.sync) ----
    cudaFuncSetAttribute(gemm_mma, cudaFuncAttributeMaxDynamicSharedMemorySize,
                         GEMM_SMEM);
    dim3 gg(HID / 128, ROWS / 128);   // (8, 32)
    gemm_mma<<<gg, 256, GEMM_SMEM>>>(hhi, hlo, wqh, wql, bq, nullptr, q);
    gemm_mma<<<gg, 256, GEMM_SMEM>>>(hhi, hlo, wkh, wkl, bk, nullptr, k);
    gemm_mma<<<gg, 256, GEMM_SMEM>>>(hhi, hlo, wvh, wvl, bv, nullptr, v);

    // ---- attention (fp32 SIMT) ----
    cudaFuncSetAttribute(flash_attn, cudaFuncAttributeMaxDynamicSharedMemorySize,
                         ATT_SMEM_BYTES);
    flash_attn<<<dim3(SEQ / BQ, HEADS, BATCH), 256, ATT_SMEM_BYTES>>>(q, k, v, ctx);

    // ---- output projection + residual (pipelined mma.sync) ----
    convert_split<<<(ROWS * HID / 4 + 255) / 256, 256>>>(ctx, chi, clo, ROWS * HID / 4);
    gemm_mma<<<gg, 256, GEMM_SMEM>>>(chi, clo, woh, wol, bo, hidden, x);

    // ---- layernorm ----
    layernorm_kernel<<<ROWS, 256>>>(x, gamma, beta, out);
}

// round 6
// speedup vs baseline: 3.6255x; 2.0932x over previous
#include <cuda_runtime.h>
#include <cuda_bf16.h>
#include <math.h>
#include <stdint.h>

// ---------------------------------------------------------------------------
// Problem constants
// ---------------------------------------------------------------------------
#define BATCH   2
#define SEQ     2048
#define HID     1024
#define HEADS   16
#define HDIM    64
#define ROWS    (BATCH * SEQ)          // 4096

// ---------------------------------------------------------------------------
// Scratch (static device globals -- no runtime allocation)
// ---------------------------------------------------------------------------
__device__ float g_X[ROWS * HID];

__device__ __nv_bfloat16 g_Hhi[ROWS * HID];
__device__ __nv_bfloat16 g_Hlo[ROWS * HID];
__device__ __nv_bfloat16 g_Qh[ROWS * HID];
__device__ __nv_bfloat16 g_Ql[ROWS * HID];
__device__ __nv_bfloat16 g_Kh[ROWS * HID];
__device__ __nv_bfloat16 g_Kl[ROWS * HID];
__device__ __nv_bfloat16 g_Vb[ROWS * HID];
__device__ __nv_bfloat16 g_Chi[ROWS * HID];
__device__ __nv_bfloat16 g_Clo[ROWS * HID];
__device__ __nv_bfloat16 g_WqTh[HID * HID];
__device__ __nv_bfloat16 g_WqTl[HID * HID];
__device__ __nv_bfloat16 g_WkTh[HID * HID];
__device__ __nv_bfloat16 g_WkTl[HID * HID];
__device__ __nv_bfloat16 g_WvTh[HID * HID];
__device__ __nv_bfloat16 g_WvTl[HID * HID];
__device__ __nv_bfloat16 g_WoTh[HID * HID];
__device__ __nv_bfloat16 g_WoTl[HID * HID];

// ---------------------------------------------------------------------------
// PTX helpers (arch-agnostic: ldmatrix + mma.sync bf16 + cp.async)
// ---------------------------------------------------------------------------
__device__ __forceinline__ uint32_t smem_u32(const void* p) {
    uint32_t a;
    asm("{ .reg .u64 t; cvta.to.shared.u64 t, %1; cvt.u32.u64 %0, t; }"
        : "=r"(a) : "l"(p));
    return a;
}
__device__ __forceinline__ void ldmx4(uint32_t& r0, uint32_t& r1, uint32_t& r2,
                                      uint32_t& r3, uint32_t addr) {
    asm volatile("ldmatrix.sync.aligned.m8n8.x4.shared.b16 {%0,%1,%2,%3}, [%4];"
                 : "=r"(r0), "=r"(r1), "=r"(r2), "=r"(r3) : "r"(addr));
}
__device__ __forceinline__ void ldmx2(uint32_t& r0, uint32_t& r1, uint32_t addr) {
    asm volatile("ldmatrix.sync.aligned.m8n8.x2.shared.b16 {%0,%1}, [%2];"
                 : "=r"(r0), "=r"(r1) : "r"(addr));
}
__device__ __forceinline__ void ldmx2t(uint32_t& r0, uint32_t& r1, uint32_t addr) {
    asm volatile("ldmatrix.sync.aligned.m8n8.x2.trans.shared.b16 {%0,%1}, [%2];"
                 : "=r"(r0), "=r"(r1) : "r"(addr));
}
__device__ __forceinline__ void mma_bf16(float& d0, float& d1, float& d2, float& d3,
                                         uint32_t a0, uint32_t a1, uint32_t a2,
                                         uint32_t a3, uint32_t b0, uint32_t b1) {
    asm volatile(
        "mma.sync.aligned.m16n8k16.row.col.f32.bf16.bf16.f32 "
        "{%0,%1,%2,%3}, {%4,%5,%6,%7}, {%8,%9}, {%0,%1,%2,%3};"
        : "+f"(d0), "+f"(d1), "+f"(d2), "+f"(d3)
        : "r"(a0), "r"(a1), "r"(a2), "r"(a3), "r"(b0), "r"(b1));
}
__device__ __forceinline__ void cp16(uint32_t dst, const void* src) {
    asm volatile("cp.async.cg.shared.global [%0], [%1], 16;"
                 :: "r"(dst), "l"(src));
}
__device__ __forceinline__ void cp_commit() {
    asm volatile("cp.async.commit_group;" ::: "memory");
}
template <int N>
__device__ __forceinline__ void cp_wait() {
    asm volatile("cp.async.wait_group %0;" :: "n"(N) : "memory");
}

__device__ __forceinline__ void split1(float x, __nv_bfloat16& h, __nv_bfloat16& l) {
    h = __float2bfloat16(x);
    l = __float2bfloat16(x - __bfloat162float(h));
}
__device__ __forceinline__ uint32_t packbf(__nv_bfloat16 a, __nv_bfloat16 b) {
    __nv_bfloat162 t(a, b);
    return *(uint32_t*)&t;
}

// ---------------------------------------------------------------------------
// fp32 -> bf16 hi/lo split (elementwise)
// ---------------------------------------------------------------------------
__global__ __launch_bounds__(256)
void convert_split(const float* __restrict__ in, __nv_bfloat16* __restrict__ hi,
                   __nv_bfloat16* __restrict__ lo, int n4)
{
    int i = blockIdx.x * blockDim.x + threadIdx.x;
    if (i >= n4) return;
    float4 v = ((const float4*)in)[i];
    __nv_bfloat16 h0, l0, h1, l1, h2, l2, h3, l3;
    split1(v.x, h0, l0); split1(v.y, h1, l1);
    split1(v.z, h2, l2); split1(v.w, h3, l3);
    ((__nv_bfloat162*)hi)[2 * i + 0] = __nv_bfloat162(h0, h1);
    ((__nv_bfloat162*)hi)[2 * i + 1] = __nv_bfloat162(h2, h3);
    ((__nv_bfloat162*)lo)[2 * i + 0] = __nv_bfloat162(l0, l1);
    ((__nv_bfloat162*)lo)[2 * i + 1] = __nv_bfloat162(l2, l3);
}

// ---------------------------------------------------------------------------
// W [K,N] fp32 -> transposed hi/lo bf16 [N,K]
// ---------------------------------------------------------------------------
__global__ __launch_bounds__(256)
void transpose_split(const float* __restrict__ W, __nv_bfloat16* __restrict__ Th,
                     __nv_bfloat16* __restrict__ Tl)
{
    __shared__ float t[32][33];
    const int n0 = blockIdx.x * 32, k0 = blockIdx.y * 32;
    const int tx = threadIdx.x, ty = threadIdx.y;
#pragma unroll
    for (int i = 0; i < 32; i += 8)
        t[ty + i][tx] = W[(size_t)(k0 + ty + i) * HID + n0 + tx];
    __syncthreads();
#pragma unroll
    for (int i = 0; i < 32; i += 8) {
        float x = t[tx][ty + i];
        __nv_bfloat16 h, l; split1(x, h, l);
        Th[(size_t)(n0 + ty + i) * HID + k0 + tx] = h;
        Tl[(size_t)(n0 + ty + i) * HID + k0 + tx] = l;
    }
}

// ---------------------------------------------------------------------------
// Pipelined split-bf16 GEMM (mma.sync), flexible epilogue:
//   Cf != null   -> fp32 output (+res)
//   else Ch (+Cl) -> bf16 hi(+lo) output
// ---------------------------------------------------------------------------
#define PIPE 3
#define STAGE_BYTES 32768
#define GEMM_SMEM   (PIPE * STAGE_BYTES)
#define NKC  (HID / 32)

__global__ __launch_bounds__(256, 2)
void gemm_mma(const __nv_bfloat16* __restrict__ Ahi, const __nv_bfloat16* __restrict__ Alo,
              const __nv_bfloat16* __restrict__ Bhi, const __nv_bfloat16* __restrict__ Blo,
              const float* __restrict__ bias, const float* __restrict__ res,
              float* __restrict__ Cf, __nv_bfloat16* __restrict__ Ch,
              __nv_bfloat16* __restrict__ Cl)
{
    extern __shared__ char smc[];
    const uint32_t sbase = smem_u32(smc);

    const int tid  = threadIdx.x;
    const int lane = tid & 31;
    const int warp = tid >> 5;
    const int wm   = (warp >> 2) * 64;
    const int wn   = (warp & 3) * 32;
    const int m0 = blockIdx.y * 128, n0 = blockIdx.x * 128;

    auto load_stage = [&](int stage, int kc) {
        const uint32_t sb = sbase + stage * STAGE_BYTES;
#pragma unroll
        for (int t = 0; t < 8; t++) {
            int idx  = tid + t * 256;
            int tile = idx >> 10;
            int r    = (idx >> 3) & 127;
            int c    = idx & 7;
            const __nv_bfloat16* src;
            if (tile == 0)
                src = (c < 4 ? Ahi : Alo) + (size_t)(m0 + r) * HID + kc * 32 + (c & 3) * 8;
            else
                src = (c < 4 ? Bhi : Blo) + (size_t)(n0 + r) * HID + kc * 32 + (c & 3) * 8;
            uint32_t dst = sb + (uint32_t)(tile * 16384 + r * 128 + ((c ^ (r & 7)) * 16));
            cp16(dst, src);
        }
        cp_commit();
    };

    float acc[4][4][4];
#pragma unroll
    for (int mi = 0; mi < 4; mi++)
#pragma unroll
        for (int nj = 0; nj < 4; nj++)
#pragma unroll
            for (int e = 0; e < 4; e++) acc[mi][nj][e] = 0.f;

    load_stage(0, 0);
    load_stage(1, 1);

    for (int kc = 0; kc < NKC; kc++) {
        cp_wait<PIPE - 2>();
        __syncthreads();

        if (kc + 2 < NKC) load_stage((kc + 2) % PIPE, kc + 2);

        const uint32_t sA = sbase + (kc % PIPE) * STAGE_BYTES;
        const uint32_t sB = sA + 16384;

#pragma unroll
        for (int ks = 0; ks < 2; ks++) {
            uint32_t bh[4][2], bl[4][2];
#pragma unroll
            for (int nj = 0; nj < 4; nj++) {
                int r  = wn + nj * 8 + (lane & 7);
                int cc = ks * 2 + ((lane >> 3) & 1);
                ldmx2(bh[nj][0], bh[nj][1],
                      sB + (uint32_t)(r * 128 + ((cc ^ (r & 7)) * 16)));
                ldmx2(bl[nj][0], bl[nj][1],
                      sB + (uint32_t)(r * 128 + (((cc + 4) ^ (r & 7)) * 16)));
            }
#pragma unroll
            for (int mi = 0; mi < 4; mi++) {
                int r  = wm + mi * 16 + (lane & 15);
                int cc = ks * 2 + (lane >> 4);
                uint32_t ah0, ah1, ah2, ah3, al0, al1, al2, al3;
                ldmx4(ah0, ah1, ah2, ah3,
                      sA + (uint32_t)(r * 128 + ((cc ^ (r & 7)) * 16)));
                ldmx4(al0, al1, al2, al3,
                      sA + (uint32_t)(r * 128 + (((cc + 4) ^ (r & 7)) * 16)));
#pragma unroll
                for (int nj = 0; nj < 4; nj++) {
                    mma_bf16(acc[mi][nj][0], acc[mi][nj][1], acc[mi][nj][2], acc[mi][nj][3],
                             ah0, ah1, ah2, ah3, bh[nj][0], bh[nj][1]);
                    mma_bf16(acc[mi][nj][0], acc[mi][nj][1], acc[mi][nj][2], acc[mi][nj][3],
                             ah0, ah1, ah2, ah3, bl[nj][0], bl[nj][1]);
                    mma_bf16(acc[mi][nj][0], acc[mi][nj][1], acc[mi][nj][2], acc[mi][nj][3],
                             al0, al1, al2, al3, bh[nj][0], bh[nj][1]);
                }
            }
        }
    }

#pragma unroll
    for (int mi = 0; mi < 4; mi++) {
#pragma unroll
        for (int nj = 0; nj < 4; nj++) {
            int row = m0 + wm + mi * 16 + (lane >> 2);
            int col = n0 + wn + nj * 8 + 2 * (lane & 3);
            float b0 = bias[col], b1 = bias[col + 1];
            float v00 = acc[mi][nj][0] + b0, v01 = acc[mi][nj][1] + b1;
            float v10 = acc[mi][nj][2] + b0, v11 = acc[mi][nj][3] + b1;
            if (Cf) {
                if (res) {
                    float2 r0 = *(const float2*)&res[(size_t)row * HID + col];
                    float2 r1 = *(const float2*)&res[(size_t)(row + 8) * HID + col];
                    v00 += r0.x; v01 += r0.y; v10 += r1.x; v11 += r1.y;
                }
                *(float2*)&Cf[(size_t)row * HID + col] = make_float2(v00, v01);
                *(float2*)&Cf[(size_t)(row + 8) * HID + col] = make_float2(v10, v11);
            } else {
                __nv_bfloat16 h00, l00, h01, l01, h10, l10, h11, l11;
                split1(v00, h00, l00); split1(v01, h01, l01);
                split1(v10, h10, l10); split1(v11, h11, l11);
                *(__nv_bfloat162*)&Ch[(size_t)row * HID + col] = __nv_bfloat162(h00, h01);
                *(__nv_bfloat162*)&Ch[(size_t)(row + 8) * HID + col] = __nv_bfloat162(h10, h11);
                if (Cl) {
                    *(__nv_bfloat162*)&Cl[(size_t)row * HID + col] = __nv_bfloat162(l00, l01);
                    *(__nv_bfloat162*)&Cl[(size_t)(row + 8) * HID + col] = __nv_bfloat162(l10, l11);
                }
            }
        }
    }
}

// ---------------------------------------------------------------------------
// Flash attention via mma.sync (bf16 split):
//   S = Qh*Kh + Qh*Kl + Ql*Kh ; softmax in fragments; O += Ph*V + Pl*V.
//   CTA: 128 q-rows, 8 warps x 16 rows. K-tile 128. Double-buffered cp.async.
//   Writes ctx as bf16 hi/lo.
// ---------------------------------------------------------------------------
#define ASTAGE 49152                           // Khi 16K + Klo 16K + V 16K
#define ATT_SMEM (32768 + 2 * ASTAGE)          // + Qhi/Qlo 32K = 128K

__global__ __launch_bounds__(256)
void flash_mma(const __nv_bfloat16* __restrict__ Qh, const __nv_bfloat16* __restrict__ Ql,
               const __nv_bfloat16* __restrict__ Kh, const __nv_bfloat16* __restrict__ Kl,
               const __nv_bfloat16* __restrict__ Vb,
               __nv_bfloat16* __restrict__ Ch, __nv_bfloat16* __restrict__ Cl)
{
    extern __shared__ char sma[];
    const uint32_t sQ = smem_u32(sma);        // Qhi 16K | Qlo 16K
    const uint32_t sS = sQ + 32768;           // 2 stages of {Khi,Klo,V}

    const int tid = threadIdx.x, lane = tid & 31, warp = tid >> 5;
    const int q0 = blockIdx.x * 128;
    const int h = blockIdx.y, b = blockIdx.z;
    const size_t gb = (size_t)b * SEQ * HID + (size_t)h * HDIM;

    // Q tiles -> smem (swizzled)
#pragma unroll
    for (int t = 0; t < 8; t++) {
        int idx = tid + t * 256;
        int tile = idx >> 10, r = (idx >> 3) & 127, c = idx & 7;
        const __nv_bfloat16* src = (tile ? Ql : Qh) + gb + (size_t)(q0 + r) * HID + c * 8;
        cp16(sQ + (uint32_t)(tile * 16384 + r * 128 + ((c ^ (r & 7)) * 16)), src);
    }
    cp_commit();

    auto loadKV = [&](int stage, int kt) {
        const uint32_t sb = sS + stage * ASTAGE;
#pragma unroll
        for (int t = 0; t < 12; t++) {
            int idx = tid + t * 256;
            int tile = idx >> 10, r = (idx >> 3) & 127, c = idx & 7;
            const __nv_bfloat16* src =
                (tile == 0 ? Kh : tile == 1 ? Kl : Vb) + gb + (size_t)(kt * 128 + r) * HID + c * 8;
            cp16(sb + (uint32_t)(tile * 16384 + r * 128 + ((c ^ (r & 7)) * 16)), src);
        }
        cp_commit();
    };
    loadKV(0, 0);
    loadKV(1, 1);

    cp_wait<2>();          // Q resident
    __syncthreads();

    // Q fragments (registers, whole kernel)
    const int wq = warp * 16;
    uint32_t qh[4][4], ql[4][4];
#pragma unroll
    for (int dc = 0; dc < 4; dc++) {
        int r = wq + (lane & 15);
        int cc = dc * 2 + (lane >> 4);
        uint32_t a = sQ + (uint32_t)(r * 128 + ((cc ^ (r & 7)) * 16));
        ldmx4(qh[dc][0], qh[dc][1], qh[dc][2], qh[dc][3], a);
        ldmx4(ql[dc][0], ql[dc][1], ql[dc][2], ql[dc][3], a + 16384);
    }

    float m0 = -1e30f, m1 = -1e30f, l0 = 0.f, l1 = 0.f;
    float o[8][4];
#pragma unroll
    for (int dj = 0; dj < 8; dj++)
#pragma unroll
        for (int e = 0; e < 4; e++) o[dj][e] = 0.f;

    for (int kt = 0; kt < SEQ / 128; kt++) {
        cp_wait<1>();
        __syncthreads();
        const uint32_t sK  = sS + (kt & 1) * ASTAGE;
        const uint32_t sKl = sK + 16384;
        const uint32_t sV  = sK + 32768;

        // ---- S = Q K^T (3-term split) ----
        float s[16][4];
#pragma unroll
        for (int nj = 0; nj < 16; nj++)
#pragma unroll
            for (int e = 0; e < 4; e++) s[nj][e] = 0.f;

#pragma unroll
        for (int nj = 0; nj < 16; nj++) {
            int r = nj * 8 + (lane & 7);
#pragma unroll
            for (int dc = 0; dc < 4; dc++) {
                int cc = dc * 2 + ((lane >> 3) & 1);
                uint32_t offh = (uint32_t)(r * 128 + ((cc ^ (r & 7)) * 16));
                uint32_t offl = (uint32_t)(r * 128 + (((cc + 4) ^ (r & 7)) * 16));
                // hi/lo K stored in separate 16K tiles, same layout (8 chunks/row)
                uint32_t bh0, bh1, bl0, bl1;
                ldmx2(bh0, bh1, sK + offh);
                ldmx2(bl0, bl1, sKl + offh);
                (void)offl;
                mma_bf16(s[nj][0], s[nj][1], s[nj][2], s[nj][3],
                         qh[dc][0], qh[dc][1], qh[dc][2], qh[dc][3], bh0, bh1);
                mma_bf16(s[nj][0], s[nj][1], s[nj][2], s[nj][3],
                         qh[dc][0], qh[dc][1], qh[dc][2], qh[dc][3], bl0, bl1);
                mma_bf16(s[nj][0], s[nj][1], s[nj][2], s[nj][3],
                         ql[dc][0], ql[dc][1], ql[dc][2], ql[dc][3], bh0, bh1);
            }
        }

        // ---- online softmax on fragments ----
        const float sc = 0.125f;
        float mx0 = -1e30f, mx1 = -1e30f;
#pragma unroll
        for (int nj = 0; nj < 16; nj++) {
            s[nj][0] *= sc; s[nj][1] *= sc; s[nj][2] *= sc; s[nj][3] *= sc;
            mx0 = fmaxf(mx0, fmaxf(s[nj][0], s[nj][1]));
            mx1 = fmaxf(mx1, fmaxf(s[nj][2], s[nj][3]));
        }
        mx0 = fmaxf(mx0, __shfl_xor_sync(0xffffffffu, mx0, 1));
        mx0 = fmaxf(mx0, __shfl_xor_sync(0xffffffffu, mx0, 2));
        mx1 = fmaxf(mx1, __shfl_xor_sync(0xffffffffu, mx1, 1));
        mx1 = fmaxf(mx1, __shfl_xor_sync(0xffffffffu, mx1, 2));
        float mn0 = fmaxf(m0, mx0), mn1 = fmaxf(m1, mx1);
        float a0 = __expf(m0 - mn0), a1 = __expf(m1 - mn1);
        float sum0 = 0.f, sum1 = 0.f;
#pragma unroll
        for (int nj = 0; nj < 16; nj++) {
            s[nj][0] = __expf(s[nj][0] - mn0);
            s[nj][1] = __expf(s[nj][1] - mn0);
            s[nj][2] = __expf(s[nj][2] - mn1);
            s[nj][3] = __expf(s[nj][3] - mn1);
            sum0 += s[nj][0] + s[nj][1];
            sum1 += s[nj][2] + s[nj][3];
        }
        sum0 += __shfl_xor_sync(0xffffffffu, sum0, 1);
        sum0 += __shfl_xor_sync(0xffffffffu, sum0, 2);
        sum1 += __shfl_xor_sync(0xffffffffu, sum1, 1);
        sum1 += __shfl_xor_sync(0xffffffffu, sum1, 2);
        l0 = l0 * a0 + sum0; l1 = l1 * a1 + sum1;
        m0 = mn0; m1 = mn1;
#pragma unroll
        for (int dj = 0; dj < 8; dj++) {
            o[dj][0] *= a0; o[dj][1] *= a0; o[dj][2] *= a1; o[dj][3] *= a1;
        }

        // ---- O += P V (P hi/lo from fragments, V via ldmatrix.trans) ----
#pragma unroll
        for (int kc = 0; kc < 8; kc++) {
            uint32_t ph[4], pl[4];
#pragma unroll
            for (int half = 0; half < 2; half++) {
                float p0 = s[2 * kc + half][0], p1 = s[2 * kc + half][1];
                float p2 = s[2 * kc + half][2], p3 = s[2 * kc + half][3];
                __nv_bfloat16 h0, e0, h1, e1, h2, e2, h3, e3;
                split1(p0, h0, e0); split1(p1, h1, e1);
                split1(p2, h2, e2); split1(p3, h3, e3);
                ph[2 * half + 0] = packbf(h0, h1);  // rows g,   k lo
                ph[2 * half + 1] = packbf(h2, h3);  // rows g+8
                pl[2 * half + 0] = packbf(e0, e1);
                pl[2 * half + 1] = packbf(e2, e3);
            }
            // reorder: a0=tile(2kc) rows g ; a1=tile(2kc) rows g+8 ;
            //          a2=tile(2kc+1) rows g ; a3=tile(2kc+1) rows g+8
            uint32_t A0 = ph[0], A1 = ph[1], A2 = ph[2], A3 = ph[3];
            uint32_t L0 = pl[0], L1 = pl[1], L2 = pl[2], L3 = pl[3];
            int r = kc * 16 + (lane & 15);
#pragma unroll
            for (int dj = 0; dj < 8; dj++) {
                uint32_t addr = sV + (uint32_t)(r * 128 + ((dj ^ (r & 7)) * 16));
                uint32_t b0, b1;
                ldmx2t(b0, b1, addr);
                mma_bf16(o[dj][0], o[dj][1], o[dj][2], o[dj][3], A0, A1, A2, A3, b0, b1);
                mma_bf16(o[dj][0], o[dj][1], o[dj][2], o[dj][3], L0, L1, L2, L3, b0, b1);
            }
        }

        __syncthreads();
        if (kt + 2 < SEQ / 128) loadKV(kt & 1, kt + 2);
    }

    // ---- epilogue: normalize, split hi/lo, store ctx ----
    float i0 = 1.f / l0, i1 = 1.f / l1;
    int r0 = q0 + wq + (lane >> 2);
    int cb = 2 * (lane & 3);
#pragma unroll
    for (int dj = 0; dj < 8; dj++) {
        int col = dj * 8 + cb;
        float v00 = o[dj][0] * i0, v01 = o[dj][1] * i0;
        float v10 = o[dj][2] * i1, v11 = o[dj][3] * i1;
        __nv_bfloat16 h00, l00, h01, l01, h10, l10, h11, l11;
        split1(v00, h00, l00); split1(v01, h01, l01);
        split1(v10, h10, l10); split1(v11, h11, l11);
        *(__nv_bfloat162*)&Ch[gb + (size_t)r0 * HID + col] = __nv_bfloat162(h00, h01);
        *(__nv_bfloat162*)&Ch[gb + (size_t)(r0 + 8) * HID + col] = __nv_bfloat162(h10, h11);
        *(__nv_bfloat162*)&Cl[gb + (size_t)r0 * HID + col] = __nv_bfloat162(l00, l01);
        *(__nv_bfloat162*)&Cl[gb + (size_t)(r0 + 8) * HID + col] = __nv_bfloat162(l10, l11);
    }
}

// ---------------------------------------------------------------------------
// LayerNorm: one block per row of 1024
// ---------------------------------------------------------------------------
__global__ __launch_bounds__(256)
void layernorm_kernel(const float* __restrict__ X, const float* __restrict__ gamma,
                      const float* __restrict__ beta, float* __restrict__ out)
{
    __shared__ float red[2][8];
    const int row = blockIdx.x;
    const int tid = threadIdx.x;
    const float* x = X + (size_t)row * HID;

    float4 v = *(const float4*)&x[tid * 4];
    float s  = v.x + v.y + v.z + v.w;
    float ss = v.x * v.x + v.y * v.y + v.z * v.z + v.w * v.w;
#pragma unroll
    for (int o = 16; o > 0; o >>= 1) {
        s  += __shfl_xor_sync(0xffffffffu, s, o);
        ss += __shfl_xor_sync(0xffffffffu, ss, o);
    }
    const int w = tid >> 5, l = tid & 31;
    if (l == 0) { red[0][w] = s; red[1][w] = ss; }
    __syncthreads();
    if (w == 0) {
        float s2  = (l < 8) ? red[0][l] : 0.f;
        float ss2 = (l < 8) ? red[1][l] : 0.f;
#pragma unroll
        for (int o = 4; o > 0; o >>= 1) {
            s2  += __shfl_xor_sync(0xffffffffu, s2, o);
            ss2 += __shfl_xor_sync(0xffffffffu, ss2, o);
        }
        if (l == 0) { red[0][0] = s2; red[1][0] = ss2; }
    }
    __syncthreads();

    const float mean = red[0][0] * (1.f / HID);
    const float var  = red[1][0] * (1.f / HID) - mean * mean;
    const float rstd = rsqrtf(var + 1e-5f);

    const int c = tid * 4;
    float4 gv = *(const float4*)&gamma[c];
    float4 bv = *(const float4*)&beta[c];
    float4 o;
    o.x = (v.x - mean) * rstd * gv.x + bv.x;
    o.y = (v.y - mean) * rstd * gv.y + bv.y;
    o.z = (v.z - mean) * rstd * gv.z + bv.z;
    o.w = (v.w - mean) * rstd * gv.w + bv.w;
    *(float4*)&out[(size_t)row * HID + c] = o;
}

// ---------------------------------------------------------------------------
// Launch
// ---------------------------------------------------------------------------
extern "C" void kernel_launch(void* const* d_in, const int* in_sizes, int n_in,
                              void* d_out, int out_size)
{
    const float* hidden = (const float*)d_in[0];
    const float* Wq = (const float*)d_in[1];
    const float* bq = (const float*)d_in[2];
    const float* Wk = (const float*)d_in[3];
    const float* bk = (const float*)d_in[4];
    const float* Wv = (const float*)d_in[5];
    const float* bv = (const float*)d_in[6];
    const float* Wo = (const float*)d_in[7];
    const float* bo = (const float*)d_in[8];
    const float* gamma = (const float*)d_in[9];
    const float* beta  = (const float*)d_in[10];
    float* out = (float*)d_out;

    float* x;
    cudaGetSymbolAddress((void**)&x, g_X);

    __nv_bfloat16 *hhi, *hlo, *chi, *clo, *qhp, *qlp, *khp, *klp, *vbp;
    __nv_bfloat16 *wqh, *wql, *wkh, *wkl, *wvh, *wvl, *woh, *wol;
    cudaGetSymbolAddress((void**)&hhi, g_Hhi);
    cudaGetSymbolAddress((void**)&hlo, g_Hlo);
    cudaGetSymbolAddress((void**)&chi, g_Chi);
    cudaGetSymbolAddress((void**)&clo, g_Clo);
    cudaGetSymbolAddress((void**)&qhp, g_Qh);
    cudaGetSymbolAddress((void**)&qlp, g_Ql);
    cudaGetSymbolAddress((void**)&khp, g_Kh);
    cudaGetSymbolAddress((void**)&klp, g_Kl);
    cudaGetSymbolAddress((void**)&vbp, g_Vb);
    cudaGetSymbolAddress((void**)&wqh, g_WqTh);
    cudaGetSymbolAddress((void**)&wql, g_WqTl);
    cudaGetSymbolAddress((void**)&wkh, g_WkTh);
    cudaGetSymbolAddress((void**)&wkl, g_WkTl);
    cudaGetSymbolAddress((void**)&wvh, g_WvTh);
    cudaGetSymbolAddress((void**)&wvl, g_WvTl);
    cudaGetSymbolAddress((void**)&woh, g_WoTh);
    cudaGetSymbolAddress((void**)&wol, g_WoTl);

    // ---- prep ----
    convert_split<<<(ROWS * HID / 4 + 255) / 256, 256>>>(hidden, hhi, hlo, ROWS * HID / 4);
    dim3 tg(HID / 32, HID / 32), tb(32, 8);
    transpose_split<<<tg, tb>>>(Wq, wqh, wql);
    transpose_split<<<tg, tb>>>(Wk, wkh, wkl);
    transpose_split<<<tg, tb>>>(Wv, wvh, wvl);
    transpose_split<<<tg, tb>>>(Wo, woh, wol);

    // ---- QKV projections -> bf16 outputs ----
    cudaFuncSetAttribute(gemm_mma, cudaFuncAttributeMaxDynamicSharedMemorySize, GEMM_SMEM);
    dim3 gg(HID / 128, ROWS / 128);
    gemm_mma<<<gg, 256, GEMM_SMEM>>>(hhi, hlo, wqh, wql, bq, nullptr, nullptr, qhp, qlp);
    gemm_mma<<<gg, 256, GEMM_SMEM>>>(hhi, hlo, wkh, wkl, bk, nullptr, nullptr, khp, klp);
    gemm_mma<<<gg, 256, GEMM_SMEM>>>(hhi, hlo, wvh, wvl, bv, nullptr, nullptr, vbp, nullptr);

    // ---- attention (tensor core) ----
    cudaFuncSetAttribute(flash_mma, cudaFuncAttributeMaxDynamicSharedMemorySize, ATT_SMEM);
    flash_mma<<<dim3(SEQ / 128, HEADS, BATCH), 256, ATT_SMEM>>>(qhp, qlp, khp, klp, vbp,
                                                                chi, clo);

    // ---- output projection + residual (fp32 out) ----
    gemm_mma<<<gg, 256, GEMM_SMEM>>>(chi, clo, woh, wol, bo, hidden, x, nullptr, nullptr);

    // ---- layernorm ----
    layernorm_kernel<<<ROWS, 256>>>(x, gamma, beta, out);
}

// round 7
// speedup vs baseline: 4.0495x; 1.1170x over previous
#include <cuda_runtime.h>
#include <cuda_bf16.h>
#include <math.h>
#include <stdint.h>

// ---------------------------------------------------------------------------
// Problem constants
// ---------------------------------------------------------------------------
#define BATCH   2
#define SEQ     2048
#define HID     1024
#define HEADS   16
#define HDIM    64
#define ROWS    (BATCH * SEQ)          // 4096

// ---------------------------------------------------------------------------
// Scratch (static device globals -- no runtime allocation)
// ---------------------------------------------------------------------------
__device__ float g_X[ROWS * HID];

__device__ __nv_bfloat16 g_Hhi[ROWS * HID];
__device__ __nv_bfloat16 g_Hlo[ROWS * HID];
__device__ __nv_bfloat16 g_Qh[ROWS * HID];
__device__ __nv_bfloat16 g_Ql[ROWS * HID];
__device__ __nv_bfloat16 g_Kh[ROWS * HID];
__device__ __nv_bfloat16 g_Kl[ROWS * HID];
__device__ __nv_bfloat16 g_Vb[ROWS * HID];
__device__ __nv_bfloat16 g_Chi[ROWS * HID];
__device__ __nv_bfloat16 g_Clo[ROWS * HID];
__device__ __nv_bfloat16 g_WqTh[HID * HID];
__device__ __nv_bfloat16 g_WqTl[HID * HID];
__device__ __nv_bfloat16 g_WkTh[HID * HID];
__device__ __nv_bfloat16 g_WkTl[HID * HID];
__device__ __nv_bfloat16 g_WvTh[HID * HID];
__device__ __nv_bfloat16 g_WvTl[HID * HID];
__device__ __nv_bfloat16 g_WoTh[HID * HID];
__device__ __nv_bfloat16 g_WoTl[HID * HID];

// ---------------------------------------------------------------------------
// PTX helpers
// ---------------------------------------------------------------------------
__device__ __forceinline__ uint32_t smem_u32(const void* p) {
    uint32_t a;
    asm("{ .reg .u64 t; cvta.to.shared.u64 t, %1; cvt.u32.u64 %0, t; }"
        : "=r"(a) : "l"(p));
    return a;
}
__device__ __forceinline__ void ldmx4(uint32_t& r0, uint32_t& r1, uint32_t& r2,
                                      uint32_t& r3, uint32_t addr) {
    asm volatile("ldmatrix.sync.aligned.m8n8.x4.shared.b16 {%0,%1,%2,%3}, [%4];"
                 : "=r"(r0), "=r"(r1), "=r"(r2), "=r"(r3) : "r"(addr));
}
__device__ __forceinline__ void ldmx2(uint32_t& r0, uint32_t& r1, uint32_t addr) {
    asm volatile("ldmatrix.sync.aligned.m8n8.x2.shared.b16 {%0,%1}, [%2];"
                 : "=r"(r0), "=r"(r1) : "r"(addr));
}
__device__ __forceinline__ void ldmx2t(uint32_t& r0, uint32_t& r1, uint32_t addr) {
    asm volatile("ldmatrix.sync.aligned.m8n8.x2.trans.shared.b16 {%0,%1}, [%2];"
                 : "=r"(r0), "=r"(r1) : "r"(addr));
}
__device__ __forceinline__ void mma_bf16(float& d0, float& d1, float& d2, float& d3,
                                         uint32_t a0, uint32_t a1, uint32_t a2,
                                         uint32_t a3, uint32_t b0, uint32_t b1) {
    asm volatile(
        "mma.sync.aligned.m16n8k16.row.col.f32.bf16.bf16.f32 "
        "{%0,%1,%2,%3}, {%4,%5,%6,%7}, {%8,%9}, {%0,%1,%2,%3};"
        : "+f"(d0), "+f"(d1), "+f"(d2), "+f"(d3)
        : "r"(a0), "r"(a1), "r"(a2), "r"(a3), "r"(b0), "r"(b1));
}
__device__ __forceinline__ void cp16(uint32_t dst, const void* src) {
    asm volatile("cp.async.cg.shared.global [%0], [%1], 16;"
                 :: "r"(dst), "l"(src));
}
__device__ __forceinline__ void cp_commit() {
    asm volatile("cp.async.commit_group;" ::: "memory");
}
template <int N>
__device__ __forceinline__ void cp_wait() {
    asm volatile("cp.async.wait_group %0;" :: "n"(N) : "memory");
}

__device__ __forceinline__ void split1(float x, __nv_bfloat16& h, __nv_bfloat16& l) {
    h = __float2bfloat16(x);
    l = __float2bfloat16(x - __bfloat162float(h));
}
__device__ __forceinline__ uint32_t packbf(__nv_bfloat16 a, __nv_bfloat16 b) {
    __nv_bfloat162 t(a, b);
    return *(uint32_t*)&t;
}

// ---------------------------------------------------------------------------
// fp32 -> bf16 hi/lo split (elementwise)
// ---------------------------------------------------------------------------
__global__ __launch_bounds__(256)
void convert_split(const float* __restrict__ in, __nv_bfloat16* __restrict__ hi,
                   __nv_bfloat16* __restrict__ lo, int n4)
{
    int i = blockIdx.x * blockDim.x + threadIdx.x;
    if (i >= n4) return;
    float4 v = ((const float4*)in)[i];
    __nv_bfloat16 h0, l0, h1, l1, h2, l2, h3, l3;
    split1(v.x, h0, l0); split1(v.y, h1, l1);
    split1(v.z, h2, l2); split1(v.w, h3, l3);
    ((__nv_bfloat162*)hi)[2 * i + 0] = __nv_bfloat162(h0, h1);
    ((__nv_bfloat162*)hi)[2 * i + 1] = __nv_bfloat162(h2, h3);
    ((__nv_bfloat162*)lo)[2 * i + 0] = __nv_bfloat162(l0, l1);
    ((__nv_bfloat162*)lo)[2 * i + 1] = __nv_bfloat162(l2, l3);
}

// ---------------------------------------------------------------------------
// All four W [K,N] fp32 -> transposed hi/lo bf16 [N,K] in one launch (z=4)
// ---------------------------------------------------------------------------
__global__ __launch_bounds__(256)
void transpose_split4(const float* __restrict__ W0, const float* __restrict__ W1,
                      const float* __restrict__ W2, const float* __restrict__ W3,
                      __nv_bfloat16* __restrict__ T0h, __nv_bfloat16* __restrict__ T0l,
                      __nv_bfloat16* __restrict__ T1h, __nv_bfloat16* __restrict__ T1l,
                      __nv_bfloat16* __restrict__ T2h, __nv_bfloat16* __restrict__ T2l,
                      __nv_bfloat16* __restrict__ T3h, __nv_bfloat16* __restrict__ T3l)
{
    __shared__ float t[32][33];
    const int z = blockIdx.z;
    const float* W = (z == 0) ? W0 : (z == 1) ? W1 : (z == 2) ? W2 : W3;
    __nv_bfloat16* Th = (z == 0) ? T0h : (z == 1) ? T1h : (z == 2) ? T2h : T3h;
    __nv_bfloat16* Tl = (z == 0) ? T0l : (z == 1) ? T1l : (z == 2) ? T2l : T3l;

    const int n0 = blockIdx.x * 32, k0 = blockIdx.y * 32;
    const int tx = threadIdx.x, ty = threadIdx.y;
#pragma unroll
    for (int i = 0; i < 32; i += 8)
        t[ty + i][tx] = W[(size_t)(k0 + ty + i) * HID + n0 + tx];
    __syncthreads();
#pragma unroll
    for (int i = 0; i < 32; i += 8) {
        float x = t[tx][ty + i];
        __nv_bfloat16 h, l; split1(x, h, l);
        Th[(size_t)(n0 + ty + i) * HID + k0 + tx] = h;
        Tl[(size_t)(n0 + ty + i) * HID + k0 + tx] = l;
    }
}

// ---------------------------------------------------------------------------
// GEMM mainloop shared constants
// ---------------------------------------------------------------------------
#define PIPE 3
#define STAGE_BYTES 32768
#define GEMM_SMEM   (PIPE * STAGE_BYTES)
#define NKC  (HID / 32)

// ---------------------------------------------------------------------------
// Merged QKV projection: grid (24, 32). blockIdx.x>>3 selects Q/K/V.
// Outputs bf16 hi/lo (V: hi only).
// ---------------------------------------------------------------------------
__global__ __launch_bounds__(256, 2)
void gemm_qkv(const __nv_bfloat16* __restrict__ Ahi, const __nv_bfloat16* __restrict__ Alo,
              const __nv_bfloat16* __restrict__ Bqh, const __nv_bfloat16* __restrict__ Bql,
              const __nv_bfloat16* __restrict__ Bkh, const __nv_bfloat16* __restrict__ Bkl,
              const __nv_bfloat16* __restrict__ Bvh, const __nv_bfloat16* __restrict__ Bvl,
              const float* __restrict__ bq, const float* __restrict__ bk,
              const float* __restrict__ bv,
              __nv_bfloat16* __restrict__ Qh, __nv_bfloat16* __restrict__ Ql,
              __nv_bfloat16* __restrict__ Kh, __nv_bfloat16* __restrict__ Kl,
              __nv_bfloat16* __restrict__ Vb)
{
    extern __shared__ char smc[];
    const uint32_t sbase = smem_u32(smc);

    const int sel = blockIdx.x >> 3;
    const __nv_bfloat16* Bhi = (sel == 0) ? Bqh : (sel == 1) ? Bkh : Bvh;
    const __nv_bfloat16* Blo = (sel == 0) ? Bql : (sel == 1) ? Bkl : Bvl;
    const float* bias = (sel == 0) ? bq : (sel == 1) ? bk : bv;
    __nv_bfloat16* Ch = (sel == 0) ? Qh : (sel == 1) ? Kh : Vb;
    __nv_bfloat16* Cl = (sel == 0) ? Ql : (sel == 1) ? Kl : nullptr;

    const int tid  = threadIdx.x;
    const int lane = tid & 31;
    const int warp = tid >> 5;
    const int wm   = (warp >> 2) * 64;
    const int wn   = (warp & 3) * 32;
    const int m0 = blockIdx.y * 128, n0 = (blockIdx.x & 7) * 128;

    auto load_stage = [&](int stage, int kc) {
        const uint32_t sb = sbase + stage * STAGE_BYTES;
#pragma unroll
        for (int t = 0; t < 8; t++) {
            int idx  = tid + t * 256;
            int tile = idx >> 10;
            int r    = (idx >> 3) & 127;
            int c    = idx & 7;
            const __nv_bfloat16* src;
            if (tile == 0)
                src = (c < 4 ? Ahi : Alo) + (size_t)(m0 + r) * HID + kc * 32 + (c & 3) * 8;
            else
                src = (c < 4 ? Bhi : Blo) + (size_t)(n0 + r) * HID + kc * 32 + (c & 3) * 8;
            uint32_t dst = sb + (uint32_t)(tile * 16384 + r * 128 + ((c ^ (r & 7)) * 16));
            cp16(dst, src);
        }
        cp_commit();
    };

    float acc[4][4][4];
#pragma unroll
    for (int mi = 0; mi < 4; mi++)
#pragma unroll
        for (int nj = 0; nj < 4; nj++)
#pragma unroll
            for (int e = 0; e < 4; e++) acc[mi][nj][e] = 0.f;

    load_stage(0, 0);
    load_stage(1, 1);

    for (int kc = 0; kc < NKC; kc++) {
        cp_wait<PIPE - 2>();
        __syncthreads();
        if (kc + 2 < NKC) load_stage((kc + 2) % PIPE, kc + 2);

        const uint32_t sA = sbase + (kc % PIPE) * STAGE_BYTES;
        const uint32_t sB = sA + 16384;

#pragma unroll
        for (int ks = 0; ks < 2; ks++) {
            uint32_t bh[4][2], bl[4][2];
#pragma unroll
            for (int nj = 0; nj < 4; nj++) {
                int r  = wn + nj * 8 + (lane & 7);
                int cc = ks * 2 + ((lane >> 3) & 1);
                ldmx2(bh[nj][0], bh[nj][1],
                      sB + (uint32_t)(r * 128 + ((cc ^ (r & 7)) * 16)));
                ldmx2(bl[nj][0], bl[nj][1],
                      sB + (uint32_t)(r * 128 + (((cc + 4) ^ (r & 7)) * 16)));
            }
#pragma unroll
            for (int mi = 0; mi < 4; mi++) {
                int r  = wm + mi * 16 + (lane & 15);
                int cc = ks * 2 + (lane >> 4);
                uint32_t ah0, ah1, ah2, ah3, al0, al1, al2, al3;
                ldmx4(ah0, ah1, ah2, ah3,
                      sA + (uint32_t)(r * 128 + ((cc ^ (r & 7)) * 16)));
                ldmx4(al0, al1, al2, al3,
                      sA + (uint32_t)(r * 128 + (((cc + 4) ^ (r & 7)) * 16)));
#pragma unroll
                for (int nj = 0; nj < 4; nj++) {
                    mma_bf16(acc[mi][nj][0], acc[mi][nj][1], acc[mi][nj][2], acc[mi][nj][3],
                             ah0, ah1, ah2, ah3, bh[nj][0], bh[nj][1]);
                    mma_bf16(acc[mi][nj][0], acc[mi][nj][1], acc[mi][nj][2], acc[mi][nj][3],
                             ah0, ah1, ah2, ah3, bl[nj][0], bl[nj][1]);
                    mma_bf16(acc[mi][nj][0], acc[mi][nj][1], acc[mi][nj][2], acc[mi][nj][3],
                             al0, al1, al2, al3, bh[nj][0], bh[nj][1]);
                }
            }
        }
    }

#pragma unroll
    for (int mi = 0; mi < 4; mi++) {
#pragma unroll
        for (int nj = 0; nj < 4; nj++) {
            int row = m0 + wm + mi * 16 + (lane >> 2);
            int col = n0 + wn + nj * 8 + 2 * (lane & 3);
            float b0 = bias[col], b1 = bias[col + 1];
            float v00 = acc[mi][nj][0] + b0, v01 = acc[mi][nj][1] + b1;
            float v10 = acc[mi][nj][2] + b0, v11 = acc[mi][nj][3] + b1;
            __nv_bfloat16 h00, l00, h01, l01, h10, l10, h11, l11;
            split1(v00, h00, l00); split1(v01, h01, l01);
            split1(v10, h10, l10); split1(v11, h11, l11);
            *(__nv_bfloat162*)&Ch[(size_t)row * HID + col] = __nv_bfloat162(h00, h01);
            *(__nv_bfloat162*)&Ch[(size_t)(row + 8) * HID + col] = __nv_bfloat162(h10, h11);
            if (Cl) {
                *(__nv_bfloat162*)&Cl[(size_t)row * HID + col] = __nv_bfloat162(l00, l01);
                *(__nv_bfloat162*)&Cl[(size_t)(row + 8) * HID + col] = __nv_bfloat162(l10, l11);
            }
        }
    }
}

// ---------------------------------------------------------------------------
// Output projection GEMM (fp32 out + residual)
// ---------------------------------------------------------------------------
__global__ __launch_bounds__(256, 2)
void gemm_out(const __nv_bfloat16* __restrict__ Ahi, const __nv_bfloat16* __restrict__ Alo,
              const __nv_bfloat16* __restrict__ Bhi, const __nv_bfloat16* __restrict__ Blo,
              const float* __restrict__ bias, const float* __restrict__ res,
              float* __restrict__ Cf)
{
    extern __shared__ char smc[];
    const uint32_t sbase = smem_u32(smc);

    const int tid  = threadIdx.x;
    const int lane = tid & 31;
    const int warp = tid >> 5;
    const int wm   = (warp >> 2) * 64;
    const int wn   = (warp & 3) * 32;
    const int m0 = blockIdx.y * 128, n0 = blockIdx.x * 128;

    auto load_stage = [&](int stage, int kc) {
        const uint32_t sb = sbase + stage * STAGE_BYTES;
#pragma unroll
        for (int t = 0; t < 8; t++) {
            int idx  = tid + t * 256;
            int tile = idx >> 10;
            int r    = (idx >> 3) & 127;
            int c    = idx & 7;
            const __nv_bfloat16* src;
            if (tile == 0)
                src = (c < 4 ? Ahi : Alo) + (size_t)(m0 + r) * HID + kc * 32 + (c & 3) * 8;
            else
                src = (c < 4 ? Bhi : Blo) + (size_t)(n0 + r) * HID + kc * 32 + (c & 3) * 8;
            uint32_t dst = sb + (uint32_t)(tile * 16384 + r * 128 + ((c ^ (r & 7)) * 16));
            cp16(dst, src);
        }
        cp_commit();
    };

    float acc[4][4][4];
#pragma unroll
    for (int mi = 0; mi < 4; mi++)
#pragma unroll
        for (int nj = 0; nj < 4; nj++)
#pragma unroll
            for (int e = 0; e < 4; e++) acc[mi][nj][e] = 0.f;

    load_stage(0, 0);
    load_stage(1, 1);

    for (int kc = 0; kc < NKC; kc++) {
        cp_wait<PIPE - 2>();
        __syncthreads();
        if (kc + 2 < NKC) load_stage((kc + 2) % PIPE, kc + 2);

        const uint32_t sA = sbase + (kc % PIPE) * STAGE_BYTES;
        const uint32_t sB = sA + 16384;

#pragma unroll
        for (int ks = 0; ks < 2; ks++) {
            uint32_t bh[4][2], bl[4][2];
#pragma unroll
            for (int nj = 0; nj < 4; nj++) {
                int r  = wn + nj * 8 + (lane & 7);
                int cc = ks * 2 + ((lane >> 3) & 1);
                ldmx2(bh[nj][0], bh[nj][1],
                      sB + (uint32_t)(r * 128 + ((cc ^ (r & 7)) * 16)));
                ldmx2(bl[nj][0], bl[nj][1],
                      sB + (uint32_t)(r * 128 + (((cc + 4) ^ (r & 7)) * 16)));
            }
#pragma unroll
            for (int mi = 0; mi < 4; mi++) {
                int r  = wm + mi * 16 + (lane & 15);
                int cc = ks * 2 + (lane >> 4);
                uint32_t ah0, ah1, ah2, ah3, al0, al1, al2, al3;
                ldmx4(ah0, ah1, ah2, ah3,
                      sA + (uint32_t)(r * 128 + ((cc ^ (r & 7)) * 16)));
                ldmx4(al0, al1, al2, al3,
                      sA + (uint32_t)(r * 128 + (((cc + 4) ^ (r & 7)) * 16)));
#pragma unroll
                for (int nj = 0; nj < 4; nj++) {
                    mma_bf16(acc[mi][nj][0], acc[mi][nj][1], acc[mi][nj][2], acc[mi][nj][3],
                             ah0, ah1, ah2, ah3, bh[nj][0], bh[nj][1]);
                    mma_bf16(acc[mi][nj][0], acc[mi][nj][1], acc[mi][nj][2], acc[mi][nj][3],
                             ah0, ah1, ah2, ah3, bl[nj][0], bl[nj][1]);
                    mma_bf16(acc[mi][nj][0], acc[mi][nj][1], acc[mi][nj][2], acc[mi][nj][3],
                             al0, al1, al2, al3, bh[nj][0], bh[nj][1]);
                }
            }
        }
    }

#pragma unroll
    for (int mi = 0; mi < 4; mi++) {
#pragma unroll
        for (int nj = 0; nj < 4; nj++) {
            int row = m0 + wm + mi * 16 + (lane >> 2);
            int col = n0 + wn + nj * 8 + 2 * (lane & 3);
            float b0 = bias[col], b1 = bias[col + 1];
            float v00 = acc[mi][nj][0] + b0, v01 = acc[mi][nj][1] + b1;
            float v10 = acc[mi][nj][2] + b0, v11 = acc[mi][nj][3] + b1;
            float2 r0 = *(const float2*)&res[(size_t)row * HID + col];
            float2 r1 = *(const float2*)&res[(size_t)(row + 8) * HID + col];
            v00 += r0.x; v01 += r0.y; v10 += r1.x; v11 += r1.y;
            *(float2*)&Cf[(size_t)row * HID + col] = make_float2(v00, v01);
            *(float2*)&Cf[(size_t)(row + 8) * HID + col] = make_float2(v10, v11);
        }
    }
}

// ---------------------------------------------------------------------------
// Flash attention via mma.sync:
//   S = Qh*Kh + Qh*Kl + Ql*Kh (3-term); softmax in fragments;
//   O += P_hi * V (single-term P and V).
// ---------------------------------------------------------------------------
#define ASTAGE 49152                           // Khi 16K + Klo 16K + V 16K
#define ATT_SMEM (32768 + 2 * ASTAGE)          // + Qhi/Qlo 32K = 128K

__global__ __launch_bounds__(256)
void flash_mma(const __nv_bfloat16* __restrict__ Qh, const __nv_bfloat16* __restrict__ Ql,
               const __nv_bfloat16* __restrict__ Kh, const __nv_bfloat16* __restrict__ Kl,
               const __nv_bfloat16* __restrict__ Vb,
               __nv_bfloat16* __restrict__ Ch, __nv_bfloat16* __restrict__ Cl)
{
    extern __shared__ char sma[];
    const uint32_t sQ = smem_u32(sma);
    const uint32_t sS = sQ + 32768;

    const int tid = threadIdx.x, lane = tid & 31, warp = tid >> 5;
    const int q0 = blockIdx.x * 128;
    const int h = blockIdx.y, b = blockIdx.z;
    const size_t gb = (size_t)b * SEQ * HID + (size_t)h * HDIM;

#pragma unroll
    for (int t = 0; t < 8; t++) {
        int idx = tid + t * 256;
        int tile = idx >> 10, r = (idx >> 3) & 127, c = idx & 7;
        const __nv_bfloat16* src = (tile ? Ql : Qh) + gb + (size_t)(q0 + r) * HID + c * 8;
        cp16(sQ + (uint32_t)(tile * 16384 + r * 128 + ((c ^ (r & 7)) * 16)), src);
    }
    cp_commit();

    auto loadKV = [&](int stage, int kt) {
        const uint32_t sb = sS + stage * ASTAGE;
#pragma unroll
        for (int t = 0; t < 12; t++) {
            int idx = tid + t * 256;
            int tile = idx >> 10, r = (idx >> 3) & 127, c = idx & 7;
            const __nv_bfloat16* src =
                (tile == 0 ? Kh : tile == 1 ? Kl : Vb) + gb + (size_t)(kt * 128 + r) * HID + c * 8;
            cp16(sb + (uint32_t)(tile * 16384 + r * 128 + ((c ^ (r & 7)) * 16)), src);
        }
        cp_commit();
    };
    loadKV(0, 0);
    loadKV(1, 1);

    cp_wait<2>();
    __syncthreads();

    const int wq = warp * 16;
    uint32_t qh[4][4], ql[4][4];
#pragma unroll
    for (int dc = 0; dc < 4; dc++) {
        int r = wq + (lane & 15);
        int cc = dc * 2 + (lane >> 4);
        uint32_t a = sQ + (uint32_t)(r * 128 + ((cc ^ (r & 7)) * 16));
        ldmx4(qh[dc][0], qh[dc][1], qh[dc][2], qh[dc][3], a);
        ldmx4(ql[dc][0], ql[dc][1], ql[dc][2], ql[dc][3], a + 16384);
    }

    float m0 = -1e30f, m1 = -1e30f, l0 = 0.f, l1 = 0.f;
    float o[8][4];
#pragma unroll
    for (int dj = 0; dj < 8; dj++)
#pragma unroll
        for (int e = 0; e < 4; e++) o[dj][e] = 0.f;

    for (int kt = 0; kt < SEQ / 128; kt++) {
        cp_wait<1>();
        __syncthreads();
        const uint32_t sK  = sS + (kt & 1) * ASTAGE;
        const uint32_t sKl = sK + 16384;
        const uint32_t sV  = sK + 32768;

        // ---- S = Q K^T (3-term split) ----
        float s[16][4];
#pragma unroll
        for (int nj = 0; nj < 16; nj++)
#pragma unroll
            for (int e = 0; e < 4; e++) s[nj][e] = 0.f;

#pragma unroll
        for (int nj = 0; nj < 16; nj++) {
            int r = nj * 8 + (lane & 7);
#pragma unroll
            for (int dc = 0; dc < 4; dc++) {
                int cc = dc * 2 + ((lane >> 3) & 1);
                uint32_t offh = (uint32_t)(r * 128 + ((cc ^ (r & 7)) * 16));
                uint32_t bh0, bh1, bl0, bl1;
                ldmx2(bh0, bh1, sK + offh);
                ldmx2(bl0, bl1, sKl + offh);
                mma_bf16(s[nj][0], s[nj][1], s[nj][2], s[nj][3],
                         qh[dc][0], qh[dc][1], qh[dc][2], qh[dc][3], bh0, bh1);
                mma_bf16(s[nj][0], s[nj][1], s[nj][2], s[nj][3],
                         qh[dc][0], qh[dc][1], qh[dc][2], qh[dc][3], bl0, bl1);
                mma_bf16(s[nj][0], s[nj][1], s[nj][2], s[nj][3],
                         ql[dc][0], ql[dc][1], ql[dc][2], ql[dc][3], bh0, bh1);
            }
        }

        // ---- online softmax on fragments ----
        const float sc = 0.125f;
        float mx0 = -1e30f, mx1 = -1e30f;
#pragma unroll
        for (int nj = 0; nj < 16; nj++) {
            s[nj][0] *= sc; s[nj][1] *= sc; s[nj][2] *= sc; s[nj][3] *= sc;
            mx0 = fmaxf(mx0, fmaxf(s[nj][0], s[nj][1]));
            mx1 = fmaxf(mx1, fmaxf(s[nj][2], s[nj][3]));
        }
        mx0 = fmaxf(mx0, __shfl_xor_sync(0xffffffffu, mx0, 1));
        mx0 = fmaxf(mx0, __shfl_xor_sync(0xffffffffu, mx0, 2));
        mx1 = fmaxf(mx1, __shfl_xor_sync(0xffffffffu, mx1, 1));
        mx1 = fmaxf(mx1, __shfl_xor_sync(0xffffffffu, mx1, 2));
        float mn0 = fmaxf(m0, mx0), mn1 = fmaxf(m1, mx1);
        float a0 = __expf(m0 - mn0), a1 = __expf(m1 - mn1);
        float sum0 = 0.f, sum1 = 0.f;
#pragma unroll
        for (int nj = 0; nj < 16; nj++) {
            s[nj][0] = __expf(s[nj][0] - mn0);
            s[nj][1] = __expf(s[nj][1] - mn0);
            s[nj][2] = __expf(s[nj][2] - mn1);
            s[nj][3] = __expf(s[nj][3] - mn1);
            sum0 += s[nj][0] + s[nj][1];
            sum1 += s[nj][2] + s[nj][3];
        }
        sum0 += __shfl_xor_sync(0xffffffffu, sum0, 1);
        sum0 += __shfl_xor_sync(0xffffffffu, sum0, 2);
        sum1 += __shfl_xor_sync(0xffffffffu, sum1, 1);
        sum1 += __shfl_xor_sync(0xffffffffu, sum1, 2);
        l0 = l0 * a0 + sum0; l1 = l1 * a1 + sum1;
        m0 = mn0; m1 = mn1;
#pragma unroll
        for (int dj = 0; dj < 8; dj++) {
            o[dj][0] *= a0; o[dj][1] *= a0; o[dj][2] *= a1; o[dj][3] *= a1;
        }

        // ---- O += P V (P single bf16, V via ldmatrix.trans) ----
#pragma unroll
        for (int kc = 0; kc < 8; kc++) {
            uint32_t A0 = packbf(__float2bfloat16(s[2 * kc][0]),
                                 __float2bfloat16(s[2 * kc][1]));
            uint32_t A1 = packbf(__float2bfloat16(s[2 * kc][2]),
                                 __float2bfloat16(s[2 * kc][3]));
            uint32_t A2 = packbf(__float2bfloat16(s[2 * kc + 1][0]),
                                 __float2bfloat16(s[2 * kc + 1][1]));
            uint32_t A3 = packbf(__float2bfloat16(s[2 * kc + 1][2]),
                                 __float2bfloat16(s[2 * kc + 1][3]));
            int r = kc * 16 + (lane & 15);
#pragma unroll
            for (int dj = 0; dj < 8; dj++) {
                uint32_t addr = sV + (uint32_t)(r * 128 + ((dj ^ (r & 7)) * 16));
                uint32_t b0, b1;
                ldmx2t(b0, b1, addr);
                mma_bf16(o[dj][0], o[dj][1], o[dj][2], o[dj][3], A0, A1, A2, A3, b0, b1);
            }
        }

        __syncthreads();
        if (kt + 2 < SEQ / 128) loadKV(kt & 1, kt + 2);
    }

    // ---- epilogue: normalize, split hi/lo, store ctx ----
    float i0 = 1.f / l0, i1 = 1.f / l1;
    int r0 = q0 + wq + (lane >> 2);
    int cb = 2 * (lane & 3);
#pragma unroll
    for (int dj = 0; dj < 8; dj++) {
        int col = dj * 8 + cb;
        float v00 = o[dj][0] * i0, v01 = o[dj][1] * i0;
        float v10 = o[dj][2] * i1, v11 = o[dj][3] * i1;
        __nv_bfloat16 h00, l00, h01, l01, h10, l10, h11, l11;
        split1(v00, h00, l00); split1(v01, h01, l01);
        split1(v10, h10, l10); split1(v11, h11, l11);
        *(__nv_bfloat162*)&Ch[gb + (size_t)r0 * HID + col] = __nv_bfloat162(h00, h01);
        *(__nv_bfloat162*)&Ch[gb + (size_t)(r0 + 8) * HID + col] = __nv_bfloat162(h10, h11);
        *(__nv_bfloat162*)&Cl[gb + (size_t)r0 * HID + col] = __nv_bfloat162(l00, l01);
        *(__nv_bfloat162*)&Cl[gb + (size_t)(r0 + 8) * HID + col] = __nv_bfloat162(l10, l11);
    }
}

// ---------------------------------------------------------------------------
// LayerNorm: one block per row of 1024
// ---------------------------------------------------------------------------
__global__ __launch_bounds__(256)
void layernorm_kernel(const float* __restrict__ X, const float* __restrict__ gamma,
                      const float* __restrict__ beta, float* __restrict__ out)
{
    __shared__ float red[2][8];
    const int row = blockIdx.x;
    const int tid = threadIdx.x;
    const float* x = X + (size_t)row * HID;

    float4 v = *(const float4*)&x[tid * 4];
    float s  = v.x + v.y + v.z + v.w;
    float ss = v.x * v.x + v.y * v.y + v.z * v.z + v.w * v.w;
#pragma unroll
    for (int o = 16; o > 0; o >>= 1) {
        s  += __shfl_xor_sync(0xffffffffu, s, o);
        ss += __shfl_xor_sync(0xffffffffu, ss, o);
    }
    const int w = tid >> 5, l = tid & 31;
    if (l == 0) { red[0][w] = s; red[1][w] = ss; }
    __syncthreads();
    if (w == 0) {
        float s2  = (l < 8) ? red[0][l] : 0.f;
        float ss2 = (l < 8) ? red[1][l] : 0.f;
#pragma unroll
        for (int o = 4; o > 0; o >>= 1) {
            s2  += __shfl_xor_sync(0xffffffffu, s2, o);
            ss2 += __shfl_xor_sync(0xffffffffu, ss2, o);
        }
        if (l == 0) { red[0][0] = s2; red[1][0] = ss2; }
    }
    __syncthreads();

    const float mean = red[0][0] * (1.f / HID);
    const float var  = red[1][0] * (1.f / HID) - mean * mean;
    const float rstd = rsqrtf(var + 1e-5f);

    const int c = tid * 4;
    float4 gv = *(const float4*)&gamma[c];
    float4 bv = *(const float4*)&beta[c];
    float4 o;
    o.x = (v.x - mean) * rstd * gv.x + bv.x;
    o.y = (v.y - mean) * rstd * gv.y + bv.y;
    o.z = (v.z - mean) * rstd * gv.z + bv.z;
    o.w = (v.w - mean) * rstd * gv.w + bv.w;
    *(float4*)&out[(size_t)row * HID + c] = o;
}

// ---------------------------------------------------------------------------
// Launch
// ---------------------------------------------------------------------------
extern "C" void kernel_launch(void* const* d_in, const int* in_sizes, int n_in,
                              void* d_out, int out_size)
{
    const float* hidden = (const float*)d_in[0];
    const float* Wq = (const float*)d_in[1];
    const float* bq = (const float*)d_in[2];
    const float* Wk = (const float*)d_in[3];
    const float* bk = (const float*)d_in[4];
    const float* Wv = (const float*)d_in[5];
    const float* bv = (const float*)d_in[6];
    const float* Wo = (const float*)d_in[7];
    const float* bo = (const float*)d_in[8];
    const float* gamma = (const float*)d_in[9];
    const float* beta  = (const float*)d_in[10];
    float* out = (float*)d_out;

    float* x;
    cudaGetSymbolAddress((void**)&x, g_X);

    __nv_bfloat16 *hhi, *hlo, *chi, *clo, *qhp, *qlp, *khp, *klp, *vbp;
    __nv_bfloat16 *wqh, *wql, *wkh, *wkl, *wvh, *wvl, *woh, *wol;
    cudaGetSymbolAddress((void**)&hhi, g_Hhi);
    cudaGetSymbolAddress((void**)&hlo, g_Hlo);
    cudaGetSymbolAddress((void**)&chi, g_Chi);
    cudaGetSymbolAddress((void**)&clo, g_Clo);
    cudaGetSymbolAddress((void**)&qhp, g_Qh);
    cudaGetSymbolAddress((void**)&qlp, g_Ql);
    cudaGetSymbolAddress((void**)&khp, g_Kh);
    cudaGetSymbolAddress((void**)&klp, g_Kl);
    cudaGetSymbolAddress((void**)&vbp, g_Vb);
    cudaGetSymbolAddress((void**)&wqh, g_WqTh);
    cudaGetSymbolAddress((void**)&wql, g_WqTl);
    cudaGetSymbolAddress((void**)&wkh, g_WkTh);
    cudaGetSymbolAddress((void**)&wkl, g_WkTl);
    cudaGetSymbolAddress((void**)&wvh, g_WvTh);
    cudaGetSymbolAddress((void**)&wvl, g_WvTl);
    cudaGetSymbolAddress((void**)&woh, g_WoTh);
    cudaGetSymbolAddress((void**)&wol, g_WoTl);

    // ---- prep ----
    convert_split<<<(ROWS * HID / 4 + 255) / 256, 256>>>(hidden, hhi, hlo, ROWS * HID / 4);
    dim3 tg(HID / 32, HID / 32, 4), tb(32, 8);
    transpose_split4<<<tg, tb>>>(Wq, Wk, Wv, Wo,
                                 wqh, wql, wkh, wkl, wvh, wvl, woh, wol);

    // ---- merged QKV projection ----
    cudaFuncSetAttribute(gemm_qkv, cudaFuncAttributeMaxDynamicSharedMemorySize, GEMM_SMEM);
    cudaFuncSetAttribute(gemm_out, cudaFuncAttributeMaxDynamicSharedMemorySize, GEMM_SMEM);
    gemm_qkv<<<dim3(24, ROWS / 128), 256, GEMM_SMEM>>>(
        hhi, hlo, wqh, wql, wkh, wkl, wvh, wvl, bq, bk, bv,
        qhp, qlp, khp, klp, vbp);

    // ---- attention (tensor core) ----
    cudaFuncSetAttribute(flash_mma, cudaFuncAttributeMaxDynamicSharedMemorySize, ATT_SMEM);
    flash_mma<<<dim3(SEQ / 128, HEADS, BATCH), 256, ATT_SMEM>>>(qhp, qlp, khp, klp, vbp,
                                                                chi, clo);

    // ---- output projection + residual ----
    gemm_out<<<dim3(HID / 128, ROWS / 128), 256, GEMM_SMEM>>>(chi, clo, woh, wol, bo,
                                                              hidden, x);

    // ---- layernorm ----
    layernorm_kernel<<<ROWS, 256>>>(x, gamma, beta, out);
}

// round 8
// speedup vs baseline: 4.4977x; 1.1107x over previous
#include <cuda_runtime.h>
#include <cuda_bf16.h>
#include <math.h>
#include <stdint.h>

// ---------------------------------------------------------------------------
// Problem constants
// ---------------------------------------------------------------------------
#define BATCH   2
#define SEQ     2048
#define HID     1024
#define HEADS   16
#define HDIM    64
#define ROWS    (BATCH * SEQ)          // 4096

// ---------------------------------------------------------------------------
// Scratch (static device globals -- no runtime allocation)
// ---------------------------------------------------------------------------
__device__ float g_X[ROWS * HID];

__device__ __nv_bfloat16 g_Hhi[ROWS * HID];
__device__ __nv_bfloat16 g_Hlo[ROWS * HID];
__device__ __nv_bfloat16 g_Qh[ROWS * HID];
__device__ __nv_bfloat16 g_Kh[ROWS * HID];
__device__ __nv_bfloat16 g_Kl[ROWS * HID];
__device__ __nv_bfloat16 g_Vb[ROWS * HID];
__device__ __nv_bfloat16 g_Chi[ROWS * HID];
__device__ __nv_bfloat16 g_Clo[ROWS * HID];
__device__ __nv_bfloat16 g_WqTh[HID * HID];
__device__ __nv_bfloat16 g_WqTl[HID * HID];
__device__ __nv_bfloat16 g_WkTh[HID * HID];
__device__ __nv_bfloat16 g_WkTl[HID * HID];
__device__ __nv_bfloat16 g_WvTh[HID * HID];
__device__ __nv_bfloat16 g_WvTl[HID * HID];
__device__ __nv_bfloat16 g_WoTh[HID * HID];
__device__ __nv_bfloat16 g_WoTl[HID * HID];

// ---------------------------------------------------------------------------
// PTX helpers
// ---------------------------------------------------------------------------
__device__ __forceinline__ uint32_t smem_u32(const void* p) {
    uint32_t a;
    asm("{ .reg .u64 t; cvta.to.shared.u64 t, %1; cvt.u32.u64 %0, t; }"
        : "=r"(a) : "l"(p));
    return a;
}
__device__ __forceinline__ void ldmx4(uint32_t& r0, uint32_t& r1, uint32_t& r2,
                                      uint32_t& r3, uint32_t addr) {
    asm volatile("ldmatrix.sync.aligned.m8n8.x4.shared.b16 {%0,%1,%2,%3}, [%4];"
                 : "=r"(r0), "=r"(r1), "=r"(r2), "=r"(r3) : "r"(addr));
}
__device__ __forceinline__ void ldmx2(uint32_t& r0, uint32_t& r1, uint32_t addr) {
    asm volatile("ldmatrix.sync.aligned.m8n8.x2.shared.b16 {%0,%1}, [%2];"
                 : "=r"(r0), "=r"(r1) : "r"(addr));
}
__device__ __forceinline__ void ldmx2t(uint32_t& r0, uint32_t& r1, uint32_t addr) {
    asm volatile("ldmatrix.sync.aligned.m8n8.x2.trans.shared.b16 {%0,%1}, [%2];"
                 : "=r"(r0), "=r"(r1) : "r"(addr));
}
__device__ __forceinline__ void mma_bf16(float& d0, float& d1, float& d2, float& d3,
                                         uint32_t a0, uint32_t a1, uint32_t a2,
                                         uint32_t a3, uint32_t b0, uint32_t b1) {
    asm volatile(
        "mma.sync.aligned.m16n8k16.row.col.f32.bf16.bf16.f32 "
        "{%0,%1,%2,%3}, {%4,%5,%6,%7}, {%8,%9}, {%0,%1,%2,%3};"
        : "+f"(d0), "+f"(d1), "+f"(d2), "+f"(d3)
        : "r"(a0), "r"(a1), "r"(a2), "r"(a3), "r"(b0), "r"(b1));
}
__device__ __forceinline__ void cp16(uint32_t dst, const void* src) {
    asm volatile("cp.async.cg.shared.global [%0], [%1], 16;"
                 :: "r"(dst), "l"(src));
}
__device__ __forceinline__ void cp_commit() {
    asm volatile("cp.async.commit_group;" ::: "memory");
}
template <int N>
__device__ __forceinline__ void cp_wait() {
    asm volatile("cp.async.wait_group %0;" :: "n"(N) : "memory");
}

__device__ __forceinline__ void split1(float x, __nv_bfloat16& h, __nv_bfloat16& l) {
    h = __float2bfloat16(x);
    l = __float2bfloat16(x - __bfloat162float(h));
}
__device__ __forceinline__ uint32_t packbf(__nv_bfloat16 a, __nv_bfloat16 b) {
    __nv_bfloat162 t(a, b);
    return *(uint32_t*)&t;
}

// ---------------------------------------------------------------------------
// fp32 -> bf16 hi/lo split (elementwise)
// ---------------------------------------------------------------------------
__global__ __launch_bounds__(256)
void convert_split(const float* __restrict__ in, __nv_bfloat16* __restrict__ hi,
                   __nv_bfloat16* __restrict__ lo, int n4)
{
    int i = blockIdx.x * blockDim.x + threadIdx.x;
    if (i >= n4) return;
    float4 v = ((const float4*)in)[i];
    __nv_bfloat16 h0, l0, h1, l1, h2, l2, h3, l3;
    split1(v.x, h0, l0); split1(v.y, h1, l1);
    split1(v.z, h2, l2); split1(v.w, h3, l3);
    ((__nv_bfloat162*)hi)[2 * i + 0] = __nv_bfloat162(h0, h1);
    ((__nv_bfloat162*)hi)[2 * i + 1] = __nv_bfloat162(h2, h3);
    ((__nv_bfloat162*)lo)[2 * i + 0] = __nv_bfloat162(l0, l1);
    ((__nv_bfloat162*)lo)[2 * i + 1] = __nv_bfloat162(l2, l3);
}

// ---------------------------------------------------------------------------
// All four W [K,N] fp32 -> transposed hi/lo bf16 [N,K] in one launch (z=4)
// ---------------------------------------------------------------------------
__global__ __launch_bounds__(256)
void transpose_split4(const float* __restrict__ W0, const float* __restrict__ W1,
                      const float* __restrict__ W2, const float* __restrict__ W3,
                      __nv_bfloat16* __restrict__ T0h, __nv_bfloat16* __restrict__ T0l,
                      __nv_bfloat16* __restrict__ T1h, __nv_bfloat16* __restrict__ T1l,
                      __nv_bfloat16* __restrict__ T2h, __nv_bfloat16* __restrict__ T2l,
                      __nv_bfloat16* __restrict__ T3h, __nv_bfloat16* __restrict__ T3l)
{
    __shared__ float t[32][33];
    const int z = blockIdx.z;
    const float* W = (z == 0) ? W0 : (z == 1) ? W1 : (z == 2) ? W2 : W3;
    __nv_bfloat16* Th = (z == 0) ? T0h : (z == 1) ? T1h : (z == 2) ? T2h : T3h;
    __nv_bfloat16* Tl = (z == 0) ? T0l : (z == 1) ? T1l : (z == 2) ? T2l : T3l;

    const int n0 = blockIdx.x * 32, k0 = blockIdx.y * 32;
    const int tx = threadIdx.x, ty = threadIdx.y;
#pragma unroll
    for (int i = 0; i < 32; i += 8)
        t[ty + i][tx] = W[(size_t)(k0 + ty + i) * HID + n0 + tx];
    __syncthreads();
#pragma unroll
    for (int i = 0; i < 32; i += 8) {
        float x = t[tx][ty + i];
        __nv_bfloat16 h, l; split1(x, h, l);
        Th[(size_t)(n0 + ty + i) * HID + k0 + tx] = h;
        Tl[(size_t)(n0 + ty + i) * HID + k0 + tx] = l;
    }
}

// ---------------------------------------------------------------------------
// GEMM mainloop shared constants
// ---------------------------------------------------------------------------
#define PIPE 3
#define STAGE_BYTES 32768
#define GEMM_SMEM   (PIPE * STAGE_BYTES)
#define NKC  (HID / 32)

// ---------------------------------------------------------------------------
// Merged QKV projection: grid (24, 32). blockIdx.x>>3 selects Q/K/V.
// Q -> hi only; K -> hi/lo; V -> hi only.
// ---------------------------------------------------------------------------
__global__ __launch_bounds__(256, 2)
void gemm_qkv(const __nv_bfloat16* __restrict__ Ahi, const __nv_bfloat16* __restrict__ Alo,
              const __nv_bfloat16* __restrict__ Bqh, const __nv_bfloat16* __restrict__ Bql,
              const __nv_bfloat16* __restrict__ Bkh, const __nv_bfloat16* __restrict__ Bkl,
              const __nv_bfloat16* __restrict__ Bvh, const __nv_bfloat16* __restrict__ Bvl,
              const float* __restrict__ bq, const float* __restrict__ bk,
              const float* __restrict__ bv,
              __nv_bfloat16* __restrict__ Qh,
              __nv_bfloat16* __restrict__ Kh, __nv_bfloat16* __restrict__ Kl,
              __nv_bfloat16* __restrict__ Vb)
{
    extern __shared__ char smc[];
    const uint32_t sbase = smem_u32(smc);

    const int sel = blockIdx.x >> 3;
    const __nv_bfloat16* Bhi = (sel == 0) ? Bqh : (sel == 1) ? Bkh : Bvh;
    const __nv_bfloat16* Blo = (sel == 0) ? Bql : (sel == 1) ? Bkl : Bvl;
    const float* bias = (sel == 0) ? bq : (sel == 1) ? bk : bv;
    __nv_bfloat16* Ch = (sel == 0) ? Qh : (sel == 1) ? Kh : Vb;
    __nv_bfloat16* Cl = (sel == 1) ? Kl : nullptr;

    const int tid  = threadIdx.x;
    const int lane = tid & 31;
    const int warp = tid >> 5;
    const int wm   = (warp >> 2) * 64;
    const int wn   = (warp & 3) * 32;
    const int m0 = blockIdx.y * 128, n0 = (blockIdx.x & 7) * 128;

    auto load_stage = [&](int stage, int kc) {
        const uint32_t sb = sbase + stage * STAGE_BYTES;
#pragma unroll
        for (int t = 0; t < 8; t++) {
            int idx  = tid + t * 256;
            int tile = idx >> 10;
            int r    = (idx >> 3) & 127;
            int c    = idx & 7;
            const __nv_bfloat16* src;
            if (tile == 0)
                src = (c < 4 ? Ahi : Alo) + (size_t)(m0 + r) * HID + kc * 32 + (c & 3) * 8;
            else
                src = (c < 4 ? Bhi : Blo) + (size_t)(n0 + r) * HID + kc * 32 + (c & 3) * 8;
            uint32_t dst = sb + (uint32_t)(tile * 16384 + r * 128 + ((c ^ (r & 7)) * 16));
            cp16(dst, src);
        }
        cp_commit();
    };

    float acc[4][4][4];
#pragma unroll
    for (int mi = 0; mi < 4; mi++)
#pragma unroll
        for (int nj = 0; nj < 4; nj++)
#pragma unroll
            for (int e = 0; e < 4; e++) acc[mi][nj][e] = 0.f;

    load_stage(0, 0);
    load_stage(1, 1);

    for (int kc = 0; kc < NKC; kc++) {
        cp_wait<PIPE - 2>();
        __syncthreads();
        if (kc + 2 < NKC) load_stage((kc + 2) % PIPE, kc + 2);

        const uint32_t sA = sbase + (kc % PIPE) * STAGE_BYTES;
        const uint32_t sB = sA + 16384;

#pragma unroll
        for (int ks = 0; ks < 2; ks++) {
            uint32_t bh[4][2], bl[4][2];
#pragma unroll
            for (int nj = 0; nj < 4; nj++) {
                int r  = wn + nj * 8 + (lane & 7);
                int cc = ks * 2 + ((lane >> 3) & 1);
                ldmx2(bh[nj][0], bh[nj][1],
                      sB + (uint32_t)(r * 128 + ((cc ^ (r & 7)) * 16)));
                ldmx2(bl[nj][0], bl[nj][1],
                      sB + (uint32_t)(r * 128 + (((cc + 4) ^ (r & 7)) * 16)));
            }
#pragma unroll
            for (int mi = 0; mi < 4; mi++) {
                int r  = wm + mi * 16 + (lane & 15);
                int cc = ks * 2 + (lane >> 4);
                uint32_t ah0, ah1, ah2, ah3, al0, al1, al2, al3;
                ldmx4(ah0, ah1, ah2, ah3,
                      sA + (uint32_t)(r * 128 + ((cc ^ (r & 7)) * 16)));
                ldmx4(al0, al1, al2, al3,
                      sA + (uint32_t)(r * 128 + (((cc + 4) ^ (r & 7)) * 16)));
#pragma unroll
                for (int nj = 0; nj < 4; nj++) {
                    mma_bf16(acc[mi][nj][0], acc[mi][nj][1], acc[mi][nj][2], acc[mi][nj][3],
                             ah0, ah1, ah2, ah3, bh[nj][0], bh[nj][1]);
                    mma_bf16(acc[mi][nj][0], acc[mi][nj][1], acc[mi][nj][2], acc[mi][nj][3],
                             ah0, ah1, ah2, ah3, bl[nj][0], bl[nj][1]);
                    mma_bf16(acc[mi][nj][0], acc[mi][nj][1], acc[mi][nj][2], acc[mi][nj][3],
                             al0, al1, al2, al3, bh[nj][0], bh[nj][1]);
                }
            }
        }
    }

#pragma unroll
    for (int mi = 0; mi < 4; mi++) {
#pragma unroll
        for (int nj = 0; nj < 4; nj++) {
            int row = m0 + wm + mi * 16 + (lane >> 2);
            int col = n0 + wn + nj * 8 + 2 * (lane & 3);
            float b0 = bias[col], b1 = bias[col + 1];
            float v00 = acc[mi][nj][0] + b0, v01 = acc[mi][nj][1] + b1;
            float v10 = acc[mi][nj][2] + b0, v11 = acc[mi][nj][3] + b1;
            __nv_bfloat16 h00, l00, h01, l01, h10, l10, h11, l11;
            split1(v00, h00, l00); split1(v01, h01, l01);
            split1(v10, h10, l10); split1(v11, h11, l11);
            *(__nv_bfloat162*)&Ch[(size_t)row * HID + col] = __nv_bfloat162(h00, h01);
            *(__nv_bfloat162*)&Ch[(size_t)(row + 8) * HID + col] = __nv_bfloat162(h10, h11);
            if (Cl) {
                *(__nv_bfloat162*)&Cl[(size_t)row * HID + col] = __nv_bfloat162(l00, l01);
                *(__nv_bfloat162*)&Cl[(size_t)(row + 8) * HID + col] = __nv_bfloat162(l10, l11);
            }
        }
    }
}

// ---------------------------------------------------------------------------
// Output projection GEMM (fp32 out + residual)
// ---------------------------------------------------------------------------
__global__ __launch_bounds__(256, 2)
void gemm_out(const __nv_bfloat16* __restrict__ Ahi, const __nv_bfloat16* __restrict__ Alo,
              const __nv_bfloat16* __restrict__ Bhi, const __nv_bfloat16* __restrict__ Blo,
              const float* __restrict__ bias, const float* __restrict__ res,
              float* __restrict__ Cf)
{
    extern __shared__ char smc[];
    const uint32_t sbase = smem_u32(smc);

    const int tid  = threadIdx.x;
    const int lane = tid & 31;
    const int warp = tid >> 5;
    const int wm   = (warp >> 2) * 64;
    const int wn   = (warp & 3) * 32;
    const int m0 = blockIdx.y * 128, n0 = blockIdx.x * 128;

    auto load_stage = [&](int stage, int kc) {
        const uint32_t sb = sbase + stage * STAGE_BYTES;
#pragma unroll
        for (int t = 0; t < 8; t++) {
            int idx  = tid + t * 256;
            int tile = idx >> 10;
            int r    = (idx >> 3) & 127;
            int c    = idx & 7;
            const __nv_bfloat16* src;
            if (tile == 0)
                src = (c < 4 ? Ahi : Alo) + (size_t)(m0 + r) * HID + kc * 32 + (c & 3) * 8;
            else
                src = (c < 4 ? Bhi : Blo) + (size_t)(n0 + r) * HID + kc * 32 + (c & 3) * 8;
            uint32_t dst = sb + (uint32_t)(tile * 16384 + r * 128 + ((c ^ (r & 7)) * 16));
            cp16(dst, src);
        }
        cp_commit();
    };

    float acc[4][4][4];
#pragma unroll
    for (int mi = 0; mi < 4; mi++)
#pragma unroll
        for (int nj = 0; nj < 4; nj++)
#pragma unroll
            for (int e = 0; e < 4; e++) acc[mi][nj][e] = 0.f;

    load_stage(0, 0);
    load_stage(1, 1);

    for (int kc = 0; kc < NKC; kc++) {
        cp_wait<PIPE - 2>();
        __syncthreads();
        if (kc + 2 < NKC) load_stage((kc + 2) % PIPE, kc + 2);

        const uint32_t sA = sbase + (kc % PIPE) * STAGE_BYTES;
        const uint32_t sB = sA + 16384;

#pragma unroll
        for (int ks = 0; ks < 2; ks++) {
            uint32_t bh[4][2], bl[4][2];
#pragma unroll
            for (int nj = 0; nj < 4; nj++) {
                int r  = wn + nj * 8 + (lane & 7);
                int cc = ks * 2 + ((lane >> 3) & 1);
                ldmx2(bh[nj][0], bh[nj][1],
                      sB + (uint32_t)(r * 128 + ((cc ^ (r & 7)) * 16)));
                ldmx2(bl[nj][0], bl[nj][1],
                      sB + (uint32_t)(r * 128 + (((cc + 4) ^ (r & 7)) * 16)));
            }
#pragma unroll
            for (int mi = 0; mi < 4; mi++) {
                int r  = wm + mi * 16 + (lane & 15);
                int cc = ks * 2 + (lane >> 4);
                uint32_t ah0, ah1, ah2, ah3, al0, al1, al2, al3;
                ldmx4(ah0, ah1, ah2, ah3,
                      sA + (uint32_t)(r * 128 + ((cc ^ (r & 7)) * 16)));
                ldmx4(al0, al1, al2, al3,
                      sA + (uint32_t)(r * 128 + (((cc + 4) ^ (r & 7)) * 16)));
#pragma unroll
                for (int nj = 0; nj < 4; nj++) {
                    mma_bf16(acc[mi][nj][0], acc[mi][nj][1], acc[mi][nj][2], acc[mi][nj][3],
                             ah0, ah1, ah2, ah3, bh[nj][0], bh[nj][1]);
                    mma_bf16(acc[mi][nj][0], acc[mi][nj][1], acc[mi][nj][2], acc[mi][nj][3],
                             ah0, ah1, ah2, ah3, bl[nj][0], bl[nj][1]);
                    mma_bf16(acc[mi][nj][0], acc[mi][nj][1], acc[mi][nj][2], acc[mi][nj][3],
                             al0, al1, al2, al3, bh[nj][0], bh[nj][1]);
                }
            }
        }
    }

#pragma unroll
    for (int mi = 0; mi < 4; mi++) {
#pragma unroll
        for (int nj = 0; nj < 4; nj++) {
            int row = m0 + wm + mi * 16 + (lane >> 2);
            int col = n0 + wn + nj * 8 + 2 * (lane & 3);
            float b0 = bias[col], b1 = bias[col + 1];
            float v00 = acc[mi][nj][0] + b0, v01 = acc[mi][nj][1] + b1;
            float v10 = acc[mi][nj][2] + b0, v11 = acc[mi][nj][3] + b1;
            float2 r0 = *(const float2*)&res[(size_t)row * HID + col];
            float2 r1 = *(const float2*)&res[(size_t)(row + 8) * HID + col];
            v00 += r0.x; v01 += r0.y; v10 += r1.x; v11 += r1.y;
            *(float2*)&Cf[(size_t)row * HID + col] = make_float2(v00, v01);
            *(float2*)&Cf[(size_t)(row + 8) * HID + col] = make_float2(v10, v11);
        }
    }
}

// ---------------------------------------------------------------------------
// Flash attention via mma.sync:
//   S = Qh*Kh + Qh*Kl (2-term, Q single bf16); softmax in fragments;
//   O += P_hi * V.  K-tile 64 for low reg pressure -> 2 CTAs/SM.
// ---------------------------------------------------------------------------
#define ASTAGE 24576                           // Khi 8K + Klo 8K + V 8K
#define ATT_SMEM (16384 + 2 * ASTAGE)          // + Qhi 16K = 64K

__global__ __launch_bounds__(256, 2)
void flash_mma(const __nv_bfloat16* __restrict__ Qh,
               const __nv_bfloat16* __restrict__ Kh, const __nv_bfloat16* __restrict__ Kl,
               const __nv_bfloat16* __restrict__ Vb,
               __nv_bfloat16* __restrict__ Ch, __nv_bfloat16* __restrict__ Cl)
{
    extern __shared__ char sma[];
    const uint32_t sQ = smem_u32(sma);        // Qhi 16K
    const uint32_t sS = sQ + 16384;           // 2 stages of {Khi 8K, Klo 8K, V 8K}

    const int tid = threadIdx.x, lane = tid & 31, warp = tid >> 5;
    const int q0 = blockIdx.x * 128;
    const int h = blockIdx.y, b = blockIdx.z;
    const size_t gb = (size_t)b * SEQ * HID + (size_t)h * HDIM;

    // Q hi tile -> smem (swizzled, 128 rows x 128 B)
#pragma unroll
    for (int t = 0; t < 4; t++) {
        int idx = tid + t * 256;               // 0..1023
        int r = idx >> 3, c = idx & 7;
        const __nv_bfloat16* src = Qh + gb + (size_t)(q0 + r) * HID + c * 8;
        cp16(sQ + (uint32_t)(r * 128 + ((c ^ (r & 7)) * 16)), src);
    }
    cp_commit();

    auto loadKV = [&](int stage, int kt) {     // kt indexes 64-row K tiles
        const uint32_t sb = sS + stage * ASTAGE;
#pragma unroll
        for (int t = 0; t < 6; t++) {
            int idx = tid + t * 256;           // 0..1535
            int tile = idx >> 9;               // 0=Kh 1=Kl 2=V (512 slots each)
            int r = (idx >> 3) & 63, c = idx & 7;
            const __nv_bfloat16* src =
                (tile == 0 ? Kh : tile == 1 ? Kl : Vb) + gb + (size_t)(kt * 64 + r) * HID + c * 8;
            cp16(sb + (uint32_t)(tile * 8192 + r * 128 + ((c ^ (r & 7)) * 16)), src);
        }
        cp_commit();
    };
    loadKV(0, 0);
    loadKV(1, 1);

    cp_wait<2>();          // Q resident
    __syncthreads();

    // Q fragments (registers, whole kernel)
    const int wq = warp * 16;
    uint32_t qh[4][4];
#pragma unroll
    for (int dc = 0; dc < 4; dc++) {
        int r = wq + (lane & 15);
        int cc = dc * 2 + (lane >> 4);
        ldmx4(qh[dc][0], qh[dc][1], qh[dc][2], qh[dc][3],
              sQ + (uint32_t)(r * 128 + ((cc ^ (r & 7)) * 16)));
    }

    float m0 = -1e30f, m1 = -1e30f, l0 = 0.f, l1 = 0.f;
    float o[8][4];
#pragma unroll
    for (int dj = 0; dj < 8; dj++)
#pragma unroll
        for (int e = 0; e < 4; e++) o[dj][e] = 0.f;

    for (int kt = 0; kt < SEQ / 64; kt++) {
        cp_wait<1>();
        __syncthreads();
        const uint32_t sK  = sS + (kt & 1) * ASTAGE;
        const uint32_t sKl = sK + 8192;
        const uint32_t sV  = sK + 16384;

        // ---- S = Q K^T (2-term: Qh*Kh + Qh*Kl) ----
        float s[8][4];
#pragma unroll
        for (int nj = 0; nj < 8; nj++)
#pragma unroll
            for (int e = 0; e < 4; e++) s[nj][e] = 0.f;

#pragma unroll
        for (int nj = 0; nj < 8; nj++) {
            int r = nj * 8 + (lane & 7);
#pragma unroll
            for (int dc = 0; dc < 4; dc++) {
                int cc = dc * 2 + ((lane >> 3) & 1);
                uint32_t off = (uint32_t)(r * 128 + ((cc ^ (r & 7)) * 16));
                uint32_t bh0, bh1, bl0, bl1;
                ldmx2(bh0, bh1, sK + off);
                ldmx2(bl0, bl1, sKl + off);
                mma_bf16(s[nj][0], s[nj][1], s[nj][2], s[nj][3],
                         qh[dc][0], qh[dc][1], qh[dc][2], qh[dc][3], bh0, bh1);
                mma_bf16(s[nj][0], s[nj][1], s[nj][2], s[nj][3],
                         qh[dc][0], qh[dc][1], qh[dc][2], qh[dc][3], bl0, bl1);
            }
        }

        // ---- online softmax on fragments ----
        const float sc = 0.125f;
        float mx0 = -1e30f, mx1 = -1e30f;
#pragma unroll
        for (int nj = 0; nj < 8; nj++) {
            s[nj][0] *= sc; s[nj][1] *= sc; s[nj][2] *= sc; s[nj][3] *= sc;
            mx0 = fmaxf(mx0, fmaxf(s[nj][0], s[nj][1]));
            mx1 = fmaxf(mx1, fmaxf(s[nj][2], s[nj][3]));
        }
        mx0 = fmaxf(mx0, __shfl_xor_sync(0xffffffffu, mx0, 1));
        mx0 = fmaxf(mx0, __shfl_xor_sync(0xffffffffu, mx0, 2));
        mx1 = fmaxf(mx1, __shfl_xor_sync(0xffffffffu, mx1, 1));
        mx1 = fmaxf(mx1, __shfl_xor_sync(0xffffffffu, mx1, 2));
        float mn0 = fmaxf(m0, mx0), mn1 = fmaxf(m1, mx1);
        float a0 = __expf(m0 - mn0), a1 = __expf(m1 - mn1);
        float sum0 = 0.f, sum1 = 0.f;
#pragma unroll
        for (int nj = 0; nj < 8; nj++) {
            s[nj][0] = __expf(s[nj][0] - mn0);
            s[nj][1] = __expf(s[nj][1] - mn0);
            s[nj][2] = __expf(s[nj][2] - mn1);
            s[nj][3] = __expf(s[nj][3] - mn1);
            sum0 += s[nj][0] + s[nj][1];
            sum1 += s[nj][2] + s[nj][3];
        }
        sum0 += __shfl_xor_sync(0xffffffffu, sum0, 1);
        sum0 += __shfl_xor_sync(0xffffffffu, sum0, 2);
        sum1 += __shfl_xor_sync(0xffffffffu, sum1, 1);
        sum1 += __shfl_xor_sync(0xffffffffu, sum1, 2);
        l0 = l0 * a0 + sum0; l1 = l1 * a1 + sum1;
        m0 = mn0; m1 = mn1;
#pragma unroll
        for (int dj = 0; dj < 8; dj++) {
            o[dj][0] *= a0; o[dj][1] *= a0; o[dj][2] *= a1; o[dj][3] *= a1;
        }

        // ---- O += P V (P single bf16, V via ldmatrix.trans) ----
#pragma unroll
        for (int kc = 0; kc < 4; kc++) {
            uint32_t A0 = packbf(__float2bfloat16(s[2 * kc][0]),
                                 __float2bfloat16(s[2 * kc][1]));
            uint32_t A1 = packbf(__float2bfloat16(s[2 * kc][2]),
                                 __float2bfloat16(s[2 * kc][3]));
            uint32_t A2 = packbf(__float2bfloat16(s[2 * kc + 1][0]),
                                 __float2bfloat16(s[2 * kc + 1][1]));
            uint32_t A3 = packbf(__float2bfloat16(s[2 * kc + 1][2]),
                                 __float2bfloat16(s[2 * kc + 1][3]));
            int r = kc * 16 + (lane & 15);
#pragma unroll
            for (int dj = 0; dj < 8; dj++) {
                uint32_t addr = sV + (uint32_t)(r * 128 + ((dj ^ (r & 7)) * 16));
                uint32_t b0, b1;
                ldmx2t(b0, b1, addr);
                mma_bf16(o[dj][0], o[dj][1], o[dj][2], o[dj][3], A0, A1, A2, A3, b0, b1);
            }
        }

        __syncthreads();
        if (kt + 2 < SEQ / 64) loadKV(kt & 1, kt + 2);
    }

    // ---- epilogue: normalize, split hi/lo, store ctx ----
    float i0 = 1.f / l0, i1 = 1.f / l1;
    int r0 = q0 + wq + (lane >> 2);
    int cb = 2 * (lane & 3);
#pragma unroll
    for (int dj = 0; dj < 8; dj++) {
        int col = dj * 8 + cb;
        float v00 = o[dj][0] * i0, v01 = o[dj][1] * i0;
        float v10 = o[dj][2] * i1, v11 = o[dj][3] * i1;
        __nv_bfloat16 h00, l00, h01, l01, h10, l10, h11, l11;
        split1(v00, h00, l00); split1(v01, h01, l01);
        split1(v10, h10, l10); split1(v11, h11, l11);
        *(__nv_bfloat162*)&Ch[gb + (size_t)r0 * HID + col] = __nv_bfloat162(h00, h01);
        *(__nv_bfloat162*)&Ch[gb + (size_t)(r0 + 8) * HID + col] = __nv_bfloat162(h10, h11);
        *(__nv_bfloat162*)&Cl[gb + (size_t)r0 * HID + col] = __nv_bfloat162(l00, l01);
        *(__nv_bfloat162*)&Cl[gb + (size_t)(r0 + 8) * HID + col] = __nv_bfloat162(l10, l11);
    }
}

// ---------------------------------------------------------------------------
// LayerNorm: one block per row of 1024
// ---------------------------------------------------------------------------
__global__ __launch_bounds__(256)
void layernorm_kernel(const float* __restrict__ X, const float* __restrict__ gamma,
                      const float* __restrict__ beta, float* __restrict__ out)
{
    __shared__ float red[2][8];
    const int row = blockIdx.x;
    const int tid = threadIdx.x;
    const float* x = X + (size_t)row * HID;

    float4 v = *(const float4*)&x[tid * 4];
    float s  = v.x + v.y + v.z + v.w;
    float ss = v.x * v.x + v.y * v.y + v.z * v.z + v.w * v.w;
#pragma unroll
    for (int o = 16; o > 0; o >>= 1) {
        s  += __shfl_xor_sync(0xffffffffu, s, o);
        ss += __shfl_xor_sync(0xffffffffu, ss, o);
    }
    const int w = tid >> 5, l = tid & 31;
    if (l == 0) { red[0][w] = s; red[1][w] = ss; }
    __syncthreads();
    if (w == 0) {
        float s2  = (l < 8) ? red[0][l] : 0.f;
        float ss2 = (l < 8) ? red[1][l] : 0.f;
#pragma unroll
        for (int o = 4; o > 0; o >>= 1) {
            s2  += __shfl_xor_sync(0xffffffffu, s2, o);
            ss2 += __shfl_xor_sync(0xffffffffu, ss2, o);
        }
        if (l == 0) { red[0][0] = s2; red[1][0] = ss2; }
    }
    __syncthreads();

    const float mean = red[0][0] * (1.f / HID);
    const float var  = red[1][0] * (1.f / HID) - mean * mean;
    const float rstd = rsqrtf(var + 1e-5f);

    const int c = tid * 4;
    float4 gv = *(const float4*)&gamma[c];
    float4 bv = *(const float4*)&beta[c];
    float4 o;
    o.x = (v.x - mean) * rstd * gv.x + bv.x;
    o.y = (v.y - mean) * rstd * gv.y + bv.y;
    o.z = (v.z - mean) * rstd * gv.z + bv.z;
    o.w = (v.w - mean) * rstd * gv.w + bv.w;
    *(float4*)&out[(size_t)row * HID + c] = o;
}

// ---------------------------------------------------------------------------
// Launch
// ---------------------------------------------------------------------------
extern "C" void kernel_launch(void* const* d_in, const int* in_sizes, int n_in,
                              void* d_out, int out_size)
{
    const float* hidden = (const float*)d_in[0];
    const float* Wq = (const float*)d_in[1];
    const float* bq = (const float*)d_in[2];
    const float* Wk = (const float*)d_in[3];
    const float* bk = (const float*)d_in[4];
    const float* Wv = (const float*)d_in[5];
    const float* bv = (const float*)d_in[6];
    const float* Wo = (const float*)d_in[7];
    const float* bo = (const float*)d_in[8];
    const float* gamma = (const float*)d_in[9];
    const float* beta  = (const float*)d_in[10];
    float* out = (float*)d_out;

    float* x;
    cudaGetSymbolAddress((void**)&x, g_X);

    __nv_bfloat16 *hhi, *hlo, *chi, *clo, *qhp, *khp, *klp, *vbp;
    __nv_bfloat16 *wqh, *wql, *wkh, *wkl, *wvh, *wvl, *woh, *wol;
    cudaGetSymbolAddress((void**)&hhi, g_Hhi);
    cudaGetSymbolAddress((void**)&hlo, g_Hlo);
    cudaGetSymbolAddress((void**)&chi, g_Chi);
    cudaGetSymbolAddress((void**)&clo, g_Clo);
    cudaGetSymbolAddress((void**)&qhp, g_Qh);
    cudaGetSymbolAddress((void**)&khp, g_Kh);
    cudaGetSymbolAddress((void**)&klp, g_Kl);
    cudaGetSymbolAddress((void**)&vbp, g_Vb);
    cudaGetSymbolAddress((void**)&wqh, g_WqTh);
    cudaGetSymbolAddress((void**)&wql, g_WqTl);
    cudaGetSymbolAddress((void**)&wkh, g_WkTh);
    cudaGetSymbolAddress((void**)&wkl, g_WkTl);
    cudaGetSymbolAddress((void**)&wvh, g_WvTh);
    cudaGetSymbolAddress((void**)&wvl, g_WvTl);
    cudaGetSymbolAddress((void**)&woh, g_WoTh);
    cudaGetSymbolAddress((void**)&wol, g_WoTl);

    // ---- prep ----
    convert_split<<<(ROWS * HID / 4 + 255) / 256, 256>>>(hidden, hhi, hlo, ROWS * HID / 4);
    dim3 tg(HID / 32, HID / 32, 4), tb(32, 8);
    transpose_split4<<<tg, tb>>>(Wq, Wk, Wv, Wo,
                                 wqh, wql, wkh, wkl, wvh, wvl, woh, wol);

    // ---- merged QKV projection ----
    cudaFuncSetAttribute(gemm_qkv, cudaFuncAttributeMaxDynamicSharedMemorySize, GEMM_SMEM);
    cudaFuncSetAttribute(gemm_out, cudaFuncAttributeMaxDynamicSharedMemorySize, GEMM_SMEM);
    gemm_qkv<<<dim3(24, ROWS / 128), 256, GEMM_SMEM>>>(
        hhi, hlo, wqh, wql, wkh, wkl, wvh, wvl, bq, bk, bv,
        qhp, khp, klp, vbp);

    // ---- attention (tensor core, 2 CTAs/SM) ----
    cudaFuncSetAttribute(flash_mma, cudaFuncAttributeMaxDynamicSharedMemorySize, ATT_SMEM);
    flash_mma<<<dim3(SEQ / 128, HEADS, BATCH), 256, ATT_SMEM>>>(qhp, khp, klp, vbp,
                                                                chi, clo);

    // ---- output projection + residual ----
    gemm_out<<<dim3(HID / 128, ROWS / 128), 256, GEMM_SMEM>>>(chi, clo, woh, wol, bo,
                                                              hidden, x);

    // ---- layernorm ----
    layernorm_kernel<<<ROWS, 256>>>(x, gamma, beta, out);
}

// round 9
// speedup vs baseline: 4.5604x; 1.0139x over previous
#include <cuda_runtime.h>
#include <cuda_bf16.h>
#include <math.h>
#include <stdint.h>

// ---------------------------------------------------------------------------
// Problem constants
// ---------------------------------------------------------------------------
#define BATCH   2
#define SEQ     2048
#define HID     1024
#define HEADS   16
#define HDIM    64
#define ROWS    (BATCH * SEQ)          // 4096

// ---------------------------------------------------------------------------
// Scratch (static device globals -- no runtime allocation)
// ---------------------------------------------------------------------------
__device__ float g_X[ROWS * HID];

__device__ __nv_bfloat16 g_Hhi[ROWS * HID];
__device__ __nv_bfloat16 g_Hlo[ROWS * HID];
__device__ __nv_bfloat16 g_Qh[ROWS * HID];
__device__ __nv_bfloat16 g_Kh[ROWS * HID];
__device__ __nv_bfloat16 g_Kl[ROWS * HID];
__device__ __nv_bfloat16 g_Vb[ROWS * HID];
__device__ __nv_bfloat16 g_Chi[ROWS * HID];
__device__ __nv_bfloat16 g_Clo[ROWS * HID];
__device__ __nv_bfloat16 g_WqTh[HID * HID];
__device__ __nv_bfloat16 g_WqTl[HID * HID];
__device__ __nv_bfloat16 g_WkTh[HID * HID];
__device__ __nv_bfloat16 g_WkTl[HID * HID];
__device__ __nv_bfloat16 g_WvTh[HID * HID];
__device__ __nv_bfloat16 g_WvTl[HID * HID];
__device__ __nv_bfloat16 g_WoTh[HID * HID];
__device__ __nv_bfloat16 g_WoTl[HID * HID];

// ---------------------------------------------------------------------------
// PTX helpers
// ---------------------------------------------------------------------------
__device__ __forceinline__ uint32_t smem_u32(const void* p) {
    uint32_t a;
    asm("{ .reg .u64 t; cvta.to.shared.u64 t, %1; cvt.u32.u64 %0, t; }"
        : "=r"(a) : "l"(p));
    return a;
}
__device__ __forceinline__ void ldmx4(uint32_t& r0, uint32_t& r1, uint32_t& r2,
                                      uint32_t& r3, uint32_t addr) {
    asm volatile("ldmatrix.sync.aligned.m8n8.x4.shared.b16 {%0,%1,%2,%3}, [%4];"
                 : "=r"(r0), "=r"(r1), "=r"(r2), "=r"(r3) : "r"(addr));
}
__device__ __forceinline__ void ldmx2(uint32_t& r0, uint32_t& r1, uint32_t addr) {
    asm volatile("ldmatrix.sync.aligned.m8n8.x2.shared.b16 {%0,%1}, [%2];"
                 : "=r"(r0), "=r"(r1) : "r"(addr));
}
__device__ __forceinline__ void ldmx4t(uint32_t& r0, uint32_t& r1, uint32_t& r2,
                                       uint32_t& r3, uint32_t addr) {
    asm volatile("ldmatrix.sync.aligned.m8n8.x4.trans.shared.b16 {%0,%1,%2,%3}, [%4];"
                 : "=r"(r0), "=r"(r1), "=r"(r2), "=r"(r3) : "r"(addr));
}
__device__ __forceinline__ void mma_bf16(float& d0, float& d1, float& d2, float& d3,
                                         uint32_t a0, uint32_t a1, uint32_t a2,
                                         uint32_t a3, uint32_t b0, uint32_t b1) {
    asm volatile(
        "mma.sync.aligned.m16n8k16.row.col.f32.bf16.bf16.f32 "
        "{%0,%1,%2,%3}, {%4,%5,%6,%7}, {%8,%9}, {%0,%1,%2,%3};"
        : "+f"(d0), "+f"(d1), "+f"(d2), "+f"(d3)
        : "r"(a0), "r"(a1), "r"(a2), "r"(a3), "r"(b0), "r"(b1));
}
__device__ __forceinline__ void cp16(uint32_t dst, const void* src) {
    asm volatile("cp.async.cg.shared.global [%0], [%1], 16;"
                 :: "r"(dst), "l"(src));
}
__device__ __forceinline__ void cp_commit() {
    asm volatile("cp.async.commit_group;" ::: "memory");
}
template <int N>
__device__ __forceinline__ void cp_wait() {
    asm volatile("cp.async.wait_group %0;" :: "n"(N) : "memory");
}

__device__ __forceinline__ void split1(float x, __nv_bfloat16& h, __nv_bfloat16& l) {
    h = __float2bfloat16(x);
    l = __float2bfloat16(x - __bfloat162float(h));
}
__device__ __forceinline__ uint32_t packbf(__nv_bfloat16 a, __nv_bfloat16 b) {
    __nv_bfloat162 t(a, b);
    return *(uint32_t*)&t;
}

// ---------------------------------------------------------------------------
// fp32 -> bf16 hi/lo split (elementwise)
// ---------------------------------------------------------------------------
__global__ __launch_bounds__(256)
void convert_split(const float* __restrict__ in, __nv_bfloat16* __restrict__ hi,
                   __nv_bfloat16* __restrict__ lo, int n4)
{
    int i = blockIdx.x * blockDim.x + threadIdx.x;
    if (i >= n4) return;
    float4 v = ((const float4*)in)[i];
    __nv_bfloat16 h0, l0, h1, l1, h2, l2, h3, l3;
    split1(v.x, h0, l0); split1(v.y, h1, l1);
    split1(v.z, h2, l2); split1(v.w, h3, l3);
    ((__nv_bfloat162*)hi)[2 * i + 0] = __nv_bfloat162(h0, h1);
    ((__nv_bfloat162*)hi)[2 * i + 1] = __nv_bfloat162(h2, h3);
    ((__nv_bfloat162*)lo)[2 * i + 0] = __nv_bfloat162(l0, l1);
    ((__nv_bfloat162*)lo)[2 * i + 1] = __nv_bfloat162(l2, l3);
}

// ---------------------------------------------------------------------------
// All four W [K,N] fp32 -> transposed hi/lo bf16 [N,K] in one launch (z=4)
// ---------------------------------------------------------------------------
__global__ __launch_bounds__(256)
void transpose_split4(const float* __restrict__ W0, const float* __restrict__ W1,
                      const float* __restrict__ W2, const float* __restrict__ W3,
                      __nv_bfloat16* __restrict__ T0h, __nv_bfloat16* __restrict__ T0l,
                      __nv_bfloat16* __restrict__ T1h, __nv_bfloat16* __restrict__ T1l,
                      __nv_bfloat16* __restrict__ T2h, __nv_bfloat16* __restrict__ T2l,
                      __nv_bfloat16* __restrict__ T3h, __nv_bfloat16* __restrict__ T3l)
{
    __shared__ float t[32][33];
    const int z = blockIdx.z;
    const float* W = (z == 0) ? W0 : (z == 1) ? W1 : (z == 2) ? W2 : W3;
    __nv_bfloat16* Th = (z == 0) ? T0h : (z == 1) ? T1h : (z == 2) ? T2h : T3h;
    __nv_bfloat16* Tl = (z == 0) ? T0l : (z == 1) ? T1l : (z == 2) ? T2l : T3l;

    const int n0 = blockIdx.x * 32, k0 = blockIdx.y * 32;
    const int tx = threadIdx.x, ty = threadIdx.y;
#pragma unroll
    for (int i = 0; i < 32; i += 8)
        t[ty + i][tx] = W[(size_t)(k0 + ty + i) * HID + n0 + tx];
    __syncthreads();
#pragma unroll
    for (int i = 0; i < 32; i += 8) {
        float x = t[tx][ty + i];
        __nv_bfloat16 h, l; split1(x, h, l);
        Th[(size_t)(n0 + ty + i) * HID + k0 + tx] = h;
        Tl[(size_t)(n0 + ty + i) * HID + k0 + tx] = l;
    }
}

// ---------------------------------------------------------------------------
// GEMM mainloop shared constants
// ---------------------------------------------------------------------------
#define PIPE 3
#define STAGE_BYTES 32768
#define GEMM_SMEM   (PIPE * STAGE_BYTES)
#define NKC  (HID / 32)

// ---------------------------------------------------------------------------
// Merged QKV projection: grid (24, 32). blockIdx.x>>3 selects Q/K/V.
// Q -> hi only (pre-scaled by 1/8), 2-term; K -> hi/lo, 3-term; V -> hi, 2-term.
// ---------------------------------------------------------------------------
__global__ __launch_bounds__(256, 2)
void gemm_qkv(const __nv_bfloat16* __restrict__ Ahi, const __nv_bfloat16* __restrict__ Alo,
              const __nv_bfloat16* __restrict__ Bqh, const __nv_bfloat16* __restrict__ Bql,
              const __nv_bfloat16* __restrict__ Bkh, const __nv_bfloat16* __restrict__ Bkl,
              const __nv_bfloat16* __restrict__ Bvh, const __nv_bfloat16* __restrict__ Bvl,
              const float* __restrict__ bq, const float* __restrict__ bk,
              const float* __restrict__ bv,
              __nv_bfloat16* __restrict__ Qh,
              __nv_bfloat16* __restrict__ Kh, __nv_bfloat16* __restrict__ Kl,
              __nv_bfloat16* __restrict__ Vb)
{
    extern __shared__ char smc[];
    const uint32_t sbase = smem_u32(smc);

    const int sel = blockIdx.x >> 3;
    const __nv_bfloat16* Bhi = (sel == 0) ? Bqh : (sel == 1) ? Bkh : Bvh;
    const __nv_bfloat16* Blo = (sel == 0) ? Bql : (sel == 1) ? Bkl : Bvl;
    const float* bias = (sel == 0) ? bq : (sel == 1) ? bk : bv;
    __nv_bfloat16* Ch = (sel == 0) ? Qh : (sel == 1) ? Kh : Vb;
    __nv_bfloat16* Cl = (sel == 1) ? Kl : nullptr;
    const bool three_term = (sel == 1);

    const int tid  = threadIdx.x;
    const int lane = tid & 31;
    const int warp = tid >> 5;
    const int wm   = (warp >> 2) * 64;
    const int wn   = (warp & 3) * 32;
    const int m0 = blockIdx.y * 128, n0 = (blockIdx.x & 7) * 128;

    auto load_stage = [&](int stage, int kc) {
        const uint32_t sb = sbase + stage * STAGE_BYTES;
#pragma unroll
        for (int t = 0; t < 8; t++) {
            int idx  = tid + t * 256;
            int tile = idx >> 10;
            int r    = (idx >> 3) & 127;
            int c    = idx & 7;
            const __nv_bfloat16* src;
            if (tile == 0)
                src = (c < 4 ? Ahi : Alo) + (size_t)(m0 + r) * HID + kc * 32 + (c & 3) * 8;
            else
                src = (c < 4 ? Bhi : Blo) + (size_t)(n0 + r) * HID + kc * 32 + (c & 3) * 8;
            uint32_t dst = sb + (uint32_t)(tile * 16384 + r * 128 + ((c ^ (r & 7)) * 16));
            cp16(dst, src);
        }
        cp_commit();
    };

    float acc[4][4][4];
#pragma unroll
    for (int mi = 0; mi < 4; mi++)
#pragma unroll
        for (int nj = 0; nj < 4; nj++)
#pragma unroll
            for (int e = 0; e < 4; e++) acc[mi][nj][e] = 0.f;

    load_stage(0, 0);
    load_stage(1, 1);

    for (int kc = 0; kc < NKC; kc++) {
        cp_wait<PIPE - 2>();
        __syncthreads();
        if (kc + 2 < NKC) load_stage((kc + 2) % PIPE, kc + 2);

        const uint32_t sA = sbase + (kc % PIPE) * STAGE_BYTES;
        const uint32_t sB = sA + 16384;

#pragma unroll
        for (int ks = 0; ks < 2; ks++) {
            uint32_t bh[4][2], bl[4][2];
#pragma unroll
            for (int nj = 0; nj < 4; nj++) {
                int r  = wn + nj * 8 + (lane & 7);
                int cc = ks * 2 + ((lane >> 3) & 1);
                ldmx2(bh[nj][0], bh[nj][1],
                      sB + (uint32_t)(r * 128 + ((cc ^ (r & 7)) * 16)));
                ldmx2(bl[nj][0], bl[nj][1],
                      sB + (uint32_t)(r * 128 + (((cc + 4) ^ (r & 7)) * 16)));
            }
#pragma unroll
            for (int mi = 0; mi < 4; mi++) {
                int r  = wm + mi * 16 + (lane & 15);
                int cc = ks * 2 + (lane >> 4);
                uint32_t ah0, ah1, ah2, ah3, al0, al1, al2, al3;
                ldmx4(ah0, ah1, ah2, ah3,
                      sA + (uint32_t)(r * 128 + ((cc ^ (r & 7)) * 16)));
                ldmx4(al0, al1, al2, al3,
                      sA + (uint32_t)(r * 128 + (((cc + 4) ^ (r & 7)) * 16)));
#pragma unroll
                for (int nj = 0; nj < 4; nj++) {
                    mma_bf16(acc[mi][nj][0], acc[mi][nj][1], acc[mi][nj][2], acc[mi][nj][3],
                             ah0, ah1, ah2, ah3, bh[nj][0], bh[nj][1]);
                    mma_bf16(acc[mi][nj][0], acc[mi][nj][1], acc[mi][nj][2], acc[mi][nj][3],
                             ah0, ah1, ah2, ah3, bl[nj][0], bl[nj][1]);
                    if (three_term)
                        mma_bf16(acc[mi][nj][0], acc[mi][nj][1], acc[mi][nj][2], acc[mi][nj][3],
                                 al0, al1, al2, al3, bh[nj][0], bh[nj][1]);
                }
            }
        }
    }

    const float oscale = (sel == 0) ? 0.125f : 1.0f;   // fold 1/sqrt(64) into Q
#pragma unroll
    for (int mi = 0; mi < 4; mi++) {
#pragma unroll
        for (int nj = 0; nj < 4; nj++) {
            int row = m0 + wm + mi * 16 + (lane >> 2);
            int col = n0 + wn + nj * 8 + 2 * (lane & 3);
            float b0 = bias[col], b1 = bias[col + 1];
            float v00 = (acc[mi][nj][0] + b0) * oscale, v01 = (acc[mi][nj][1] + b1) * oscale;
            float v10 = (acc[mi][nj][2] + b0) * oscale, v11 = (acc[mi][nj][3] + b1) * oscale;
            __nv_bfloat16 h00, l00, h01, l01, h10, l10, h11, l11;
            split1(v00, h00, l00); split1(v01, h01, l01);
            split1(v10, h10, l10); split1(v11, h11, l11);
            *(__nv_bfloat162*)&Ch[(size_t)row * HID + col] = __nv_bfloat162(h00, h01);
            *(__nv_bfloat162*)&Ch[(size_t)(row + 8) * HID + col] = __nv_bfloat162(h10, h11);
            if (Cl) {
                *(__nv_bfloat162*)&Cl[(size_t)row * HID + col] = __nv_bfloat162(l00, l01);
                *(__nv_bfloat162*)&Cl[(size_t)(row + 8) * HID + col] = __nv_bfloat162(l10, l11);
            }
        }
    }
}

// ---------------------------------------------------------------------------
// Output projection GEMM (fp32 out + residual, 3-term)
// ---------------------------------------------------------------------------
__global__ __launch_bounds__(256, 2)
void gemm_out(const __nv_bfloat16* __restrict__ Ahi, const __nv_bfloat16* __restrict__ Alo,
              const __nv_bfloat16* __restrict__ Bhi, const __nv_bfloat16* __restrict__ Blo,
              const float* __restrict__ bias, const float* __restrict__ res,
              float* __restrict__ Cf)
{
    extern __shared__ char smc[];
    const uint32_t sbase = smem_u32(smc);

    const int tid  = threadIdx.x;
    const int lane = tid & 31;
    const int warp = tid >> 5;
    const int wm   = (warp >> 2) * 64;
    const int wn   = (warp & 3) * 32;
    const int m0 = blockIdx.y * 128, n0 = blockIdx.x * 128;

    auto load_stage = [&](int stage, int kc) {
        const uint32_t sb = sbase + stage * STAGE_BYTES;
#pragma unroll
        for (int t = 0; t < 8; t++) {
            int idx  = tid + t * 256;
            int tile = idx >> 10;
            int r    = (idx >> 3) & 127;
            int c    = idx & 7;
            const __nv_bfloat16* src;
            if (tile == 0)
                src = (c < 4 ? Ahi : Alo) + (size_t)(m0 + r) * HID + kc * 32 + (c & 3) * 8;
            else
                src = (c < 4 ? Bhi : Blo) + (size_t)(n0 + r) * HID + kc * 32 + (c & 3) * 8;
            uint32_t dst = sb + (uint32_t)(tile * 16384 + r * 128 + ((c ^ (r & 7)) * 16));
            cp16(dst, src);
        }
        cp_commit();
    };

    float acc[4][4][4];
#pragma unroll
    for (int mi = 0; mi < 4; mi++)
#pragma unroll
        for (int nj = 0; nj < 4; nj++)
#pragma unroll
            for (int e = 0; e < 4; e++) acc[mi][nj][e] = 0.f;

    load_stage(0, 0);
    load_stage(1, 1);

    for (int kc = 0; kc < NKC; kc++) {
        cp_wait<PIPE - 2>();
        __syncthreads();
        if (kc + 2 < NKC) load_stage((kc + 2) % PIPE, kc + 2);

        const uint32_t sA = sbase + (kc % PIPE) * STAGE_BYTES;
        const uint32_t sB = sA + 16384;

#pragma unroll
        for (int ks = 0; ks < 2; ks++) {
            uint32_t bh[4][2], bl[4][2];
#pragma unroll
            for (int nj = 0; nj < 4; nj++) {
                int r  = wn + nj * 8 + (lane & 7);
                int cc = ks * 2 + ((lane >> 3) & 1);
                ldmx2(bh[nj][0], bh[nj][1],
                      sB + (uint32_t)(r * 128 + ((cc ^ (r & 7)) * 16)));
                ldmx2(bl[nj][0], bl[nj][1],
                      sB + (uint32_t)(r * 128 + (((cc + 4) ^ (r & 7)) * 16)));
            }
#pragma unroll
            for (int mi = 0; mi < 4; mi++) {
                int r  = wm + mi * 16 + (lane & 15);
                int cc = ks * 2 + (lane >> 4);
                uint32_t ah0, ah1, ah2, ah3, al0, al1, al2, al3;
                ldmx4(ah0, ah1, ah2, ah3,
                      sA + (uint32_t)(r * 128 + ((cc ^ (r & 7)) * 16)));
                ldmx4(al0, al1, al2, al3,
                      sA + (uint32_t)(r * 128 + (((cc + 4) ^ (r & 7)) * 16)));
#pragma unroll
                for (int nj = 0; nj < 4; nj++) {
                    mma_bf16(acc[mi][nj][0], acc[mi][nj][1], acc[mi][nj][2], acc[mi][nj][3],
                             ah0, ah1, ah2, ah3, bh[nj][0], bh[nj][1]);
                    mma_bf16(acc[mi][nj][0], acc[mi][nj][1], acc[mi][nj][2], acc[mi][nj][3],
                             ah0, ah1, ah2, ah3, bl[nj][0], bl[nj][1]);
                    mma_bf16(acc[mi][nj][0], acc[mi][nj][1], acc[mi][nj][2], acc[mi][nj][3],
                             al0, al1, al2, al3, bh[nj][0], bh[nj][1]);
                }
            }
        }
    }

#pragma unroll
    for (int mi = 0; mi < 4; mi++) {
#pragma unroll
        for (int nj = 0; nj < 4; nj++) {
            int row = m0 + wm + mi * 16 + (lane >> 2);
            int col = n0 + wn + nj * 8 + 2 * (lane & 3);
            float b0 = bias[col], b1 = bias[col + 1];
            float v00 = acc[mi][nj][0] + b0, v01 = acc[mi][nj][1] + b1;
            float v10 = acc[mi][nj][2] + b0, v11 = acc[mi][nj][3] + b1;
            float2 r0 = *(const float2*)&res[(size_t)row * HID + col];
            float2 r1 = *(const float2*)&res[(size_t)(row + 8) * HID + col];
            v00 += r0.x; v01 += r0.y; v10 += r1.x; v11 += r1.y;
            *(float2*)&Cf[(size_t)row * HID + col] = make_float2(v00, v01);
            *(float2*)&Cf[(size_t)(row + 8) * HID + col] = make_float2(v10, v11);
        }
    }
}

// ---------------------------------------------------------------------------
// Flash attention via mma.sync:
//   S = Qh*Kh + Qh*Kl (Q pre-scaled by 1/8); softmax in fragments;
//   O += P_hi * V.  K-tile 64, 2 CTAs/SM, paired ldmatrix.x4 loads.
// ---------------------------------------------------------------------------
#define ASTAGE 24576                           // Khi 8K + Klo 8K + V 8K
#define ATT_SMEM (16384 + 2 * ASTAGE)          // + Qhi 16K = 64K

__global__ __launch_bounds__(256, 2)
void flash_mma(const __nv_bfloat16* __restrict__ Qh,
               const __nv_bfloat16* __restrict__ Kh, const __nv_bfloat16* __restrict__ Kl,
               const __nv_bfloat16* __restrict__ Vb,
               __nv_bfloat16* __restrict__ Ch, __nv_bfloat16* __restrict__ Cl)
{
    extern __shared__ char sma[];
    const uint32_t sQ = smem_u32(sma);        // Qhi 16K
    const uint32_t sS = sQ + 16384;           // 2 stages of {Khi 8K, Klo 8K, V 8K}

    const int tid = threadIdx.x, lane = tid & 31, warp = tid >> 5;
    const int q0 = blockIdx.x * 128;
    const int h = blockIdx.y, b = blockIdx.z;
    const size_t gb = (size_t)b * SEQ * HID + (size_t)h * HDIM;

    // Q hi tile -> smem (swizzled, 128 rows x 128 B)
#pragma unroll
    for (int t = 0; t < 4; t++) {
        int idx = tid + t * 256;               // 0..1023
        int r = idx >> 3, c = idx & 7;
        const __nv_bfloat16* src = Qh + gb + (size_t)(q0 + r) * HID + c * 8;
        cp16(sQ + (uint32_t)(r * 128 + ((c ^ (r & 7)) * 16)), src);
    }
    cp_commit();

    auto loadKV = [&](int stage, int kt) {     // kt indexes 64-row K tiles
        const uint32_t sb = sS + stage * ASTAGE;
#pragma unroll
        for (int t = 0; t < 6; t++) {
            int idx = tid + t * 256;           // 0..1535
            int tile = idx >> 9;               // 0=Kh 1=Kl 2=V (512 slots each)
            int r = (idx >> 3) & 63, c = idx & 7;
            const __nv_bfloat16* src =
                (tile == 0 ? Kh : tile == 1 ? Kl : Vb) + gb + (size_t)(kt * 64 + r) * HID + c * 8;
            cp16(sb + (uint32_t)(tile * 8192 + r * 128 + ((c ^ (r & 7)) * 16)), src);
        }
        cp_commit();
    };
    loadKV(0, 0);
    loadKV(1, 1);

    cp_wait<2>();          // Q resident
    __syncthreads();

    // Q fragments (registers, whole kernel)
    const int wq = warp * 16;
    uint32_t qh[4][4];
#pragma unroll
    for (int dc = 0; dc < 4; dc++) {
        int r = wq + (lane & 15);
        int cc = dc * 2 + (lane >> 4);
        ldmx4(qh[dc][0], qh[dc][1], qh[dc][2], qh[dc][3],
              sQ + (uint32_t)(r * 128 + ((cc ^ (r & 7)) * 16)));
    }

    float m0 = -1e30f, m1 = -1e30f, l0 = 0.f, l1 = 0.f;
    float o[8][4];
#pragma unroll
    for (int dj = 0; dj < 8; dj++)
#pragma unroll
        for (int e = 0; e < 4; e++) o[dj][e] = 0.f;

    for (int kt = 0; kt < SEQ / 64; kt++) {
        cp_wait<1>();
        __syncthreads();
        const uint32_t sK  = sS + (kt & 1) * ASTAGE;
        const uint32_t sKl = sK + 8192;
        const uint32_t sV  = sK + 16384;

        // ---- S = Q K^T (Qh*Kh + Qh*Kl); paired n-tiles via ldmatrix.x4 ----
        float s[8][4];
#pragma unroll
        for (int nj = 0; nj < 8; nj++)
#pragma unroll
            for (int e = 0; e < 4; e++) s[nj][e] = 0.f;

#pragma unroll
        for (int np = 0; np < 4; np++) {       // pair of n-tiles (2np, 2np+1)
            int r = (np * 2 + (lane >> 4)) * 8 + (lane & 7);
#pragma unroll
            for (int dc = 0; dc < 4; dc++) {
                int cc = dc * 2 + ((lane >> 3) & 1);
                uint32_t off = (uint32_t)(r * 128 + ((cc ^ (r & 7)) * 16));
                uint32_t h0, h1, h2, h3, e0, e1, e2, e3;
                ldmx4(h0, h1, h2, h3, sK + off);
                ldmx4(e0, e1, e2, e3, sKl + off);
                mma_bf16(s[2*np][0], s[2*np][1], s[2*np][2], s[2*np][3],
                         qh[dc][0], qh[dc][1], qh[dc][2], qh[dc][3], h0, h1);
                mma_bf16(s[2*np][0], s[2*np][1], s[2*np][2], s[2*np][3],
                         qh[dc][0], qh[dc][1], qh[dc][2], qh[dc][3], e0, e1);
                mma_bf16(s[2*np+1][0], s[2*np+1][1], s[2*np+1][2], s[2*np+1][3],
                         qh[dc][0], qh[dc][1], qh[dc][2], qh[dc][3], h2, h3);
                mma_bf16(s[2*np+1][0], s[2*np+1][1], s[2*np+1][2], s[2*np+1][3],
                         qh[dc][0], qh[dc][1], qh[dc][2], qh[dc][3], e2, e3);
            }
        }

        // ---- online softmax on fragments (Q pre-scaled; no mul here) ----
        float mx0 = -1e30f, mx1 = -1e30f;
#pragma unroll
        for (int nj = 0; nj < 8; nj++) {
            mx0 = fmaxf(mx0, fmaxf(s[nj][0], s[nj][1]));
            mx1 = fmaxf(mx1, fmaxf(s[nj][2], s[nj][3]));
        }
        mx0 = fmaxf(mx0, __shfl_xor_sync(0xffffffffu, mx0, 1));
        mx0 = fmaxf(mx0, __shfl_xor_sync(0xffffffffu, mx0, 2));
        mx1 = fmaxf(mx1, __shfl_xor_sync(0xffffffffu, mx1, 1));
        mx1 = fmaxf(mx1, __shfl_xor_sync(0xffffffffu, mx1, 2));
        float mn0 = fmaxf(m0, mx0), mn1 = fmaxf(m1, mx1);
        float a0 = __expf(m0 - mn0), a1 = __expf(m1 - mn1);
        float sum0 = 0.f, sum1 = 0.f;
#pragma unroll
        for (int nj = 0; nj < 8; nj++) {
            s[nj][0] = __expf(s[nj][0] - mn0);
            s[nj][1] = __expf(s[nj][1] - mn0);
            s[nj][2] = __expf(s[nj][2] - mn1);
            s[nj][3] = __expf(s[nj][3] - mn1);
            sum0 += s[nj][0] + s[nj][1];
            sum1 += s[nj][2] + s[nj][3];
        }
        sum0 += __shfl_xor_sync(0xffffffffu, sum0, 1);
        sum0 += __shfl_xor_sync(0xffffffffu, sum0, 2);
        sum1 += __shfl_xor_sync(0xffffffffu, sum1, 1);
        sum1 += __shfl_xor_sync(0xffffffffu, sum1, 2);
        l0 = l0 * a0 + sum0; l1 = l1 * a1 + sum1;
        m0 = mn0; m1 = mn1;
#pragma unroll
        for (int dj = 0; dj < 8; dj++) {
            o[dj][0] *= a0; o[dj][1] *= a0; o[dj][2] *= a1; o[dj][3] *= a1;
        }

        // ---- O += P V (P single bf16; paired d-tiles via ldmatrix.x4.trans) ----
#pragma unroll
        for (int kc = 0; kc < 4; kc++) {
            uint32_t A0 = packbf(__float2bfloat16(s[2 * kc][0]),
                                 __float2bfloat16(s[2 * kc][1]));
            uint32_t A1 = packbf(__float2bfloat16(s[2 * kc][2]),
                                 __float2bfloat16(s[2 * kc][3]));
            uint32_t A2 = packbf(__float2bfloat16(s[2 * kc + 1][0]),
                                 __float2bfloat16(s[2 * kc + 1][1]));
            uint32_t A3 = packbf(__float2bfloat16(s[2 * kc + 1][2]),
                                 __float2bfloat16(s[2 * kc + 1][3]));
            int r = kc * 16 + (lane & 15);
#pragma unroll
            for (int dp = 0; dp < 4; dp++) {   // pair of d-tiles (2dp, 2dp+1)
                int c = dp * 2 + (lane >> 4);
                uint32_t addr = sV + (uint32_t)(r * 128 + ((c ^ (r & 7)) * 16));
                uint32_t b0, b1, b2, b3;
                ldmx4t(b0, b1, b2, b3, addr);
                mma_bf16(o[2*dp][0], o[2*dp][1], o[2*dp][2], o[2*dp][3],
                         A0, A1, A2, A3, b0, b1);
                mma_bf16(o[2*dp+1][0], o[2*dp+1][1], o[2*dp+1][2], o[2*dp+1][3],
                         A0, A1, A2, A3, b2, b3);
            }
        }

        __syncthreads();
        if (kt + 2 < SEQ / 64) loadKV(kt & 1, kt + 2);
    }

    // ---- epilogue: normalize, split hi/lo, store ctx ----
    float i0 = 1.f / l0, i1 = 1.f / l1;
    int r0 = q0 + wq + (lane >> 2);
    int cb = 2 * (lane & 3);
#pragma unroll
    for (int dj = 0; dj < 8; dj++) {
        int col = dj * 8 + cb;
        float v00 = o[dj][0] * i0, v01 = o[dj][1] * i0;
        float v10 = o[dj][2] * i1, v11 = o[dj][3] * i1;
        __nv_bfloat16 h00, l00, h01, l01, h10, l10, h11, l11;
        split1(v00, h00, l00); split1(v01, h01, l01);
        split1(v10, h10, l10); split1(v11, h11, l11);
        *(__nv_bfloat162*)&Ch[gb + (size_t)r0 * HID + col] = __nv_bfloat162(h00, h01);
        *(__nv_bfloat162*)&Ch[gb + (size_t)(r0 + 8) * HID + col] = __nv_bfloat162(h10, h11);
        *(__nv_bfloat162*)&Cl[gb + (size_t)r0 * HID + col] = __nv_bfloat162(l00, l01);
        *(__nv_bfloat162*)&Cl[gb + (size_t)(r0 + 8) * HID + col] = __nv_bfloat162(l10, l11);
    }
}

// ---------------------------------------------------------------------------
// LayerNorm: one block per row of 1024
// ---------------------------------------------------------------------------
__global__ __launch_bounds__(256)
void layernorm_kernel(const float* __restrict__ X, const float* __restrict__ gamma,
                      const float* __restrict__ beta, float* __restrict__ out)
{
    __shared__ float red[2][8];
    const int row = blockIdx.x;
    const int tid = threadIdx.x;
    const float* x = X + (size_t)row * HID;

    float4 v = *(const float4*)&x[tid * 4];
    float s  = v.x + v.y + v.z + v.w;
    float ss = v.x * v.x + v.y * v.y + v.z * v.z + v.w * v.w;
#pragma unroll
    for (int o = 16; o > 0; o >>= 1) {
        s  += __shfl_xor_sync(0xffffffffu, s, o);
        ss += __shfl_xor_sync(0xffffffffu, ss, o);
    }
    const int w = tid >> 5, l = tid & 31;
    if (l == 0) { red[0][w] = s; red[1][w] = ss; }
    __syncthreads();
    if (w == 0) {
        float s2  = (l < 8) ? red[0][l] : 0.f;
        float ss2 = (l < 8) ? red[1][l] : 0.f;
#pragma unroll
        for (int o = 4; o > 0; o >>= 1) {
            s2  += __shfl_xor_sync(0xffffffffu, s2, o);
            ss2 += __shfl_xor_sync(0xffffffffu, ss2, o);
        }
        if (l == 0) { red[0][0] = s2; red[1][0] = ss2; }
    }
    __syncthreads();

    const float mean = red[0][0] * (1.f / HID);
    const float var  = red[1][0] * (1.f / HID) - mean * mean;
    const float rstd = rsqrtf(var + 1e-5f);

    const int c = tid * 4;
    float4 gv = *(const float4*)&gamma[c];
    float4 bv = *(const float4*)&beta[c];
    float4 o;
    o.x = (v.x - mean) * rstd * gv.x + bv.x;
    o.y = (v.y - mean) * rstd * gv.y + bv.y;
    o.z = (v.z - mean) * rstd * gv.z + bv.z;
    o.w = (v.w - mean) * rstd * gv.w + bv.w;
    *(float4*)&out[(size_t)row * HID + c] = o;
}

// ---------------------------------------------------------------------------
// Launch
// ---------------------------------------------------------------------------
extern "C" void kernel_launch(void* const* d_in, const int* in_sizes, int n_in,
                              void* d_out, int out_size)
{
    const float* hidden = (const float*)d_in[0];
    const float* Wq = (const float*)d_in[1];
    const float* bq = (const float*)d_in[2];
    const float* Wk = (const float*)d_in[3];
    const float* bk = (const float*)d_in[4];
    const float* Wv = (const float*)d_in[5];
    const float* bv = (const float*)d_in[6];
    const float* Wo = (const float*)d_in[7];
    const float* bo = (const float*)d_in[8];
    const float* gamma = (const float*)d_in[9];
    const float* beta  = (const float*)d_in[10];
    float* out = (float*)d_out;

    float* x;
    cudaGetSymbolAddress((void**)&x, g_X);

    __nv_bfloat16 *hhi, *hlo, *chi, *clo, *qhp, *khp, *klp, *vbp;
    __nv_bfloat16 *wqh, *wql, *wkh, *wkl, *wvh, *wvl, *woh, *wol;
    cudaGetSymbolAddress((void**)&hhi, g_Hhi);
    cudaGetSymbolAddress((void**)&hlo, g_Hlo);
    cudaGetSymbolAddress((void**)&chi, g_Chi);
    cudaGetSymbolAddress((void**)&clo, g_Clo);
    cudaGetSymbolAddress((void**)&qhp, g_Qh);
    cudaGetSymbolAddress((void**)&khp, g_Kh);
    cudaGetSymbolAddress((void**)&klp, g_Kl);
    cudaGetSymbolAddress((void**)&vbp, g_Vb);
    cudaGetSymbolAddress((void**)&wqh, g_WqTh);
    cudaGetSymbolAddress((void**)&wql, g_WqTl);
    cudaGetSymbolAddress((void**)&wkh, g_WkTh);
    cudaGetSymbolAddress((void**)&wkl, g_WkTl);
    cudaGetSymbolAddress((void**)&wvh, g_WvTh);
    cudaGetSymbolAddress((void**)&wvl, g_WvTl);
    cudaGetSymbolAddress((void**)&woh, g_WoTh);
    cudaGetSymbolAddress((void**)&wol, g_WoTl);

    // ---- prep ----
    convert_split<<<(ROWS * HID / 4 + 255) / 256, 256>>>(hidden, hhi, hlo, ROWS * HID / 4);
    dim3 tg(HID / 32, HID / 32, 4), tb(32, 8);
    transpose_split4<<<tg, tb>>>(Wq, Wk, Wv, Wo,
                                 wqh, wql, wkh, wkl, wvh, wvl, woh, wol);

    // ---- merged QKV projection ----
    cudaFuncSetAttribute(gemm_qkv, cudaFuncAttributeMaxDynamicSharedMemorySize, GEMM_SMEM);
    cudaFuncSetAttribute(gemm_out, cudaFuncAttributeMaxDynamicSharedMemorySize, GEMM_SMEM);
    gemm_qkv<<<dim3(24, ROWS / 128), 256, GEMM_SMEM>>>(
        hhi, hlo, wqh, wql, wkh, wkl, wvh, wvl, bq, bk, bv,
        qhp, khp, klp, vbp);

    // ---- attention (tensor core, 2 CTAs/SM) ----
    cudaFuncSetAttribute(flash_mma, cudaFuncAttributeMaxDynamicSharedMemorySize, ATT_SMEM);
    flash_mma<<<dim3(SEQ / 128, HEADS, BATCH), 256, ATT_SMEM>>>(qhp, khp, klp, vbp,
                                                                chi, clo);

    // ---- output projection + residual ----
    gemm_out<<<dim3(HID / 128, ROWS / 128), 256, GEMM_SMEM>>>(chi, clo, woh, wol, bo,
                                                              hidden, x);

    // ---- layernorm ----
    layernorm_kernel<<<ROWS, 256>>>(x, gamma, beta, out);
}

// round 10
// speedup vs baseline: 5.7066x; 1.2513x over previous
#include <cuda_runtime.h>
#include <cuda_bf16.h>
#include <math.h>
#include <stdint.h>

// ---------------------------------------------------------------------------
// Problem constants
// ---------------------------------------------------------------------------
#define BATCH   2
#define SEQ     2048
#define HID     1024
#define HEADS   16
#define HDIM    64
#define ROWS    (BATCH * SEQ)          // 4096

// ---------------------------------------------------------------------------
// Scratch (static device globals -- no runtime allocation)
// ---------------------------------------------------------------------------
__device__ float g_X[ROWS * HID];

__device__ __nv_bfloat16 g_Hhi[ROWS * HID];
__device__ __nv_bfloat16 g_Hlo[ROWS * HID];
__device__ __nv_bfloat16 g_Qh[ROWS * HID];
__device__ __nv_bfloat16 g_Kh[ROWS * HID];
__device__ __nv_bfloat16 g_Vb[ROWS * HID];
__device__ __nv_bfloat16 g_Chi[ROWS * HID];
__device__ __nv_bfloat16 g_Clo[ROWS * HID];
__device__ __nv_bfloat16 g_WqTh[HID * HID];
__device__ __nv_bfloat16 g_WqTl[HID * HID];
__device__ __nv_bfloat16 g_WkTh[HID * HID];
__device__ __nv_bfloat16 g_WkTl[HID * HID];
__device__ __nv_bfloat16 g_WvTh[HID * HID];
__device__ __nv_bfloat16 g_WvTl[HID * HID];
__device__ __nv_bfloat16 g_WoTh[HID * HID];
__device__ __nv_bfloat16 g_WoTl[HID * HID];

// ---------------------------------------------------------------------------
// PTX helpers
// ---------------------------------------------------------------------------
__device__ __forceinline__ uint32_t smem_u32(const void* p) {
    uint32_t a;
    asm("{ .reg .u64 t; cvta.to.shared.u64 t, %1; cvt.u32.u64 %0, t; }"
        : "=r"(a) : "l"(p));
    return a;
}
__device__ __forceinline__ void ldmx4(uint32_t& r0, uint32_t& r1, uint32_t& r2,
                                      uint32_t& r3, uint32_t addr) {
    asm volatile("ldmatrix.sync.aligned.m8n8.x4.shared.b16 {%0,%1,%2,%3}, [%4];"
                 : "=r"(r0), "=r"(r1), "=r"(r2), "=r"(r3) : "r"(addr));
}
__device__ __forceinline__ void ldmx2(uint32_t& r0, uint32_t& r1, uint32_t addr) {
    asm volatile("ldmatrix.sync.aligned.m8n8.x2.shared.b16 {%0,%1}, [%2];"
                 : "=r"(r0), "=r"(r1) : "r"(addr));
}
__device__ __forceinline__ void ldmx4t(uint32_t& r0, uint32_t& r1, uint32_t& r2,
                                       uint32_t& r3, uint32_t addr) {
    asm volatile("ldmatrix.sync.aligned.m8n8.x4.trans.shared.b16 {%0,%1,%2,%3}, [%4];"
                 : "=r"(r0), "=r"(r1), "=r"(r2), "=r"(r3) : "r"(addr));
}
__device__ __forceinline__ void mma_bf16(float& d0, float& d1, float& d2, float& d3,
                                         uint32_t a0, uint32_t a1, uint32_t a2,
                                         uint32_t a3, uint32_t b0, uint32_t b1) {
    asm volatile(
        "mma.sync.aligned.m16n8k16.row.col.f32.bf16.bf16.f32 "
        "{%0,%1,%2,%3}, {%4,%5,%6,%7}, {%8,%9}, {%0,%1,%2,%3};"
        : "+f"(d0), "+f"(d1), "+f"(d2), "+f"(d3)
        : "r"(a0), "r"(a1), "r"(a2), "r"(a3), "r"(b0), "r"(b1));
}
__device__ __forceinline__ void cp16(uint32_t dst, const void* src) {
    asm volatile("cp.async.cg.shared.global [%0], [%1], 16;"
                 :: "r"(dst), "l"(src));
}
__device__ __forceinline__ void cp_commit() {
    asm volatile("cp.async.commit_group;" ::: "memory");
}
template <int N>
__device__ __forceinline__ void cp_wait() {
    asm volatile("cp.async.wait_group %0;" :: "n"(N) : "memory");
}

__device__ __forceinline__ void split1(float x, __nv_bfloat16& h, __nv_bfloat16& l) {
    h = __float2bfloat16(x);
    l = __float2bfloat16(x - __bfloat162float(h));
}
__device__ __forceinline__ uint32_t packbf(__nv_bfloat16 a, __nv_bfloat16 b) {
    __nv_bfloat162 t(a, b);
    return *(uint32_t*)&t;
}

// ---------------------------------------------------------------------------
// fp32 -> bf16 hi/lo split (elementwise)
// ---------------------------------------------------------------------------
__global__ __launch_bounds__(256)
void convert_split(const float* __restrict__ in, __nv_bfloat16* __restrict__ hi,
                   __nv_bfloat16* __restrict__ lo, int n4)
{
    int i = blockIdx.x * blockDim.x + threadIdx.x;
    if (i >= n4) return;
    float4 v = ((const float4*)in)[i];
    __nv_bfloat16 h0, l0, h1, l1, h2, l2, h3, l3;
    split1(v.x, h0, l0); split1(v.y, h1, l1);
    split1(v.z, h2, l2); split1(v.w, h3, l3);
    ((__nv_bfloat162*)hi)[2 * i + 0] = __nv_bfloat162(h0, h1);
    ((__nv_bfloat162*)hi)[2 * i + 1] = __nv_bfloat162(h2, h3);
    ((__nv_bfloat162*)lo)[2 * i + 0] = __nv_bfloat162(l0, l1);
    ((__nv_bfloat162*)lo)[2 * i + 1] = __nv_bfloat162(l2, l3);
}

// ---------------------------------------------------------------------------
// All four W [K,N] fp32 -> transposed hi/lo bf16 [N,K] in one launch (z=4)
// ---------------------------------------------------------------------------
__global__ __launch_bounds__(256)
void transpose_split4(const float* __restrict__ W0, const float* __restrict__ W1,
                      const float* __restrict__ W2, const float* __restrict__ W3,
                      __nv_bfloat16* __restrict__ T0h, __nv_bfloat16* __restrict__ T0l,
                      __nv_bfloat16* __restrict__ T1h, __nv_bfloat16* __restrict__ T1l,
                      __nv_bfloat16* __restrict__ T2h, __nv_bfloat16* __restrict__ T2l,
                      __nv_bfloat16* __restrict__ T3h, __nv_bfloat16* __restrict__ T3l)
{
    __shared__ float t[32][33];
    const int z = blockIdx.z;
    const float* W = (z == 0) ? W0 : (z == 1) ? W1 : (z == 2) ? W2 : W3;
    __nv_bfloat16* Th = (z == 0) ? T0h : (z == 1) ? T1h : (z == 2) ? T2h : T3h;
    __nv_bfloat16* Tl = (z == 0) ? T0l : (z == 1) ? T1l : (z == 2) ? T2l : T3l;

    const int n0 = blockIdx.x * 32, k0 = blockIdx.y * 32;
    const int tx = threadIdx.x, ty = threadIdx.y;
#pragma unroll
    for (int i = 0; i < 32; i += 8)
        t[ty + i][tx] = W[(size_t)(k0 + ty + i) * HID + n0 + tx];
    __syncthreads();
#pragma unroll
    for (int i = 0; i < 32; i += 8) {
        float x = t[tx][ty + i];
        __nv_bfloat16 h, l; split1(x, h, l);
        Th[(size_t)(n0 + ty + i) * HID + k0 + tx] = h;
        Tl[(size_t)(n0 + ty + i) * HID + k0 + tx] = l;
    }
}

// ---------------------------------------------------------------------------
// GEMM mainloop shared constants
// ---------------------------------------------------------------------------
#define PIPE 3
#define STAGE_BYTES 32768
#define GEMM_SMEM   (PIPE * STAGE_BYTES)
#define NKC  (HID / 32)

// ---------------------------------------------------------------------------
// Merged QKV projection: grid (24, 32). blockIdx.x>>3 selects Q/K/V.
// All outputs single bf16 (2-term: Ahi*(Bhi+Blo)). Q pre-scaled by 1/8.
// ---------------------------------------------------------------------------
__global__ __launch_bounds__(256, 2)
void gemm_qkv(const __nv_bfloat16* __restrict__ Ahi,
              const __nv_bfloat16* __restrict__ Bqh, const __nv_bfloat16* __restrict__ Bql,
              const __nv_bfloat16* __restrict__ Bkh, const __nv_bfloat16* __restrict__ Bkl,
              const __nv_bfloat16* __restrict__ Bvh, const __nv_bfloat16* __restrict__ Bvl,
              const float* __restrict__ bq, const float* __restrict__ bk,
              const float* __restrict__ bv,
              __nv_bfloat16* __restrict__ Qh,
              __nv_bfloat16* __restrict__ Kh,
              __nv_bfloat16* __restrict__ Vb)
{
    extern __shared__ char smc[];
    const uint32_t sbase = smem_u32(smc);

    const int sel = blockIdx.x >> 3;
    const __nv_bfloat16* Bhi = (sel == 0) ? Bqh : (sel == 1) ? Bkh : Bvh;
    const __nv_bfloat16* Blo = (sel == 0) ? Bql : (sel == 1) ? Bkl : Bvl;
    const float* bias = (sel == 0) ? bq : (sel == 1) ? bk : bv;
    __nv_bfloat16* Ch = (sel == 0) ? Qh : (sel == 1) ? Kh : Vb;

    const int tid  = threadIdx.x;
    const int lane = tid & 31;
    const int warp = tid >> 5;
    const int wm   = (warp >> 2) * 64;
    const int wn   = (warp & 3) * 32;
    const int m0 = blockIdx.y * 128, n0 = (blockIdx.x & 7) * 128;

    // Per stage: A hi (16K used: rows x 128B with hi in chunks 0-3, A-lo slot
    // unused -> we keep layout with A hi only in 8K? simpler: keep same layout,
    // load A hi twice region). Simpler: A tile 8 chunks = hi(4) + unused -> we
    // compact: A hi 4 chunks/row (64 B/row). To keep the swizzle identical we
    // retain the 128B row with chunks 0-3 = Ahi and 4-7 = Bhi? No -- keep
    // original layout but only A-hi + B-hi/lo: tile0 chunks0-3 Ahi, chunks4-7
    // Bhi ; tile1 chunks0-3 Blo, chunks4-7 unused-dup(Blo).
    auto load_stage = [&](int stage, int kc) {
        const uint32_t sb = sbase + stage * STAGE_BYTES;
#pragma unroll
        for (int t = 0; t < 8; t++) {
            int idx  = tid + t * 256;
            int tile = idx >> 10;
            int r    = (idx >> 3) & 127;
            int c    = idx & 7;
            const __nv_bfloat16* src;
            if (tile == 0)
                src = (c < 4 ? Ahi : Bhi) + (size_t)(((c < 4) ? m0 : n0) + r) * HID
                      + kc * 32 + (c & 3) * 8;
            else
                src = Blo + (size_t)(n0 + r) * HID + kc * 32 + (c & 3) * 8;
            uint32_t dst = sb + (uint32_t)(tile * 16384 + r * 128 + ((c ^ (r & 7)) * 16));
            cp16(dst, src);
        }
        cp_commit();
    };

    float acc[4][4][4];
#pragma unroll
    for (int mi = 0; mi < 4; mi++)
#pragma unroll
        for (int nj = 0; nj < 4; nj++)
#pragma unroll
            for (int e = 0; e < 4; e++) acc[mi][nj][e] = 0.f;

    load_stage(0, 0);
    load_stage(1, 1);

    for (int kc = 0; kc < NKC; kc++) {
        cp_wait<PIPE - 2>();
        __syncthreads();
        if (kc + 2 < NKC) load_stage((kc + 2) % PIPE, kc + 2);

        const uint32_t sT0 = sbase + (kc % PIPE) * STAGE_BYTES;   // Ahi | Bhi
        const uint32_t sT1 = sT0 + 16384;                          // Blo

#pragma unroll
        for (int ks = 0; ks < 2; ks++) {
            uint32_t bh[4][2], bl[4][2];
#pragma unroll
            for (int nj = 0; nj < 4; nj++) {
                int r  = wn + nj * 8 + (lane & 7);
                int cc = ks * 2 + ((lane >> 3) & 1);
                ldmx2(bh[nj][0], bh[nj][1],
                      sT0 + (uint32_t)(r * 128 + (((cc + 4) ^ (r & 7)) * 16)));
                ldmx2(bl[nj][0], bl[nj][1],
                      sT1 + (uint32_t)(r * 128 + ((cc ^ (r & 7)) * 16)));
            }
#pragma unroll
            for (int mi = 0; mi < 4; mi++) {
                int r  = wm + mi * 16 + (lane & 15);
                int cc = ks * 2 + (lane >> 4);
                uint32_t ah0, ah1, ah2, ah3;
                ldmx4(ah0, ah1, ah2, ah3,
                      sT0 + (uint32_t)(r * 128 + ((cc ^ (r & 7)) * 16)));
#pragma unroll
                for (int nj = 0; nj < 4; nj++) {
                    mma_bf16(acc[mi][nj][0], acc[mi][nj][1], acc[mi][nj][2], acc[mi][nj][3],
                             ah0, ah1, ah2, ah3, bh[nj][0], bh[nj][1]);
                    mma_bf16(acc[mi][nj][0], acc[mi][nj][1], acc[mi][nj][2], acc[mi][nj][3],
                             ah0, ah1, ah2, ah3, bl[nj][0], bl[nj][1]);
                }
            }
        }
    }

    const float oscale = (sel == 0) ? 0.125f : 1.0f;   // fold 1/sqrt(64) into Q
#pragma unroll
    for (int mi = 0; mi < 4; mi++) {
#pragma unroll
        for (int nj = 0; nj < 4; nj++) {
            int row = m0 + wm + mi * 16 + (lane >> 2);
            int col = n0 + wn + nj * 8 + 2 * (lane & 3);
            float b0 = bias[col], b1 = bias[col + 1];
            float v00 = (acc[mi][nj][0] + b0) * oscale, v01 = (acc[mi][nj][1] + b1) * oscale;
            float v10 = (acc[mi][nj][2] + b0) * oscale, v11 = (acc[mi][nj][3] + b1) * oscale;
            *(__nv_bfloat162*)&Ch[(size_t)row * HID + col] =
                __nv_bfloat162(__float2bfloat16(v00), __float2bfloat16(v01));
            *(__nv_bfloat162*)&Ch[(size_t)(row + 8) * HID + col] =
                __nv_bfloat162(__float2bfloat16(v10), __float2bfloat16(v11));
        }
    }
}

// ---------------------------------------------------------------------------
// Output projection GEMM (fp32 out + residual, 3-term split A and B)
// ---------------------------------------------------------------------------
__global__ __launch_bounds__(256, 2)
void gemm_out(const __nv_bfloat16* __restrict__ Ahi, const __nv_bfloat16* __restrict__ Alo,
              const __nv_bfloat16* __restrict__ Bhi, const __nv_bfloat16* __restrict__ Blo,
              const float* __restrict__ bias, const float* __restrict__ res,
              float* __restrict__ Cf)
{
    extern __shared__ char smc[];
    const uint32_t sbase = smem_u32(smc);

    const int tid  = threadIdx.x;
    const int lane = tid & 31;
    const int warp = tid >> 5;
    const int wm   = (warp >> 2) * 64;
    const int wn   = (warp & 3) * 32;
    const int m0 = blockIdx.y * 128, n0 = blockIdx.x * 128;

    auto load_stage = [&](int stage, int kc) {
        const uint32_t sb = sbase + stage * STAGE_BYTES;
#pragma unroll
        for (int t = 0; t < 8; t++) {
            int idx  = tid + t * 256;
            int tile = idx >> 10;
            int r    = (idx >> 3) & 127;
            int c    = idx & 7;
            const __nv_bfloat16* src;
            if (tile == 0)
                src = (c < 4 ? Ahi : Alo) + (size_t)(m0 + r) * HID + kc * 32 + (c & 3) * 8;
            else
                src = (c < 4 ? Bhi : Blo) + (size_t)(n0 + r) * HID + kc * 32 + (c & 3) * 8;
            uint32_t dst = sb + (uint32_t)(tile * 16384 + r * 128 + ((c ^ (r & 7)) * 16));
            cp16(dst, src);
        }
        cp_commit();
    };

    float acc[4][4][4];
#pragma unroll
    for (int mi = 0; mi < 4; mi++)
#pragma unroll
        for (int nj = 0; nj < 4; nj++)
#pragma unroll
            for (int e = 0; e < 4; e++) acc[mi][nj][e] = 0.f;

    load_stage(0, 0);
    load_stage(1, 1);

    for (int kc = 0; kc < NKC; kc++) {
        cp_wait<PIPE - 2>();
        __syncthreads();
        if (kc + 2 < NKC) load_stage((kc + 2) % PIPE, kc + 2);

        const uint32_t sA = sbase + (kc % PIPE) * STAGE_BYTES;
        const uint32_t sB = sA + 16384;

#pragma unroll
        for (int ks = 0; ks < 2; ks++) {
            uint32_t bh[4][2], bl[4][2];
#pragma unroll
            for (int nj = 0; nj < 4; nj++) {
                int r  = wn + nj * 8 + (lane & 7);
                int cc = ks * 2 + ((lane >> 3) & 1);
                ldmx2(bh[nj][0], bh[nj][1],
                      sB + (uint32_t)(r * 128 + ((cc ^ (r & 7)) * 16)));
                ldmx2(bl[nj][0], bl[nj][1],
                      sB + (uint32_t)(r * 128 + (((cc + 4) ^ (r & 7)) * 16)));
            }
#pragma unroll
            for (int mi = 0; mi < 4; mi++) {
                int r  = wm + mi * 16 + (lane & 15);
                int cc = ks * 2 + (lane >> 4);
                uint32_t ah0, ah1, ah2, ah3, al0, al1, al2, al3;
                ldmx4(ah0, ah1, ah2, ah3,
                      sA + (uint32_t)(r * 128 + ((cc ^ (r & 7)) * 16)));
                ldmx4(al0, al1, al2, al3,
                      sA + (uint32_t)(r * 128 + (((cc + 4) ^ (r & 7)) * 16)));
#pragma unroll
                for (int nj = 0; nj < 4; nj++) {
                    mma_bf16(acc[mi][nj][0], acc[mi][nj][1], acc[mi][nj][2], acc[mi][nj][3],
                             ah0, ah1, ah2, ah3, bh[nj][0], bh[nj][1]);
                    mma_bf16(acc[mi][nj][0], acc[mi][nj][1], acc[mi][nj][2], acc[mi][nj][3],
                             ah0, ah1, ah2, ah3, bl[nj][0], bl[nj][1]);
                    mma_bf16(acc[mi][nj][0], acc[mi][nj][1], acc[mi][nj][2], acc[mi][nj][3],
                             al0, al1, al2, al3, bh[nj][0], bh[nj][1]);
                }
            }
        }
    }

#pragma unroll
    for (int mi = 0; mi < 4; mi++) {
#pragma unroll
        for (int nj = 0; nj < 4; nj++) {
            int row = m0 + wm + mi * 16 + (lane >> 2);
            int col = n0 + wn + nj * 8 + 2 * (lane & 3);
            float b0 = bias[col], b1 = bias[col + 1];
            float v00 = acc[mi][nj][0] + b0, v01 = acc[mi][nj][1] + b1;
            float v10 = acc[mi][nj][2] + b0, v11 = acc[mi][nj][3] + b1;
            float2 r0 = *(const float2*)&res[(size_t)row * HID + col];
            float2 r1 = *(const float2*)&res[(size_t)(row + 8) * HID + col];
            v00 += r0.x; v01 += r0.y; v10 += r1.x; v11 += r1.y;
            *(float2*)&Cf[(size_t)row * HID + col] = make_float2(v00, v01);
            *(float2*)&Cf[(size_t)(row + 8) * HID + col] = make_float2(v10, v11);
        }
    }
}

// ---------------------------------------------------------------------------
// Flash attention via mma.sync (all-bf16 scores):
//   S = Qh*Kh (Q pre-scaled by 1/8); softmax in fragments; O += P_hi * V.
//   K-tile 64, 2 CTAs/SM, paired ldmatrix.x4 loads.
// ---------------------------------------------------------------------------
#define ASTAGE 16384                           // Kh 8K + V 8K
#define ATT_SMEM (16384 + 2 * ASTAGE)          // + Qhi 16K = 48K

__global__ __launch_bounds__(256, 2)
void flash_mma(const __nv_bfloat16* __restrict__ Qh,
               const __nv_bfloat16* __restrict__ Kh,
               const __nv_bfloat16* __restrict__ Vb,
               __nv_bfloat16* __restrict__ Ch, __nv_bfloat16* __restrict__ Cl)
{
    extern __shared__ char sma[];
    const uint32_t sQ = smem_u32(sma);        // Qhi 16K
    const uint32_t sS = sQ + 16384;           // 2 stages of {Kh 8K, V 8K}

    const int tid = threadIdx.x, lane = tid & 31, warp = tid >> 5;
    const int q0 = blockIdx.x * 128;
    const int h = blockIdx.y, b = blockIdx.z;
    const size_t gb = (size_t)b * SEQ * HID + (size_t)h * HDIM;

    // Q hi tile -> smem (swizzled, 128 rows x 128 B)
#pragma unroll
    for (int t = 0; t < 4; t++) {
        int idx = tid + t * 256;               // 0..1023
        int r = idx >> 3, c = idx & 7;
        const __nv_bfloat16* src = Qh + gb + (size_t)(q0 + r) * HID + c * 8;
        cp16(sQ + (uint32_t)(r * 128 + ((c ^ (r & 7)) * 16)), src);
    }
    cp_commit();

    auto loadKV = [&](int stage, int kt) {     // kt indexes 64-row K tiles
        const uint32_t sb = sS + stage * ASTAGE;
#pragma unroll
        for (int t = 0; t < 4; t++) {
            int idx = tid + t * 256;           // 0..1023
            int tile = idx >> 9;               // 0=Kh 1=V (512 slots each)
            int r = (idx >> 3) & 63, c = idx & 7;
            const __nv_bfloat16* src =
                (tile == 0 ? Kh : Vb) + gb + (size_t)(kt * 64 + r) * HID + c * 8;
            cp16(sb + (uint32_t)(tile * 8192 + r * 128 + ((c ^ (r & 7)) * 16)), src);
        }
        cp_commit();
    };
    loadKV(0, 0);
    loadKV(1, 1);

    cp_wait<2>();          // Q resident
    __syncthreads();

    // Q fragments (registers, whole kernel)
    const int wq = warp * 16;
    uint32_t qh[4][4];
#pragma unroll
    for (int dc = 0; dc < 4; dc++) {
        int r = wq + (lane & 15);
        int cc = dc * 2 + (lane >> 4);
        ldmx4(qh[dc][0], qh[dc][1], qh[dc][2], qh[dc][3],
              sQ + (uint32_t)(r * 128 + ((cc ^ (r & 7)) * 16)));
    }

    float m0 = -1e30f, m1 = -1e30f, l0 = 0.f, l1 = 0.f;
    float o[8][4];
#pragma unroll
    for (int dj = 0; dj < 8; dj++)
#pragma unroll
        for (int e = 0; e < 4; e++) o[dj][e] = 0.f;

    for (int kt = 0; kt < SEQ / 64; kt++) {
        cp_wait<1>();
        __syncthreads();
        const uint32_t sK = sS + (kt & 1) * ASTAGE;
        const uint32_t sV = sK + 8192;

        // ---- S = Q K^T (single-term, Q pre-scaled) ----
        float s[8][4];
#pragma unroll
        for (int nj = 0; nj < 8; nj++)
#pragma unroll
            for (int e = 0; e < 4; e++) s[nj][e] = 0.f;

#pragma unroll
        for (int np = 0; np < 4; np++) {       // pair of n-tiles (2np, 2np+1)
            int r = (np * 2 + (lane >> 4)) * 8 + (lane & 7);
#pragma unroll
            for (int dc = 0; dc < 4; dc++) {
                int cc = dc * 2 + ((lane >> 3) & 1);
                uint32_t off = (uint32_t)(r * 128 + ((cc ^ (r & 7)) * 16));
                uint32_t h0, h1, h2, h3;
                ldmx4(h0, h1, h2, h3, sK + off);
                mma_bf16(s[2*np][0], s[2*np][1], s[2*np][2], s[2*np][3],
                         qh[dc][0], qh[dc][1], qh[dc][2], qh[dc][3], h0, h1);
                mma_bf16(s[2*np+1][0], s[2*np+1][1], s[2*np+1][2], s[2*np+1][3],
                         qh[dc][0], qh[dc][1], qh[dc][2], qh[dc][3], h2, h3);
            }
        }

        // ---- online softmax on fragments ----
        float mx0 = -1e30f, mx1 = -1e30f;
#pragma unroll
        for (int nj = 0; nj < 8; nj++) {
            mx0 = fmaxf(mx0, fmaxf(s[nj][0], s[nj][1]));
            mx1 = fmaxf(mx1, fmaxf(s[nj][2], s[nj][3]));
        }
        mx0 = fmaxf(mx0, __shfl_xor_sync(0xffffffffu, mx0, 1));
        mx0 = fmaxf(mx0, __shfl_xor_sync(0xffffffffu, mx0, 2));
        mx1 = fmaxf(mx1, __shfl_xor_sync(0xffffffffu, mx1, 1));
        mx1 = fmaxf(mx1, __shfl_xor_sync(0xffffffffu, mx1, 2));
        float mn0 = fmaxf(m0, mx0), mn1 = fmaxf(m1, mx1);
        float a0 = __expf(m0 - mn0), a1 = __expf(m1 - mn1);
        float sum0 = 0.f, sum1 = 0.f;
#pragma unroll
        for (int nj = 0; nj < 8; nj++) {
            s[nj][0] = __expf(s[nj][0] - mn0);
            s[nj][1] = __expf(s[nj][1] - mn0);
            s[nj][2] = __expf(s[nj][2] - mn1);
            s[nj][3] = __expf(s[nj][3] - mn1);
            sum0 += s[nj][0] + s[nj][1];
            sum1 += s[nj][2] + s[nj][3];
        }
        sum0 += __shfl_xor_sync(0xffffffffu, sum0, 1);
        sum0 += __shfl_xor_sync(0xffffffffu, sum0, 2);
        sum1 += __shfl_xor_sync(0xffffffffu, sum1, 1);
        sum1 += __shfl_xor_sync(0xffffffffu, sum1, 2);
        l0 = l0 * a0 + sum0; l1 = l1 * a1 + sum1;
        m0 = mn0; m1 = mn1;
#pragma unroll
        for (int dj = 0; dj < 8; dj++) {
            o[dj][0] *= a0; o[dj][1] *= a0; o[dj][2] *= a1; o[dj][3] *= a1;
        }

        // ---- O += P V (P single bf16; paired d-tiles via ldmatrix.x4.trans) ----
#pragma unroll
        for (int kc = 0; kc < 4; kc++) {
            uint32_t A0 = packbf(__float2bfloat16(s[2 * kc][0]),
                                 __float2bfloat16(s[2 * kc][1]));
            uint32_t A1 = packbf(__float2bfloat16(s[2 * kc][2]),
                                 __float2bfloat16(s[2 * kc][3]));
            uint32_t A2 = packbf(__float2bfloat16(s[2 * kc + 1][0]),
                                 __float2bfloat16(s[2 * kc + 1][1]));
            uint32_t A3 = packbf(__float2bfloat16(s[2 * kc + 1][2]),
                                 __float2bfloat16(s[2 * kc + 1][3]));
            int r = kc * 16 + (lane & 15);
#pragma unroll
            for (int dp = 0; dp < 4; dp++) {   // pair of d-tiles (2dp, 2dp+1)
                int c = dp * 2 + (lane >> 4);
                uint32_t addr = sV + (uint32_t)(r * 128 + ((c ^ (r & 7)) * 16));
                uint32_t b0, b1, b2, b3;
                ldmx4t(b0, b1, b2, b3, addr);
                mma_bf16(o[2*dp][0], o[2*dp][1], o[2*dp][2], o[2*dp][3],
                         A0, A1, A2, A3, b0, b1);
                mma_bf16(o[2*dp+1][0], o[2*dp+1][1], o[2*dp+1][2], o[2*dp+1][3],
                         A0, A1, A2, A3, b2, b3);
            }
        }

        __syncthreads();
        if (kt + 2 < SEQ / 64) loadKV(kt & 1, kt + 2);
    }

    // ---- epilogue: normalize, split hi/lo, store ctx ----
    float i0 = 1.f / l0, i1 = 1.f / l1;
    int r0 = q0 + wq + (lane >> 2);
    int cb = 2 * (lane & 3);
#pragma unroll
    for (int dj = 0; dj < 8; dj++) {
        int col = dj * 8 + cb;
        float v00 = o[dj][0] * i0, v01 = o[dj][1] * i0;
        float v10 = o[dj][2] * i1, v11 = o[dj][3] * i1;
        __nv_bfloat16 h00, l00, h01, l01, h10, l10, h11, l11;
        split1(v00, h00, l00); split1(v01, h01, l01);
        split1(v10, h10, l10); split1(v11, h11, l11);
        *(__nv_bfloat162*)&Ch[gb + (size_t)r0 * HID + col] = __nv_bfloat162(h00, h01);
        *(__nv_bfloat162*)&Ch[gb + (size_t)(r0 + 8) * HID + col] = __nv_bfloat162(h10, h11);
        *(__nv_bfloat162*)&Cl[gb + (size_t)r0 * HID + col] = __nv_bfloat162(l00, l01);
        *(__nv_bfloat162*)&Cl[gb + (size_t)(r0 + 8) * HID + col] = __nv_bfloat162(l10, l11);
    }
}

// ---------------------------------------------------------------------------
// LayerNorm: one block per row of 1024
// ---------------------------------------------------------------------------
__global__ __launch_bounds__(256)
void layernorm_kernel(const float* __restrict__ X, const float* __restrict__ gamma,
                      const float* __restrict__ beta, float* __restrict__ out)
{
    __shared__ float red[2][8];
    const int row = blockIdx.x;
    const int tid = threadIdx.x;
    const float* x = X + (size_t)row * HID;

    float4 v = *(const float4*)&x[tid * 4];
    float s  = v.x + v.y + v.z + v.w;
    float ss = v.x * v.x + v.y * v.y + v.z * v.z + v.w * v.w;
#pragma unroll
    for (int o = 16; o > 0; o >>= 1) {
        s  += __shfl_xor_sync(0xffffffffu, s, o);
        ss += __shfl_xor_sync(0xffffffffu, ss, o);
    }
    const int w = tid >> 5, l = tid & 31;
    if (l == 0) { red[0][w] = s; red[1][w] = ss; }
    __syncthreads();
    if (w == 0) {
        float s2  = (l < 8) ? red[0][l] : 0.f;
        float ss2 = (l < 8) ? red[1][l] : 0.f;
#pragma unroll
        for (int o = 4; o > 0; o >>= 1) {
            s2  += __shfl_xor_sync(0xffffffffu, s2, o);
            ss2 += __shfl_xor_sync(0xffffffffu, ss2, o);
        }
        if (l == 0) { red[0][0] = s2; red[1][0] = ss2; }
    }
    __syncthreads();

    const float mean = red[0][0] * (1.f / HID);
    const float var  = red[1][0] * (1.f / HID) - mean * mean;
    const float rstd = rsqrtf(var + 1e-5f);

    const int c = tid * 4;
    float4 gv = *(const float4*)&gamma[c];
    float4 bv = *(const float4*)&beta[c];
    float4 o;
    o.x = (v.x - mean) * rstd * gv.x + bv.x;
    o.y = (v.y - mean) * rstd * gv.y + bv.y;
    o.z = (v.z - mean) * rstd * gv.z + bv.z;
    o.w = (v.w - mean) * rstd * gv.w + bv.w;
    *(float4*)&out[(size_t)row * HID + c] = o;
}

// ---------------------------------------------------------------------------
// Launch
// ---------------------------------------------------------------------------
extern "C" void kernel_launch(void* const* d_in, const int* in_sizes, int n_in,
                              void* d_out, int out_size)
{
    const float* hidden = (const float*)d_in[0];
    const float* Wq = (const float*)d_in[1];
    const float* bq = (const float*)d_in[2];
    const float* Wk = (const float*)d_in[3];
    const float* bk = (const float*)d_in[4];
    const float* Wv = (const float*)d_in[5];
    const float* bv = (const float*)d_in[6];
    const float* Wo = (const float*)d_in[7];
    const float* bo = (const float*)d_in[8];
    const float* gamma = (const float*)d_in[9];
    const float* beta  = (const float*)d_in[10];
    float* out = (float*)d_out;

    float* x;
    cudaGetSymbolAddress((void**)&x, g_X);

    __nv_bfloat16 *hhi, *hlo, *chi, *clo, *qhp, *khp, *vbp;
    __nv_bfloat16 *wqh, *wql, *wkh, *wkl, *wvh, *wvl, *woh, *wol;
    cudaGetSymbolAddress((void**)&hhi, g_Hhi);
    cudaGetSymbolAddress((void**)&hlo, g_Hlo);
    cudaGetSymbolAddress((void**)&chi, g_Chi);
    cudaGetSymbolAddress((void**)&clo, g_Clo);
    cudaGetSymbolAddress((void**)&qhp, g_Qh);
    cudaGetSymbolAddress((void**)&khp, g_Kh);
    cudaGetSymbolAddress((void**)&vbp, g_Vb);
    cudaGetSymbolAddress((void**)&wqh, g_WqTh);
    cudaGetSymbolAddress((void**)&wql, g_WqTl);
    cudaGetSymbolAddress((void**)&wkh, g_WkTh);
    cudaGetSymbolAddress((void**)&wkl, g_WkTl);
    cudaGetSymbolAddress((void**)&wvh, g_WvTh);
    cudaGetSymbolAddress((void**)&wvl, g_WvTl);
    cudaGetSymbolAddress((void**)&woh, g_WoTh);
    cudaGetSymbolAddress((void**)&wol, g_WoTl);

    // ---- prep ----
    convert_split<<<(ROWS * HID / 4 + 255) / 256, 256>>>(hidden, hhi, hlo, ROWS * HID / 4);
    dim3 tg(HID / 32, HID / 32, 4), tb(32, 8);
    transpose_split4<<<tg, tb>>>(Wq, Wk, Wv, Wo,
                                 wqh, wql, wkh, wkl, wvh, wvl, woh, wol);

    // ---- merged QKV projection (2-term, bf16 outputs) ----
    cudaFuncSetAttribute(gemm_qkv, cudaFuncAttributeMaxDynamicSharedMemorySize, GEMM_SMEM);
    cudaFuncSetAttribute(gemm_out, cudaFuncAttributeMaxDynamicSharedMemorySize, GEMM_SMEM);
    gemm_qkv<<<dim3(24, ROWS / 128), 256, GEMM_SMEM>>>(
        hhi, wqh, wql, wkh, wkl, wvh, wvl, bq, bk, bv,
        qhp, khp, vbp);

    // ---- attention (tensor core, 2 CTAs/SM, all-bf16 scores) ----
    cudaFuncSetAttribute(flash_mma, cudaFuncAttributeMaxDynamicSharedMemorySize, ATT_SMEM);
    flash_mma<<<dim3(SEQ / 128, HEADS, BATCH), 256, ATT_SMEM>>>(qhp, khp, vbp,
                                                                chi, clo);

    // ---- output projection + residual ----
    gemm_out<<<dim3(HID / 128, ROWS / 128), 256, GEMM_SMEM>>>(chi, clo, woh, wol, bo,
                                                              hidden, x);

    // ---- layernorm ----
    layernorm_kernel<<<ROWS, 256>>>(x, gamma, beta, out);
}

// round 11
// speedup vs baseline: 6.1914x; 1.0850x over previous
#include <cuda_runtime.h>
#include <cuda_bf16.h>
#include <math.h>
#include <stdint.h>

// ---------------------------------------------------------------------------
// Problem constants
// ---------------------------------------------------------------------------
#define BATCH   2
#define SEQ     2048
#define HID     1024
#define HEADS   16
#define HDIM    64
#define ROWS    (BATCH * SEQ)          // 4096

// ---------------------------------------------------------------------------
// Scratch (static device globals -- no runtime allocation)
// ---------------------------------------------------------------------------
__device__ float g_X[ROWS * HID];

__device__ __nv_bfloat16 g_Hhi[ROWS * HID];
__device__ __nv_bfloat16 g_Qh[ROWS * HID];
__device__ __nv_bfloat16 g_Kh[ROWS * HID];
__device__ __nv_bfloat16 g_Vb[ROWS * HID];
__device__ __nv_bfloat16 g_Ctx[ROWS * HID];
__device__ __nv_bfloat16 g_WqTh[HID * HID];
__device__ __nv_bfloat16 g_WqTl[HID * HID];
__device__ __nv_bfloat16 g_WkTh[HID * HID];
__device__ __nv_bfloat16 g_WkTl[HID * HID];
__device__ __nv_bfloat16 g_WvTh[HID * HID];
__device__ __nv_bfloat16 g_WvTl[HID * HID];
__device__ __nv_bfloat16 g_WoTh[HID * HID];
__device__ __nv_bfloat16 g_WoTl[HID * HID];

// ---------------------------------------------------------------------------
// PTX helpers
// ---------------------------------------------------------------------------
__device__ __forceinline__ uint32_t smem_u32(const void* p) {
    uint32_t a;
    asm("{ .reg .u64 t; cvta.to.shared.u64 t, %1; cvt.u32.u64 %0, t; }"
        : "=r"(a) : "l"(p));
    return a;
}
__device__ __forceinline__ void ldmx4(uint32_t& r0, uint32_t& r1, uint32_t& r2,
                                      uint32_t& r3, uint32_t addr) {
    asm volatile("ldmatrix.sync.aligned.m8n8.x4.shared.b16 {%0,%1,%2,%3}, [%4];"
                 : "=r"(r0), "=r"(r1), "=r"(r2), "=r"(r3) : "r"(addr));
}
__device__ __forceinline__ void ldmx2(uint32_t& r0, uint32_t& r1, uint32_t addr) {
    asm volatile("ldmatrix.sync.aligned.m8n8.x2.shared.b16 {%0,%1}, [%2];"
                 : "=r"(r0), "=r"(r1) : "r"(addr));
}
__device__ __forceinline__ void ldmx4t(uint32_t& r0, uint32_t& r1, uint32_t& r2,
                                       uint32_t& r3, uint32_t addr) {
    asm volatile("ldmatrix.sync.aligned.m8n8.x4.trans.shared.b16 {%0,%1,%2,%3}, [%4];"
                 : "=r"(r0), "=r"(r1), "=r"(r2), "=r"(r3) : "r"(addr));
}
__device__ __forceinline__ void mma_bf16(float& d0, float& d1, float& d2, float& d3,
                                         uint32_t a0, uint32_t a1, uint32_t a2,
                                         uint32_t a3, uint32_t b0, uint32_t b1) {
    asm volatile(
        "mma.sync.aligned.m16n8k16.row.col.f32.bf16.bf16.f32 "
        "{%0,%1,%2,%3}, {%4,%5,%6,%7}, {%8,%9}, {%0,%1,%2,%3};"
        : "+f"(d0), "+f"(d1), "+f"(d2), "+f"(d3)
        : "r"(a0), "r"(a1), "r"(a2), "r"(a3), "r"(b0), "r"(b1));
}
__device__ __forceinline__ void cp16(uint32_t dst, const void* src) {
    asm volatile("cp.async.cg.shared.global [%0], [%1], 16;"
                 :: "r"(dst), "l"(src));
}
__device__ __forceinline__ void cp_commit() {
    asm volatile("cp.async.commit_group;" ::: "memory");
}
template <int N>
__device__ __forceinline__ void cp_wait() {
    asm volatile("cp.async.wait_group %0;" :: "n"(N) : "memory");
}

__device__ __forceinline__ void split1(float x, __nv_bfloat16& h, __nv_bfloat16& l) {
    h = __float2bfloat16(x);
    l = __float2bfloat16(x - __bfloat162float(h));
}
__device__ __forceinline__ uint32_t packbf(__nv_bfloat16 a, __nv_bfloat16 b) {
    __nv_bfloat162 t(a, b);
    return *(uint32_t*)&t;
}

// ---------------------------------------------------------------------------
// fp32 -> bf16 (hi only)
// ---------------------------------------------------------------------------
__global__ __launch_bounds__(256)
void convert_hi(const float* __restrict__ in, __nv_bfloat16* __restrict__ hi, int n4)
{
    int i = blockIdx.x * blockDim.x + threadIdx.x;
    if (i >= n4) return;
    float4 v = ((const float4*)in)[i];
    ((__nv_bfloat162*)hi)[2 * i + 0] =
        __nv_bfloat162(__float2bfloat16(v.x), __float2bfloat16(v.y));
    ((__nv_bfloat162*)hi)[2 * i + 1] =
        __nv_bfloat162(__float2bfloat16(v.z), __float2bfloat16(v.w));
}

// ---------------------------------------------------------------------------
// All four W [K,N] fp32 -> transposed hi/lo bf16 [N,K] in one launch (z=4)
// ---------------------------------------------------------------------------
__global__ __launch_bounds__(256)
void transpose_split4(const float* __restrict__ W0, const float* __restrict__ W1,
                      const float* __restrict__ W2, const float* __restrict__ W3,
                      __nv_bfloat16* __restrict__ T0h, __nv_bfloat16* __restrict__ T0l,
                      __nv_bfloat16* __restrict__ T1h, __nv_bfloat16* __restrict__ T1l,
                      __nv_bfloat16* __restrict__ T2h, __nv_bfloat16* __restrict__ T2l,
                      __nv_bfloat16* __restrict__ T3h, __nv_bfloat16* __restrict__ T3l)
{
    __shared__ float t[32][33];
    const int z = blockIdx.z;
    const float* W = (z == 0) ? W0 : (z == 1) ? W1 : (z == 2) ? W2 : W3;
    __nv_bfloat16* Th = (z == 0) ? T0h : (z == 1) ? T1h : (z == 2) ? T2h : T3h;
    __nv_bfloat16* Tl = (z == 0) ? T0l : (z == 1) ? T1l : (z == 2) ? T2l : T3l;

    const int n0 = blockIdx.x * 32, k0 = blockIdx.y * 32;
    const int tx = threadIdx.x, ty = threadIdx.y;
#pragma unroll
    for (int i = 0; i < 32; i += 8)
        t[ty + i][tx] = W[(size_t)(k0 + ty + i) * HID + n0 + tx];
    __syncthreads();
#pragma unroll
    for (int i = 0; i < 32; i += 8) {
        float x = t[tx][ty + i];
        __nv_bfloat16 h, l; split1(x, h, l);
        Th[(size_t)(n0 + ty + i) * HID + k0 + tx] = h;
        Tl[(size_t)(n0 + ty + i) * HID + k0 + tx] = l;
    }
}

// ---------------------------------------------------------------------------
// GEMM mainloop shared constants
// ---------------------------------------------------------------------------
#define PIPE 3
#define STAGE_BYTES 32768
#define GEMM_SMEM   (PIPE * STAGE_BYTES)
#define NKC  (HID / 32)

#define LOG2E 1.44269504f

// ---------------------------------------------------------------------------
// Shared 2-term GEMM mainloop:
//   acc += Ahi*(Bhi + Blo).  Stage layout: tile0 = Ahi(c0-3)|Bhi(c4-7),
//   tile1 = Blo(c0-3). 1536 cp.asyncs per stage (6 iters).
// ---------------------------------------------------------------------------
struct GemmCtx {
    uint32_t sbase;
    const __nv_bfloat16 *Ahi, *Bhi, *Blo;
    int m0, n0, tid, lane, wm, wn;
};

__device__ __forceinline__ void gemm2_load_stage(const GemmCtx& g, int stage, int kc) {
    const uint32_t sb = g.sbase + stage * STAGE_BYTES;
#pragma unroll
    for (int t = 0; t < 6; t++) {
        int idx  = g.tid + t * 256;            // 0..1535
        int tile = idx >> 9;                   // 0=Ahi 1=Bhi 2=Blo
        int r    = (idx >> 2) & 127;
        int c    = idx & 3;
        const __nv_bfloat16* src;
        uint32_t region, cd;
        if (tile == 0)      { src = g.Ahi + (size_t)(g.m0 + r) * HID + kc * 32 + c * 8;
                              region = 0;      cd = (uint32_t)c; }
        else if (tile == 1) { src = g.Bhi + (size_t)(g.n0 + r) * HID + kc * 32 + c * 8;
                              region = 0;      cd = (uint32_t)(c + 4); }
        else                { src = g.Blo + (size_t)(g.n0 + r) * HID + kc * 32 + c * 8;
                              region = 16384;  cd = (uint32_t)c; }
        uint32_t dst = sb + region + (uint32_t)(r * 128 + ((cd ^ (r & 7)) * 16));
        cp16(dst, src);
    }
    cp_commit();
}

__device__ __forceinline__ void gemm2_mainloop(const GemmCtx& g, float acc[4][4][4]) {
    gemm2_load_stage(g, 0, 0);
    gemm2_load_stage(g, 1, 1);
    for (int kc = 0; kc < NKC; kc++) {
        cp_wait<PIPE - 2>();
        __syncthreads();
        if (kc + 2 < NKC) gemm2_load_stage(g, (kc + 2) % PIPE, kc + 2);

        const uint32_t sT0 = g.sbase + (kc % PIPE) * STAGE_BYTES;   // Ahi | Bhi
        const uint32_t sT1 = sT0 + 16384;                            // Blo

#pragma unroll
        for (int ks = 0; ks < 2; ks++) {
            uint32_t bh[4][2], bl[4][2];
#pragma unroll
            for (int nj = 0; nj < 4; nj++) {
                int r  = g.wn + nj * 8 + (g.lane & 7);
                int cc = ks * 2 + ((g.lane >> 3) & 1);
                ldmx2(bh[nj][0], bh[nj][1],
                      sT0 + (uint32_t)(r * 128 + (((cc + 4) ^ (r & 7)) * 16)));
                ldmx2(bl[nj][0], bl[nj][1],
                      sT1 + (uint32_t)(r * 128 + ((cc ^ (r & 7)) * 16)));
            }
#pragma unroll
            for (int mi = 0; mi < 4; mi++) {
                int r  = g.wm + mi * 16 + (g.lane & 15);
                int cc = ks * 2 + (g.lane >> 4);
                uint32_t ah0, ah1, ah2, ah3;
                ldmx4(ah0, ah1, ah2, ah3,
                      sT0 + (uint32_t)(r * 128 + ((cc ^ (r & 7)) * 16)));
#pragma unroll
                for (int nj = 0; nj < 4; nj++) {
                    mma_bf16(acc[mi][nj][0], acc[mi][nj][1], acc[mi][nj][2], acc[mi][nj][3],
                             ah0, ah1, ah2, ah3, bh[nj][0], bh[nj][1]);
                    mma_bf16(acc[mi][nj][0], acc[mi][nj][1], acc[mi][nj][2], acc[mi][nj][3],
                             ah0, ah1, ah2, ah3, bl[nj][0], bl[nj][1]);
                }
            }
        }
    }
}

// ---------------------------------------------------------------------------
// Merged QKV projection: grid (24, 32). blockIdx.x>>3 selects Q/K/V.
// Output single bf16; Q pre-scaled by log2(e)/8 for exp2-domain softmax.
// ---------------------------------------------------------------------------
__global__ __launch_bounds__(256, 2)
void gemm_qkv(const __nv_bfloat16* __restrict__ Ahi,
              const __nv_bfloat16* __restrict__ Bqh, const __nv_bfloat16* __restrict__ Bql,
              const __nv_bfloat16* __restrict__ Bkh, const __nv_bfloat16* __restrict__ Bkl,
              const __nv_bfloat16* __restrict__ Bvh, const __nv_bfloat16* __restrict__ Bvl,
              const float* __restrict__ bq, const float* __restrict__ bk,
              const float* __restrict__ bv,
              __nv_bfloat16* __restrict__ Qh,
              __nv_bfloat16* __restrict__ Kh,
              __nv_bfloat16* __restrict__ Vb)
{
    extern __shared__ char smc[];
    const int sel = blockIdx.x >> 3;
    const int tid = threadIdx.x, lane = tid & 31, warp = tid >> 5;

    GemmCtx g;
    g.sbase = smem_u32(smc);
    g.Ahi = Ahi;
    g.Bhi = (sel == 0) ? Bqh : (sel == 1) ? Bkh : Bvh;
    g.Blo = (sel == 0) ? Bql : (sel == 1) ? Bkl : Bvl;
    g.m0 = blockIdx.y * 128; g.n0 = (blockIdx.x & 7) * 128;
    g.tid = tid; g.lane = lane;
    g.wm = (warp >> 2) * 64; g.wn = (warp & 3) * 32;

    const float* bias = (sel == 0) ? bq : (sel == 1) ? bk : bv;
    __nv_bfloat16* Ch = (sel == 0) ? Qh : (sel == 1) ? Kh : Vb;

    float acc[4][4][4];
#pragma unroll
    for (int mi = 0; mi < 4; mi++)
#pragma unroll
        for (int nj = 0; nj < 4; nj++)
#pragma unroll
            for (int e = 0; e < 4; e++) acc[mi][nj][e] = 0.f;

    gemm2_mainloop(g, acc);

    const float oscale = (sel == 0) ? 0.125f * LOG2E : 1.0f;
#pragma unroll
    for (int mi = 0; mi < 4; mi++) {
#pragma unroll
        for (int nj = 0; nj < 4; nj++) {
            int row = g.m0 + g.wm + mi * 16 + (lane >> 2);
            int col = g.n0 + g.wn + nj * 8 + 2 * (lane & 3);
            float b0 = bias[col], b1 = bias[col + 1];
            float v00 = (acc[mi][nj][0] + b0) * oscale, v01 = (acc[mi][nj][1] + b1) * oscale;
            float v10 = (acc[mi][nj][2] + b0) * oscale, v11 = (acc[mi][nj][3] + b1) * oscale;
            *(__nv_bfloat162*)&Ch[(size_t)row * HID + col] =
                __nv_bfloat162(__float2bfloat16(v00), __float2bfloat16(v01));
            *(__nv_bfloat162*)&Ch[(size_t)(row + 8) * HID + col] =
                __nv_bfloat162(__float2bfloat16(v10), __float2bfloat16(v11));
        }
    }
}

// ---------------------------------------------------------------------------
// Output projection GEMM (ctx single bf16, 2-term; fp32 out + residual)
// ---------------------------------------------------------------------------
__global__ __launch_bounds__(256, 2)
void gemm_out(const __nv_bfloat16* __restrict__ Ctx,
              const __nv_bfloat16* __restrict__ Bhi, const __nv_bfloat16* __restrict__ Blo,
              const float* __restrict__ bias, const float* __restrict__ res,
              float* __restrict__ Cf)
{
    extern __shared__ char smc[];
    const int tid = threadIdx.x, lane = tid & 31, warp = tid >> 5;

    GemmCtx g;
    g.sbase = smem_u32(smc);
    g.Ahi = Ctx; g.Bhi = Bhi; g.Blo = Blo;
    g.m0 = blockIdx.y * 128; g.n0 = blockIdx.x * 128;
    g.tid = tid; g.lane = lane;
    g.wm = (warp >> 2) * 64; g.wn = (warp & 3) * 32;

    float acc[4][4][4];
#pragma unroll
    for (int mi = 0; mi < 4; mi++)
#pragma unroll
        for (int nj = 0; nj < 4; nj++)
#pragma unroll
            for (int e = 0; e < 4; e++) acc[mi][nj][e] = 0.f;

    gemm2_mainloop(g, acc);

#pragma unroll
    for (int mi = 0; mi < 4; mi++) {
#pragma unroll
        for (int nj = 0; nj < 4; nj++) {
            int row = g.m0 + g.wm + mi * 16 + (lane >> 2);
            int col = g.n0 + g.wn + nj * 8 + 2 * (lane & 3);
            float b0 = bias[col], b1 = bias[col + 1];
            float v00 = acc[mi][nj][0] + b0, v01 = acc[mi][nj][1] + b1;
            float v10 = acc[mi][nj][2] + b0, v11 = acc[mi][nj][3] + b1;
            float2 r0 = *(const float2*)&res[(size_t)row * HID + col];
            float2 r1 = *(const float2*)&res[(size_t)(row + 8) * HID + col];
            v00 += r0.x; v01 += r0.y; v10 += r1.x; v11 += r1.y;
            *(float2*)&Cf[(size_t)row * HID + col] = make_float2(v00, v01);
            *(float2*)&Cf[(size_t)(row + 8) * HID + col] = make_float2(v10, v11);
        }
    }
}

// ---------------------------------------------------------------------------
// Flash attention via mma.sync (all-bf16):
//   S = Qh*Kh (Q pre-scaled by log2e/8); exp2-domain online softmax;
//   O += P_hi * V. K-tile 64, 2 CTAs/SM. Output ctx single bf16.
// ---------------------------------------------------------------------------
#define ASTAGE 16384                           // Kh 8K + V 8K
#define ATT_SMEM (16384 + 2 * ASTAGE)          // + Qhi 16K = 48K

__global__ __launch_bounds__(256, 2)
void flash_mma(const __nv_bfloat16* __restrict__ Qh,
               const __nv_bfloat16* __restrict__ Kh,
               const __nv_bfloat16* __restrict__ Vb,
               __nv_bfloat16* __restrict__ Ctx)
{
    extern __shared__ char sma[];
    const uint32_t sQ = smem_u32(sma);        // Qhi 16K
    const uint32_t sS = sQ + 16384;           // 2 stages of {Kh 8K, V 8K}

    const int tid = threadIdx.x, lane = tid & 31, warp = tid >> 5;
    const int q0 = blockIdx.x * 128;
    const int h = blockIdx.y, b = blockIdx.z;
    const size_t gb = (size_t)b * SEQ * HID + (size_t)h * HDIM;

    // Q tile -> smem (swizzled, 128 rows x 128 B)
#pragma unroll
    for (int t = 0; t < 4; t++) {
        int idx = tid + t * 256;
        int r = idx >> 3, c = idx & 7;
        const __nv_bfloat16* src = Qh + gb + (size_t)(q0 + r) * HID + c * 8;
        cp16(sQ + (uint32_t)(r * 128 + ((c ^ (r & 7)) * 16)), src);
    }
    cp_commit();

    auto loadKV = [&](int stage, int kt) {
        const uint32_t sb = sS + stage * ASTAGE;
#pragma unroll
        for (int t = 0; t < 4; t++) {
            int idx = tid + t * 256;
            int tile = idx >> 9;
            int r = (idx >> 3) & 63, c = idx & 7;
            const __nv_bfloat16* src =
                (tile == 0 ? Kh : Vb) + gb + (size_t)(kt * 64 + r) * HID + c * 8;
            cp16(sb + (uint32_t)(tile * 8192 + r * 128 + ((c ^ (r & 7)) * 16)), src);
        }
        cp_commit();
    };
    loadKV(0, 0);
    loadKV(1, 1);

    cp_wait<2>();
    __syncthreads();

    const int wq = warp * 16;
    uint32_t qh[4][4];
#pragma unroll
    for (int dc = 0; dc < 4; dc++) {
        int r = wq + (lane & 15);
        int cc = dc * 2 + (lane >> 4);
        ldmx4(qh[dc][0], qh[dc][1], qh[dc][2], qh[dc][3],
              sQ + (uint32_t)(r * 128 + ((cc ^ (r & 7)) * 16)));
    }

    float m0 = -1e30f, m1 = -1e30f, l0 = 0.f, l1 = 0.f;
    float o[8][4];
#pragma unroll
    for (int dj = 0; dj < 8; dj++)
#pragma unroll
        for (int e = 0; e < 4; e++) o[dj][e] = 0.f;

    for (int kt = 0; kt < SEQ / 64; kt++) {
        cp_wait<1>();
        __syncthreads();
        const uint32_t sK = sS + (kt & 1) * ASTAGE;
        const uint32_t sV = sK + 8192;

        // ---- S = Q K^T (exp2-domain scores) ----
        float s[8][4];
#pragma unroll
        for (int nj = 0; nj < 8; nj++)
#pragma unroll
            for (int e = 0; e < 4; e++) s[nj][e] = 0.f;

#pragma unroll
        for (int np = 0; np < 4; np++) {
            int r = (np * 2 + (lane >> 4)) * 8 + (lane & 7);
#pragma unroll
            for (int dc = 0; dc < 4; dc++) {
                int cc = dc * 2 + ((lane >> 3) & 1);
                uint32_t off = (uint32_t)(r * 128 + ((cc ^ (r & 7)) * 16));
                uint32_t h0, h1, h2, h3;
                ldmx4(h0, h1, h2, h3, sK + off);
                mma_bf16(s[2*np][0], s[2*np][1], s[2*np][2], s[2*np][3],
                         qh[dc][0], qh[dc][1], qh[dc][2], qh[dc][3], h0, h1);
                mma_bf16(s[2*np+1][0], s[2*np+1][1], s[2*np+1][2], s[2*np+1][3],
                         qh[dc][0], qh[dc][1], qh[dc][2], qh[dc][3], h2, h3);
            }
        }

        // ---- online softmax (exp2 domain) ----
        float mx0 = -1e30f, mx1 = -1e30f;
#pragma unroll
        for (int nj = 0; nj < 8; nj++) {
            mx0 = fmaxf(mx0, fmaxf(s[nj][0], s[nj][1]));
            mx1 = fmaxf(mx1, fmaxf(s[nj][2], s[nj][3]));
        }
        mx0 = fmaxf(mx0, __shfl_xor_sync(0xffffffffu, mx0, 1));
        mx0 = fmaxf(mx0, __shfl_xor_sync(0xffffffffu, mx0, 2));
        mx1 = fmaxf(mx1, __shfl_xor_sync(0xffffffffu, mx1, 1));
        mx1 = fmaxf(mx1, __shfl_xor_sync(0xffffffffu, mx1, 2));
        float mn0 = fmaxf(m0, mx0), mn1 = fmaxf(m1, mx1);
        float a0 = exp2f(m0 - mn0), a1 = exp2f(m1 - mn1);
        float sum0 = 0.f, sum1 = 0.f;
#pragma unroll
        for (int nj = 0; nj < 8; nj++) {
            s[nj][0] = exp2f(s[nj][0] - mn0);
            s[nj][1] = exp2f(s[nj][1] - mn0);
            s[nj][2] = exp2f(s[nj][2] - mn1);
            s[nj][3] = exp2f(s[nj][3] - mn1);
            sum0 += s[nj][0] + s[nj][1];
            sum1 += s[nj][2] + s[nj][3];
        }
        sum0 += __shfl_xor_sync(0xffffffffu, sum0, 1);
        sum0 += __shfl_xor_sync(0xffffffffu, sum0, 2);
        sum1 += __shfl_xor_sync(0xffffffffu, sum1, 1);
        sum1 += __shfl_xor_sync(0xffffffffu, sum1, 2);
        l0 = l0 * a0 + sum0; l1 = l1 * a1 + sum1;
        m0 = mn0; m1 = mn1;
#pragma unroll
        for (int dj = 0; dj < 8; dj++) {
            o[dj][0] *= a0; o[dj][1] *= a0; o[dj][2] *= a1; o[dj][3] *= a1;
        }

        // ---- O += P V ----
#pragma unroll
        for (int kc = 0; kc < 4; kc++) {
            uint32_t A0 = packbf(__float2bfloat16(s[2 * kc][0]),
                                 __float2bfloat16(s[2 * kc][1]));
            uint32_t A1 = packbf(__float2bfloat16(s[2 * kc][2]),
                                 __float2bfloat16(s[2 * kc][3]));
            uint32_t A2 = packbf(__float2bfloat16(s[2 * kc + 1][0]),
                                 __float2bfloat16(s[2 * kc + 1][1]));
            uint32_t A3 = packbf(__float2bfloat16(s[2 * kc + 1][2]),
                                 __float2bfloat16(s[2 * kc + 1][3]));
            int r = kc * 16 + (lane & 15);
#pragma unroll
            for (int dp = 0; dp < 4; dp++) {
                int c = dp * 2 + (lane >> 4);
                uint32_t addr = sV + (uint32_t)(r * 128 + ((c ^ (r & 7)) * 16));
                uint32_t b0, b1, b2, b3;
                ldmx4t(b0, b1, b2, b3, addr);
                mma_bf16(o[2*dp][0], o[2*dp][1], o[2*dp][2], o[2*dp][3],
                         A0, A1, A2, A3, b0, b1);
                mma_bf16(o[2*dp+1][0], o[2*dp+1][1], o[2*dp+1][2], o[2*dp+1][3],
                         A0, A1, A2, A3, b2, b3);
            }
        }

        __syncthreads();
        if (kt + 2 < SEQ / 64) loadKV(kt & 1, kt + 2);
    }

    // ---- epilogue: normalize, store ctx (single bf16) ----
    float i0 = 1.f / l0, i1 = 1.f / l1;
    int r0 = q0 + wq + (lane >> 2);
    int cb = 2 * (lane & 3);
#pragma unroll
    for (int dj = 0; dj < 8; dj++) {
        int col = dj * 8 + cb;
        *(__nv_bfloat162*)&Ctx[gb + (size_t)r0 * HID + col] =
            __nv_bfloat162(__float2bfloat16(o[dj][0] * i0),
                           __float2bfloat16(o[dj][1] * i0));
        *(__nv_bfloat162*)&Ctx[gb + (size_t)(r0 + 8) * HID + col] =
            __nv_bfloat162(__float2bfloat16(o[dj][2] * i1),
                           __float2bfloat16(o[dj][3] * i1));
    }
}

// ---------------------------------------------------------------------------
// LayerNorm: one block per row of 1024
// ---------------------------------------------------------------------------
__global__ __launch_bounds__(256)
void layernorm_kernel(const float* __restrict__ X, const float* __restrict__ gamma,
                      const float* __restrict__ beta, float* __restrict__ out)
{
    __shared__ float red[2][8];
    const int row = blockIdx.x;
    const int tid = threadIdx.x;
    const float* x = X + (size_t)row * HID;

    float4 v = *(const float4*)&x[tid * 4];
    float s  = v.x + v.y + v.z + v.w;
    float ss = v.x * v.x + v.y * v.y + v.z * v.z + v.w * v.w;
#pragma unroll
    for (int o = 16; o > 0; o >>= 1) {
        s  += __shfl_xor_sync(0xffffffffu, s, o);
        ss += __shfl_xor_sync(0xffffffffu, ss, o);
    }
    const int w = tid >> 5, l = tid & 31;
    if (l == 0) { red[0][w] = s; red[1][w] = ss; }
    __syncthreads();
    if (w == 0) {
        float s2  = (l < 8) ? red[0][l] : 0.f;
        float ss2 = (l < 8) ? red[1][l] : 0.f;
#pragma unroll
        for (int o = 4; o > 0; o >>= 1) {
            s2  += __shfl_xor_sync(0xffffffffu, s2, o);
            ss2 += __shfl_xor_sync(0xffffffffu, ss2, o);
        }
        if (l == 0) { red[0][0] = s2; red[1][0] = ss2; }
    }
    __syncthreads();

    const float mean = red[0][0] * (1.f / HID);
    const float var  = red[1][0] * (1.f / HID) - mean * mean;
    const float rstd = rsqrtf(var + 1e-5f);

    const int c = tid * 4;
    float4 gv = *(const float4*)&gamma[c];
    float4 bv = *(const float4*)&beta[c];
    float4 o;
    o.x = (v.x - mean) * rstd * gv.x + bv.x;
    o.y = (v.y - mean) * rstd * gv.y + bv.y;
    o.z = (v.z - mean) * rstd * gv.z + bv.z;
    o.w = (v.w - mean) * rstd * gv.w + bv.w;
    *(float4*)&out[(size_t)row * HID + c] = o;
}

// ---------------------------------------------------------------------------
// Launch
// ---------------------------------------------------------------------------
extern "C" void kernel_launch(void* const* d_in, const int* in_sizes, int n_in,
                              void* d_out, int out_size)
{
    const float* hidden = (const float*)d_in[0];
    const float* Wq = (const float*)d_in[1];
    const float* bq = (const float*)d_in[2];
    const float* Wk = (const float*)d_in[3];
    const float* bk = (const float*)d_in[4];
    const float* Wv = (const float*)d_in[5];
    const float* bv = (const float*)d_in[6];
    const float* Wo = (const float*)d_in[7];
    const float* bo = (const float*)d_in[8];
    const float* gamma = (const float*)d_in[9];
    const float* beta  = (const float*)d_in[10];
    float* out = (float*)d_out;

    float* x;
    cudaGetSymbolAddress((void**)&x, g_X);

    __nv_bfloat16 *hhi, *ctx, *qhp, *khp, *vbp;
    __nv_bfloat16 *wqh, *wql, *wkh, *wkl, *wvh, *wvl, *woh, *wol;
    cudaGetSymbolAddress((void**)&hhi, g_Hhi);
    cudaGetSymbolAddress((void**)&ctx, g_Ctx);
    cudaGetSymbolAddress((void**)&qhp, g_Qh);
    cudaGetSymbolAddress((void**)&khp, g_Kh);
    cudaGetSymbolAddress((void**)&vbp, g_Vb);
    cudaGetSymbolAddress((void**)&wqh, g_WqTh);
    cudaGetSymbolAddress((void**)&wql, g_WqTl);
    cudaGetSymbolAddress((void**)&wkh, g_WkTh);
    cudaGetSymbolAddress((void**)&wkl, g_WkTl);
    cudaGetSymbolAddress((void**)&wvh, g_WvTh);
    cudaGetSymbolAddress((void**)&wvl, g_WvTl);
    cudaGetSymbolAddress((void**)&woh, g_WoTh);
    cudaGetSymbolAddress((void**)&wol, g_WoTl);

    // ---- prep ----
    convert_hi<<<(ROWS * HID / 4 + 255) / 256, 256>>>(hidden, hhi, ROWS * HID / 4);
    dim3 tg(HID / 32, HID / 32, 4), tb(32, 8);
    transpose_split4<<<tg, tb>>>(Wq, Wk, Wv, Wo,
                                 wqh, wql, wkh, wkl, wvh, wvl, woh, wol);

    // ---- merged QKV projection (2-term, bf16 outputs) ----
    cudaFuncSetAttribute(gemm_qkv, cudaFuncAttributeMaxDynamicSharedMemorySize, GEMM_SMEM);
    cudaFuncSetAttribute(gemm_out, cudaFuncAttributeMaxDynamicSharedMemorySize, GEMM_SMEM);
    gemm_qkv<<<dim3(24, ROWS / 128), 256, GEMM_SMEM>>>(
        hhi, wqh, wql, wkh, wkl, wvh, wvl, bq, bk, bv,
        qhp, khp, vbp);

    // ---- attention (tensor core, 2 CTAs/SM) ----
    cudaFuncSetAttribute(flash_mma, cudaFuncAttributeMaxDynamicSharedMemorySize, ATT_SMEM);
    flash_mma<<<dim3(SEQ / 128, HEADS, BATCH), 256, ATT_SMEM>>>(qhp, khp, vbp, ctx);

    // ---- output projection + residual (2-term) ----
    gemm_out<<<dim3(HID / 128, ROWS / 128), 256, GEMM_SMEM>>>(ctx, woh, wol, bo,
                                                              hidden, x);

    // ---- layernorm ----
    layernorm_kernel<<<ROWS, 256>>>(x, gamma, beta, out);
}

// round 12
// speedup vs baseline: 8.2517x; 1.3328x over previous
#include <cuda_runtime.h>
#include <cuda_bf16.h>
#include <math.h>
#include <stdint.h>

// ---------------------------------------------------------------------------
// Problem constants
// ---------------------------------------------------------------------------
#define BATCH   2
#define SEQ     2048
#define HID     1024
#define HEADS   16
#define HDIM    64
#define ROWS    (BATCH * SEQ)          // 4096

// ---------------------------------------------------------------------------
// Scratch (static device globals -- no runtime allocation)
// ---------------------------------------------------------------------------
__device__ float g_X[ROWS * HID];

__device__ __nv_bfloat16 g_Hhi[ROWS * HID];
__device__ __nv_bfloat16 g_Qh[ROWS * HID];
__device__ __nv_bfloat16 g_Kh[ROWS * HID];
__device__ __nv_bfloat16 g_Vb[ROWS * HID];
__device__ __nv_bfloat16 g_Ctx[ROWS * HID];
__device__ __nv_bfloat16 g_WqT[HID * HID];
__device__ __nv_bfloat16 g_WkT[HID * HID];
__device__ __nv_bfloat16 g_WvT[HID * HID];
__device__ __nv_bfloat16 g_WoT[HID * HID];

// ---------------------------------------------------------------------------
// PTX helpers
// ---------------------------------------------------------------------------
__device__ __forceinline__ uint32_t smem_u32(const void* p) {
    uint32_t a;
    asm("{ .reg .u64 t; cvta.to.shared.u64 t, %1; cvt.u32.u64 %0, t; }"
        : "=r"(a) : "l"(p));
    return a;
}
__device__ __forceinline__ void ldmx4(uint32_t& r0, uint32_t& r1, uint32_t& r2,
                                      uint32_t& r3, uint32_t addr) {
    asm volatile("ldmatrix.sync.aligned.m8n8.x4.shared.b16 {%0,%1,%2,%3}, [%4];"
                 : "=r"(r0), "=r"(r1), "=r"(r2), "=r"(r3) : "r"(addr));
}
__device__ __forceinline__ void ldmx2(uint32_t& r0, uint32_t& r1, uint32_t addr) {
    asm volatile("ldmatrix.sync.aligned.m8n8.x2.shared.b16 {%0,%1}, [%2];"
                 : "=r"(r0), "=r"(r1) : "r"(addr));
}
__device__ __forceinline__ void ldmx4t(uint32_t& r0, uint32_t& r1, uint32_t& r2,
                                       uint32_t& r3, uint32_t addr) {
    asm volatile("ldmatrix.sync.aligned.m8n8.x4.trans.shared.b16 {%0,%1,%2,%3}, [%4];"
                 : "=r"(r0), "=r"(r1), "=r"(r2), "=r"(r3) : "r"(addr));
}
__device__ __forceinline__ void mma_bf16(float& d0, float& d1, float& d2, float& d3,
                                         uint32_t a0, uint32_t a1, uint32_t a2,
                                         uint32_t a3, uint32_t b0, uint32_t b1) {
    asm volatile(
        "mma.sync.aligned.m16n8k16.row.col.f32.bf16.bf16.f32 "
        "{%0,%1,%2,%3}, {%4,%5,%6,%7}, {%8,%9}, {%0,%1,%2,%3};"
        : "+f"(d0), "+f"(d1), "+f"(d2), "+f"(d3)
        : "r"(a0), "r"(a1), "r"(a2), "r"(a3), "r"(b0), "r"(b1));
}
__device__ __forceinline__ void cp16(uint32_t dst, const void* src) {
    asm volatile("cp.async.cg.shared.global [%0], [%1], 16;"
                 :: "r"(dst), "l"(src));
}
__device__ __forceinline__ void cp_commit() {
    asm volatile("cp.async.commit_group;" ::: "memory");
}
template <int N>
__device__ __forceinline__ void cp_wait() {
    asm volatile("cp.async.wait_group %0;" :: "n"(N) : "memory");
}

__device__ __forceinline__ uint32_t packbf(__nv_bfloat16 a, __nv_bfloat16 b) {
    __nv_bfloat162 t(a, b);
    return *(uint32_t*)&t;
}

// ---------------------------------------------------------------------------
// fp32 -> bf16 (hi only)
// ---------------------------------------------------------------------------
__global__ __launch_bounds__(256)
void convert_hi(const float* __restrict__ in, __nv_bfloat16* __restrict__ hi, int n4)
{
    int i = blockIdx.x * blockDim.x + threadIdx.x;
    if (i >= n4) return;
    float4 v = ((const float4*)in)[i];
    ((__nv_bfloat162*)hi)[2 * i + 0] =
        __nv_bfloat162(__float2bfloat16(v.x), __float2bfloat16(v.y));
    ((__nv_bfloat162*)hi)[2 * i + 1] =
        __nv_bfloat162(__float2bfloat16(v.z), __float2bfloat16(v.w));
}

// ---------------------------------------------------------------------------
// All four W [K,N] fp32 -> transposed bf16 [N,K] in one launch (z=4)
// ---------------------------------------------------------------------------
__global__ __launch_bounds__(256)
void transpose_hi4(const float* __restrict__ W0, const float* __restrict__ W1,
                   const float* __restrict__ W2, const float* __restrict__ W3,
                   __nv_bfloat16* __restrict__ T0, __nv_bfloat16* __restrict__ T1,
                   __nv_bfloat16* __restrict__ T2, __nv_bfloat16* __restrict__ T3)
{
    __shared__ float t[32][33];
    const int z = blockIdx.z;
    const float* W = (z == 0) ? W0 : (z == 1) ? W1 : (z == 2) ? W2 : W3;
    __nv_bfloat16* Th = (z == 0) ? T0 : (z == 1) ? T1 : (z == 2) ? T2 : T3;

    const int n0 = blockIdx.x * 32, k0 = blockIdx.y * 32;
    const int tx = threadIdx.x, ty = threadIdx.y;
#pragma unroll
    for (int i = 0; i < 32; i += 8)
        t[ty + i][tx] = W[(size_t)(k0 + ty + i) * HID + n0 + tx];
    __syncthreads();
#pragma unroll
    for (int i = 0; i < 32; i += 8)
        Th[(size_t)(n0 + ty + i) * HID + k0 + tx] = __float2bfloat16(t[tx][ty + i]);
}

// ---------------------------------------------------------------------------
// GEMM mainloop shared constants
// ---------------------------------------------------------------------------
#define PIPE 3
#define STAGE_BYTES 16384                 // A(c0-3) | B(c4-7), 128 rows x 128 B
#define GEMM_SMEM   (PIPE * STAGE_BYTES)
#define NKC  (HID / 32)

#define LOG2E 1.44269504f

// ---------------------------------------------------------------------------
// Shared 1-term GEMM mainloop: acc += A*B (both single bf16).
// Stage: one 16KB tile, rows 0..127: chunks 0-3 = A, 4-7 = B.
// 1024 cp.asyncs per stage (4 iters).
// ---------------------------------------------------------------------------
struct GemmCtx {
    uint32_t sbase;
    const __nv_bfloat16 *A, *B;
    int m0, n0, tid, lane, wm, wn;
};

__device__ __forceinline__ void gemm1_load_stage(const GemmCtx& g, int stage, int kc) {
    const uint32_t sb = g.sbase + stage * STAGE_BYTES;
#pragma unroll
    for (int t = 0; t < 4; t++) {
        int idx  = g.tid + t * 256;            // 0..1023
        int tile = idx >> 9;                   // 0=A 1=B
        int r    = (idx >> 2) & 127;
        int c    = idx & 3;
        const __nv_bfloat16* src = (tile == 0)
            ? g.A + (size_t)(g.m0 + r) * HID + kc * 32 + c * 8
            : g.B + (size_t)(g.n0 + r) * HID + kc * 32 + c * 8;
        uint32_t cd = (uint32_t)(tile == 0 ? c : c + 4);
        uint32_t dst = sb + (uint32_t)(r * 128 + ((cd ^ (r & 7)) * 16));
        cp16(dst, src);
    }
    cp_commit();
}

__device__ __forceinline__ void gemm1_mainloop(const GemmCtx& g, float acc[4][4][4]) {
    gemm1_load_stage(g, 0, 0);
    gemm1_load_stage(g, 1, 1);
    for (int kc = 0; kc < NKC; kc++) {
        cp_wait<PIPE - 2>();
        __syncthreads();
        if (kc + 2 < NKC) gemm1_load_stage(g, (kc + 2) % PIPE, kc + 2);

        const uint32_t sT = g.sbase + (kc % PIPE) * STAGE_BYTES;

#pragma unroll
        for (int ks = 0; ks < 2; ks++) {
            uint32_t bh[4][2];
#pragma unroll
            for (int nj = 0; nj < 4; nj++) {
                int r  = g.wn + nj * 8 + (g.lane & 7);
                int cc = ks * 2 + ((g.lane >> 3) & 1) + 4;
                ldmx2(bh[nj][0], bh[nj][1],
                      sT + (uint32_t)(r * 128 + ((cc ^ (r & 7)) * 16)));
            }
#pragma unroll
            for (int mi = 0; mi < 4; mi++) {
                int r  = g.wm + mi * 16 + (g.lane & 15);
                int cc = ks * 2 + (g.lane >> 4);
                uint32_t a0, a1, a2, a3;
                ldmx4(a0, a1, a2, a3,
                      sT + (uint32_t)(r * 128 + ((cc ^ (r & 7)) * 16)));
#pragma unroll
                for (int nj = 0; nj < 4; nj++)
                    mma_bf16(acc[mi][nj][0], acc[mi][nj][1], acc[mi][nj][2], acc[mi][nj][3],
                             a0, a1, a2, a3, bh[nj][0], bh[nj][1]);
            }
        }
    }
}

// ---------------------------------------------------------------------------
// Merged QKV projection: grid (24, 32). blockIdx.x>>3 selects Q/K/V.
// Output single bf16; Q pre-scaled by log2(e)/8 for exp2-domain softmax.
// ---------------------------------------------------------------------------
__global__ __launch_bounds__(256, 2)
void gemm_qkv(const __nv_bfloat16* __restrict__ Ahi,
              const __nv_bfloat16* __restrict__ Bq, const __nv_bfloat16* __restrict__ Bk,
              const __nv_bfloat16* __restrict__ Bv,
              const float* __restrict__ bq, const float* __restrict__ bk,
              const float* __restrict__ bv,
              __nv_bfloat16* __restrict__ Qh,
              __nv_bfloat16* __restrict__ Kh,
              __nv_bfloat16* __restrict__ Vb)
{
    extern __shared__ char smc[];
    const int sel = blockIdx.x >> 3;
    const int tid = threadIdx.x, lane = tid & 31, warp = tid >> 5;

    GemmCtx g;
    g.sbase = smem_u32(smc);
    g.A = Ahi;
    g.B = (sel == 0) ? Bq : (sel == 1) ? Bk : Bv;
    g.m0 = blockIdx.y * 128; g.n0 = (blockIdx.x & 7) * 128;
    g.tid = tid; g.lane = lane;
    g.wm = (warp >> 2) * 64; g.wn = (warp & 3) * 32;

    const float* bias = (sel == 0) ? bq : (sel == 1) ? bk : bv;
    __nv_bfloat16* Ch = (sel == 0) ? Qh : (sel == 1) ? Kh : Vb;

    float acc[4][4][4];
#pragma unroll
    for (int mi = 0; mi < 4; mi++)
#pragma unroll
        for (int nj = 0; nj < 4; nj++)
#pragma unroll
            for (int e = 0; e < 4; e++) acc[mi][nj][e] = 0.f;

    gemm1_mainloop(g, acc);

    const float oscale = (sel == 0) ? 0.125f * LOG2E : 1.0f;
#pragma unroll
    for (int mi = 0; mi < 4; mi++) {
#pragma unroll
        for (int nj = 0; nj < 4; nj++) {
            int row = g.m0 + g.wm + mi * 16 + (lane >> 2);
            int col = g.n0 + g.wn + nj * 8 + 2 * (lane & 3);
            float b0 = bias[col], b1 = bias[col + 1];
            float v00 = (acc[mi][nj][0] + b0) * oscale, v01 = (acc[mi][nj][1] + b1) * oscale;
            float v10 = (acc[mi][nj][2] + b0) * oscale, v11 = (acc[mi][nj][3] + b1) * oscale;
            *(__nv_bfloat162*)&Ch[(size_t)row * HID + col] =
                __nv_bfloat162(__float2bfloat16(v00), __float2bfloat16(v01));
            *(__nv_bfloat162*)&Ch[(size_t)(row + 8) * HID + col] =
                __nv_bfloat162(__float2bfloat16(v10), __float2bfloat16(v11));
        }
    }
}

// ---------------------------------------------------------------------------
// Output projection GEMM (single bf16 operands; fp32 out + residual)
// ---------------------------------------------------------------------------
__global__ __launch_bounds__(256, 2)
void gemm_out(const __nv_bfloat16* __restrict__ Ctx,
              const __nv_bfloat16* __restrict__ Bo,
              const float* __restrict__ bias, const float* __restrict__ res,
              float* __restrict__ Cf)
{
    extern __shared__ char smc[];
    const int tid = threadIdx.x, lane = tid & 31, warp = tid >> 5;

    GemmCtx g;
    g.sbase = smem_u32(smc);
    g.A = Ctx; g.B = Bo;
    g.m0 = blockIdx.y * 128; g.n0 = blockIdx.x * 128;
    g.tid = tid; g.lane = lane;
    g.wm = (warp >> 2) * 64; g.wn = (warp & 3) * 32;

    float acc[4][4][4];
#pragma unroll
    for (int mi = 0; mi < 4; mi++)
#pragma unroll
        for (int nj = 0; nj < 4; nj++)
#pragma unroll
            for (int e = 0; e < 4; e++) acc[mi][nj][e] = 0.f;

    gemm1_mainloop(g, acc);

#pragma unroll
    for (int mi = 0; mi < 4; mi++) {
#pragma unroll
        for (int nj = 0; nj < 4; nj++) {
            int row = g.m0 + g.wm + mi * 16 + (lane >> 2);
            int col = g.n0 + g.wn + nj * 8 + 2 * (lane & 3);
            float b0 = bias[col], b1 = bias[col + 1];
            float v00 = acc[mi][nj][0] + b0, v01 = acc[mi][nj][1] + b1;
            float v10 = acc[mi][nj][2] + b0, v11 = acc[mi][nj][3] + b1;
            float2 r0 = *(const float2*)&res[(size_t)row * HID + col];
            float2 r1 = *(const float2*)&res[(size_t)(row + 8) * HID + col];
            v00 += r0.x; v01 += r0.y; v10 += r1.x; v11 += r1.y;
            *(float2*)&Cf[(size_t)row * HID + col] = make_float2(v00, v01);
            *(float2*)&Cf[(size_t)(row + 8) * HID + col] = make_float2(v10, v11);
        }
    }
}

// ---------------------------------------------------------------------------
// Flash attention via mma.sync (all-bf16):
//   S = Qh*Kh (Q pre-scaled by log2e/8); exp2-domain online softmax;
//   O += P_hi * V. K-tile 64, 2 CTAs/SM. Output ctx single bf16.
// ---------------------------------------------------------------------------
#define ASTAGE 16384                           // Kh 8K + V 8K
#define ATT_SMEM (16384 + 2 * ASTAGE)          // + Qhi 16K = 48K

__global__ __launch_bounds__(256, 2)
void flash_mma(const __nv_bfloat16* __restrict__ Qh,
               const __nv_bfloat16* __restrict__ Kh,
               const __nv_bfloat16* __restrict__ Vb,
               __nv_bfloat16* __restrict__ Ctx)
{
    extern __shared__ char sma[];
    const uint32_t sQ = smem_u32(sma);        // Qhi 16K
    const uint32_t sS = sQ + 16384;           // 2 stages of {Kh 8K, V 8K}

    const int tid = threadIdx.x, lane = tid & 31, warp = tid >> 5;
    const int q0 = blockIdx.x * 128;
    const int h = blockIdx.y, b = blockIdx.z;
    const size_t gb = (size_t)b * SEQ * HID + (size_t)h * HDIM;

#pragma unroll
    for (int t = 0; t < 4; t++) {
        int idx = tid + t * 256;
        int r = idx >> 3, c = idx & 7;
        const __nv_bfloat16* src = Qh + gb + (size_t)(q0 + r) * HID + c * 8;
        cp16(sQ + (uint32_t)(r * 128 + ((c ^ (r & 7)) * 16)), src);
    }
    cp_commit();

    auto loadKV = [&](int stage, int kt) {
        const uint32_t sb = sS + stage * ASTAGE;
#pragma unroll
        for (int t = 0; t < 4; t++) {
            int idx = tid + t * 256;
            int tile = idx >> 9;
            int r = (idx >> 3) & 63, c = idx & 7;
            const __nv_bfloat16* src =
                (tile == 0 ? Kh : Vb) + gb + (size_t)(kt * 64 + r) * HID + c * 8;
            cp16(sb + (uint32_t)(tile * 8192 + r * 128 + ((c ^ (r & 7)) * 16)), src);
        }
        cp_commit();
    };
    loadKV(0, 0);
    loadKV(1, 1);

    cp_wait<2>();
    __syncthreads();

    const int wq = warp * 16;
    uint32_t qh[4][4];
#pragma unroll
    for (int dc = 0; dc < 4; dc++) {
        int r = wq + (lane & 15);
        int cc = dc * 2 + (lane >> 4);
        ldmx4(qh[dc][0], qh[dc][1], qh[dc][2], qh[dc][3],
              sQ + (uint32_t)(r * 128 + ((cc ^ (r & 7)) * 16)));
    }

    float m0 = -1e30f, m1 = -1e30f, l0 = 0.f, l1 = 0.f;
    float o[8][4];
#pragma unroll
    for (int dj = 0; dj < 8; dj++)
#pragma unroll
        for (int e = 0; e < 4; e++) o[dj][e] = 0.f;

    for (int kt = 0; kt < SEQ / 64; kt++) {
        cp_wait<1>();
        __syncthreads();
        const uint32_t sK = sS + (kt & 1) * ASTAGE;
        const uint32_t sV = sK + 8192;

        // ---- S = Q K^T ----
        float s[8][4];
#pragma unroll
        for (int nj = 0; nj < 8; nj++)
#pragma unroll
            for (int e = 0; e < 4; e++) s[nj][e] = 0.f;

#pragma unroll
        for (int np = 0; np < 4; np++) {
            int r = (np * 2 + (lane >> 4)) * 8 + (lane & 7);
#pragma unroll
            for (int dc = 0; dc < 4; dc++) {
                int cc = dc * 2 + ((lane >> 3) & 1);
                uint32_t off = (uint32_t)(r * 128 + ((cc ^ (r & 7)) * 16));
                uint32_t h0, h1, h2, h3;
                ldmx4(h0, h1, h2, h3, sK + off);
                mma_bf16(s[2*np][0], s[2*np][1], s[2*np][2], s[2*np][3],
                         qh[dc][0], qh[dc][1], qh[dc][2], qh[dc][3], h0, h1);
                mma_bf16(s[2*np+1][0], s[2*np+1][1], s[2*np+1][2], s[2*np+1][3],
                         qh[dc][0], qh[dc][1], qh[dc][2], qh[dc][3], h2, h3);
            }
        }

        // ---- online softmax (exp2 domain) ----
        float mx0 = -1e30f, mx1 = -1e30f;
#pragma unroll
        for (int nj = 0; nj < 8; nj++) {
            mx0 = fmaxf(mx0, fmaxf(s[nj][0], s[nj][1]));
            mx1 = fmaxf(mx1, fmaxf(s[nj][2], s[nj][3]));
        }
        mx0 = fmaxf(mx0, __shfl_xor_sync(0xffffffffu, mx0, 1));
        mx0 = fmaxf(mx0, __shfl_xor_sync(0xffffffffu, mx0, 2));
        mx1 = fmaxf(mx1, __shfl_xor_sync(0xffffffffu, mx1, 1));
        mx1 = fmaxf(mx1, __shfl_xor_sync(0xffffffffu, mx1, 2));
        float mn0 = fmaxf(m0, mx0), mn1 = fmaxf(m1, mx1);
        float a0 = exp2f(m0 - mn0), a1 = exp2f(m1 - mn1);
        float sum0 = 0.f, sum1 = 0.f;
#pragma unroll
        for (int nj = 0; nj < 8; nj++) {
            s[nj][0] = exp2f(s[nj][0] - mn0);
            s[nj][1] = exp2f(s[nj][1] - mn0);
            s[nj][2] = exp2f(s[nj][2] - mn1);
            s[nj][3] = exp2f(s[nj][3] - mn1);
            sum0 += s[nj][0] + s[nj][1];
            sum1 += s[nj][2] + s[nj][3];
        }
        sum0 += __shfl_xor_sync(0xffffffffu, sum0, 1);
        sum0 += __shfl_xor_sync(0xffffffffu, sum0, 2);
        sum1 += __shfl_xor_sync(0xffffffffu, sum1, 1);
        sum1 += __shfl_xor_sync(0xffffffffu, sum1, 2);
        l0 = l0 * a0 + sum0; l1 = l1 * a1 + sum1;
        m0 = mn0; m1 = mn1;
#pragma unroll
        for (int dj = 0; dj < 8; dj++) {
            o[dj][0] *= a0; o[dj][1] *= a0; o[dj][2] *= a1; o[dj][3] *= a1;
        }

        // ---- O += P V ----
#pragma unroll
        for (int kc = 0; kc < 4; kc++) {
            uint32_t A0 = packbf(__float2bfloat16(s[2 * kc][0]),
                                 __float2bfloat16(s[2 * kc][1]));
            uint32_t A1 = packbf(__float2bfloat16(s[2 * kc][2]),
                                 __float2bfloat16(s[2 * kc][3]));
            uint32_t A2 = packbf(__float2bfloat16(s[2 * kc + 1][0]),
                                 __float2bfloat16(s[2 * kc + 1][1]));
            uint32_t A3 = packbf(__float2bfloat16(s[2 * kc + 1][2]),
                                 __float2bfloat16(s[2 * kc + 1][3]));
            int r = kc * 16 + (lane & 15);
#pragma unroll
            for (int dp = 0; dp < 4; dp++) {
                int c = dp * 2 + (lane >> 4);
                uint32_t addr = sV + (uint32_t)(r * 128 + ((c ^ (r & 7)) * 16));
                uint32_t b0, b1, b2, b3;
                ldmx4t(b0, b1, b2, b3, addr);
                mma_bf16(o[2*dp][0], o[2*dp][1], o[2*dp][2], o[2*dp][3],
                         A0, A1, A2, A3, b0, b1);
                mma_bf16(o[2*dp+1][0], o[2*dp+1][1], o[2*dp+1][2], o[2*dp+1][3],
                         A0, A1, A2, A3, b2, b3);
            }
        }

        __syncthreads();
        if (kt + 2 < SEQ / 64) loadKV(kt & 1, kt + 2);
    }

    // ---- epilogue: normalize, store ctx (single bf16) ----
    float i0 = 1.f / l0, i1 = 1.f / l1;
    int r0 = q0 + wq + (lane >> 2);
    int cb = 2 * (lane & 3);
#pragma unroll
    for (int dj = 0; dj < 8; dj++) {
        int col = dj * 8 + cb;
        *(__nv_bfloat162*)&Ctx[gb + (size_t)r0 * HID + col] =
            __nv_bfloat162(__float2bfloat16(o[dj][0] * i0),
                           __float2bfloat16(o[dj][1] * i0));
        *(__nv_bfloat162*)&Ctx[gb + (size_t)(r0 + 8) * HID + col] =
            __nv_bfloat162(__float2bfloat16(o[dj][2] * i1),
                           __float2bfloat16(o[dj][3] * i1));
    }
}

// ---------------------------------------------------------------------------
// LayerNorm: one block per row of 1024
// ---------------------------------------------------------------------------
__global__ __launch_bounds__(256)
void layernorm_kernel(const float* __restrict__ X, const float* __restrict__ gamma,
                      const float* __restrict__ beta, float* __restrict__ out)
{
    __shared__ float red[2][8];
    const int row = blockIdx.x;
    const int tid = threadIdx.x;
    const float* x = X + (size_t)row * HID;

    float4 v = *(const float4*)&x[tid * 4];
    float s  = v.x + v.y + v.z + v.w;
    float ss = v.x * v.x + v.y * v.y + v.z * v.z + v.w * v.w;
#pragma unroll
    for (int o = 16; o > 0; o >>= 1) {
        s  += __shfl_xor_sync(0xffffffffu, s, o);
        ss += __shfl_xor_sync(0xffffffffu, ss, o);
    }
    const int w = tid >> 5, l = tid & 31;
    if (l == 0) { red[0][w] = s; red[1][w] = ss; }
    __syncthreads();
    if (w == 0) {
        float s2  = (l < 8) ? red[0][l] : 0.f;
        float ss2 = (l < 8) ? red[1][l] : 0.f;
#pragma unroll
        for (int o = 4; o > 0; o >>= 1) {
            s2  += __shfl_xor_sync(0xffffffffu, s2, o);
            ss2 += __shfl_xor_sync(0xffffffffu, ss2, o);
        }
        if (l == 0) { red[0][0] = s2; red[1][0] = ss2; }
    }
    __syncthreads();

    const float mean = red[0][0] * (1.f / HID);
    const float var  = red[1][0] * (1.f / HID) - mean * mean;
    const float rstd = rsqrtf(var + 1e-5f);

    const int c = tid * 4;
    float4 gv = *(const float4*)&gamma[c];
    float4 bv = *(const float4*)&beta[c];
    float4 o;
    o.x = (v.x - mean) * rstd * gv.x + bv.x;
    o.y = (v.y - mean) * rstd * gv.y + bv.y;
    o.z = (v.z - mean) * rstd * gv.z + bv.z;
    o.w = (v.w - mean) * rstd * gv.w + bv.w;
    *(float4*)&out[(size_t)row * HID + c] = o;
}

// ---------------------------------------------------------------------------
// Launch
// ---------------------------------------------------------------------------
extern "C" void kernel_launch(void* const* d_in, const int* in_sizes, int n_in,
                              void* d_out, int out_size)
{
    const float* hidden = (const float*)d_in[0];
    const float* Wq = (const float*)d_in[1];
    const float* bq = (const float*)d_in[2];
    const float* Wk = (const float*)d_in[3];
    const float* bk = (const float*)d_in[4];
    const float* Wv = (const float*)d_in[5];
    const float* bv = (const float*)d_in[6];
    const float* Wo = (const float*)d_in[7];
    const float* bo = (const float*)d_in[8];
    const float* gamma = (const float*)d_in[9];
    const float* beta  = (const float*)d_in[10];
    float* out = (float*)d_out;

    float* x;
    cudaGetSymbolAddress((void**)&x, g_X);

    __nv_bfloat16 *hhi, *ctx, *qhp, *khp, *vbp;
    __nv_bfloat16 *wqt, *wkt, *wvt, *wot;
    cudaGetSymbolAddress((void**)&hhi, g_Hhi);
    cudaGetSymbolAddress((void**)&ctx, g_Ctx);
    cudaGetSymbolAddress((void**)&qhp, g_Qh);
    cudaGetSymbolAddress((void**)&khp, g_Kh);
    cudaGetSymbolAddress((void**)&vbp, g_Vb);
    cudaGetSymbolAddress((void**)&wqt, g_WqT);
    cudaGetSymbolAddress((void**)&wkt, g_WkT);
    cudaGetSymbolAddress((void**)&wvt, g_WvT);
    cudaGetSymbolAddress((void**)&wot, g_WoT);

    // ---- prep ----
    convert_hi<<<(ROWS * HID / 4 + 255) / 256, 256>>>(hidden, hhi, ROWS * HID / 4);
    dim3 tg(HID / 32, HID / 32, 4), tb(32, 8);
    transpose_hi4<<<tg, tb>>>(Wq, Wk, Wv, Wo, wqt, wkt, wvt, wot);

    // ---- merged QKV projection (1-term bf16) ----
    cudaFuncSetAttribute(gemm_qkv, cudaFuncAttributeMaxDynamicSharedMemorySize, GEMM_SMEM);
    cudaFuncSetAttribute(gemm_out, cudaFuncAttributeMaxDynamicSharedMemorySize, GEMM_SMEM);
    gemm_qkv<<<dim3(24, ROWS / 128), 256, GEMM_SMEM>>>(
        hhi, wqt, wkt, wvt, bq, bk, bv, qhp, khp, vbp);

    // ---- attention (tensor core, 2 CTAs/SM) ----
    cudaFuncSetAttribute(flash_mma, cudaFuncAttributeMaxDynamicSharedMemorySize, ATT_SMEM);
    flash_mma<<<dim3(SEQ / 128, HEADS, BATCH), 256, ATT_SMEM>>>(qhp, khp, vbp, ctx);

    // ---- output projection + residual (1-term bf16) ----
    gemm_out<<<dim3(HID / 128, ROWS / 128), 256, GEMM_SMEM>>>(ctx, wot, bo, hidden, x);

    // ---- layernorm ----
    layernorm_kernel<<<ROWS, 256>>>(x, gamma, beta, out);
}